// round 12
// baseline (speedup 1.0000x reference)
#include <cuda_runtime.h>
#include <cuda_bf16.h>
#include <cstdint>
#include <math.h>

#define B_   2
#define L_   8192
#define D_   1024
#define H_   16
#define DH_  64
#define M_   266
#define BL   (B_*L_)
#define BH   (B_*H_)

#define SCALE  0.17677669529663687f
#define SCALE2 0.03125f
#define NC     0.061313932f
#define KEPS   1e-4f
#define NSTAB  1e-6f

#define SPLIT  16
#define KVROW  272
#define KVCOL  72
#define KVSZ2  (BH*KVROW*KVCOL)

// ---------------- device scratch ----------------
__device__ float g_Qp[BL*D_];
__device__ float g_Kp[BL*D_];
__device__ float g_Vp[BL*D_];
__device__ float g_hk[BH*L_];
__device__ unsigned int g_kstab;
__device__ float g_kv[KVSZ2];
__device__ float g_kvpart[(size_t)SPLIT*KVSZ2];
// bf16 split buffers
__device__ __nv_bfloat16 g_ah[BL*D_];
__device__ __nv_bfloat16 g_al[BL*D_];
__device__ __nv_bfloat16 g_wh[D_*D_];
__device__ __nv_bfloat16 g_wl[D_*D_];
__device__ __nv_bfloat16 g_ctxh[BL*D_];
__device__ __nv_bfloat16 g_ctxl[BL*D_];

// ================= helpers =================
__device__ __forceinline__ uint32_t smem_u32(const void* p) {
    uint32_t a;
    asm("{ .reg .u64 t; cvta.to.shared.u64 t, %1; cvt.u32.u64 %0, t; }" : "=r"(a) : "l"(p));
    return a;
}
__device__ __forceinline__ void cvt_split(float4 v, uint32_t& h01, uint32_t& h23,
                                          uint32_t& l01, uint32_t& l23) {
    asm("cvt.rn.bf16x2.f32 %0, %1, %2;" : "=r"(h01) : "f"(v.y), "f"(v.x));
    asm("cvt.rn.bf16x2.f32 %0, %1, %2;" : "=r"(h23) : "f"(v.w), "f"(v.z));
    float r0 = v.x - __uint_as_float(h01 << 16);
    float r1 = v.y - __uint_as_float(h01 & 0xffff0000u);
    float r2 = v.z - __uint_as_float(h23 << 16);
    float r3 = v.w - __uint_as_float(h23 & 0xffff0000u);
    asm("cvt.rn.bf16x2.f32 %0, %1, %2;" : "=r"(l01) : "f"(r1), "f"(r0));
    asm("cvt.rn.bf16x2.f32 %0, %1, %2;" : "=r"(l23) : "f"(r3), "f"(r2));
}
__device__ __forceinline__ void cvt_split2(float a, float b, uint32_t& hh, uint32_t& ll) {
    asm("cvt.rn.bf16x2.f32 %0, %1, %2;" : "=r"(hh) : "f"(b), "f"(a));
    float ra = a - __uint_as_float(hh << 16);
    float rb = b - __uint_as_float(hh & 0xffff0000u);
    asm("cvt.rn.bf16x2.f32 %0, %1, %2;" : "=r"(ll) : "f"(rb), "f"(ra));
}
#define LDSM_X4(r0,r1,r2,r3,addr) \
    asm volatile("ldmatrix.sync.aligned.m8n8.x4.shared.b16 {%0,%1,%2,%3}, [%4];" \
        : "=r"(r0),"=r"(r1),"=r"(r2),"=r"(r3) : "r"(addr))
#define LDSM_X4T(r0,r1,r2,r3,addr) \
    asm volatile("ldmatrix.sync.aligned.m8n8.x4.trans.shared.b16 {%0,%1,%2,%3}, [%4];" \
        : "=r"(r0),"=r"(r1),"=r"(r2),"=r"(r3) : "r"(addr))
#define LDSM_X2T(r0,r1,addr) \
    asm volatile("ldmatrix.sync.aligned.m8n8.x2.trans.shared.b16 {%0,%1}, [%2];" \
        : "=r"(r0),"=r"(r1) : "r"(addr))
#define MMA_BF16(d,a,b0_,b1_) \
    asm volatile("mma.sync.aligned.m16n8k16.row.col.f32.bf16.bf16.f32 " \
        "{%0,%1,%2,%3}, {%4,%5,%6,%7}, {%8,%9}, {%0,%1,%2,%3};" \
        : "+f"((d)[0]),"+f"((d)[1]),"+f"((d)[2]),"+f"((d)[3]) \
        : "r"((a)[0]),"r"((a)[1]),"r"((a)[2]),"r"((a)[3]),"r"(b0_),"r"(b1_))
#define CP16(dst, src) \
    asm volatile("cp.async.cg.shared.global [%0], [%1], 16;" :: "r"(dst), "l"(src))
#define CP_COMMIT() asm volatile("cp.async.commit_group;" ::: "memory")
#define CP_WAIT1()  asm volatile("cp.async.wait_group 1;" ::: "memory")
#define CP_WAIT0()  asm volatile("cp.async.wait_group 0;" ::: "memory")

// ================= fp32 -> bf16 hi/lo split (streaming) =================
__global__ __launch_bounds__(256) void split_kernel(const float* __restrict__ X,
                                                    __nv_bfloat16* __restrict__ hi,
                                                    __nv_bfloat16* __restrict__ lo,
                                                    int n4) {
    int i = blockIdx.x * 256 + threadIdx.x;
    if (i < n4) {
        float4 v = ((const float4*)X)[i];
        uint32_t h01, h23, l01, l23;
        cvt_split(v, h01, h23, l01, l23);
        ((uint2*)hi)[i] = make_uint2(h01, h23);
        ((uint2*)lo)[i] = make_uint2(l01, l23);
    }
}

// ============ bf16x3 GEMM: CTA tile 128x256, 512 thr, cp.async 2-stage ============
#define AST 40
// stage layout (bytes): Ah 10240 | Al 10240 | Wh 20480 | Wl 20480  = 61440
#define GC_STAGE 61440
#define GC_SMEM  122880

__global__ __launch_bounds__(512, 1) void gemm_mma_c(const __nv_bfloat16* __restrict__ Ah_,
                                                     const __nv_bfloat16* __restrict__ Al_,
                                                     const __nv_bfloat16* __restrict__ Wh_,
                                                     const __nv_bfloat16* __restrict__ Wl_,
                                                     const float* __restrict__ bias,
                                                     float* __restrict__ C) {
    extern __shared__ char smg[];
    const uint32_t sb = smem_u32(smg);
    const int tid = threadIdx.x, lane = tid & 31, wid = tid >> 5;
    const int wm = wid & 1, wn = wid >> 1;           // wn 0..7 over 256 cols
    const size_t mbase = (size_t)blockIdx.y * 128, nbase = (size_t)blockIdx.x * 256;
    const __nv_bfloat16* Abh = Ah_ + mbase * D_;
    const __nv_bfloat16* Abl = Al_ + mbase * D_;
    const __nv_bfloat16* Wbh = Wh_ + nbase * D_;
    const __nv_bfloat16* Wbl = Wl_ + nbase * D_;

    const int arow = lane & 15, acolsel = (lane >> 4) << 3;
    const int brow = (lane & 7) + ((lane >> 4) << 3), bcolsel = ((lane >> 3) & 1) << 3;

    // prefetch coords: A 128x4 slots (tid), W 256x4 slots (tid, tid+512)
    const int ar  = tid >> 2, au = tid & 3;
    const int wr0 = tid >> 2, wu0 = tid & 3;
    const int wr1 = (tid + 512) >> 2, wu1 = (tid + 512) & 3;

    float acc[4][4][4];
    #pragma unroll
    for (int i = 0; i < 4; ++i)
        #pragma unroll
        for (int j = 0; j < 4; ++j)
            #pragma unroll
            for (int k = 0; k < 4; ++k) acc[i][j][k] = 0.f;

    // prefetch chunk 0 -> stage 0
    {
        uint32_t stA = sb, stW = sb + 20480;
        CP16(stA + ar*80 + au*16,          Abh + (size_t)ar*D_ + au*8);
        CP16(stA + 10240 + ar*80 + au*16,  Abl + (size_t)ar*D_ + au*8);
        CP16(stW + wr0*80 + wu0*16,         Wbh + (size_t)wr0*D_ + wu0*8);
        CP16(stW + 20480 + wr0*80 + wu0*16, Wbl + (size_t)wr0*D_ + wu0*8);
        CP16(stW + wr1*80 + wu1*16,         Wbh + (size_t)wr1*D_ + wu1*8);
        CP16(stW + 20480 + wr1*80 + wu1*16, Wbl + (size_t)wr1*D_ + wu1*8);
        CP_COMMIT();
    }

    for (int kc = 0; kc < 32; ++kc) {
        int s = kc & 1;
        if (kc) __syncthreads();   // all warps done reading stage s^1 before overwrite
        if (kc + 1 < 32) {
            uint32_t stA = sb + (s^1)*GC_STAGE, stW = stA + 20480;
            int koff = (kc + 1) * 32;
            CP16(stA + ar*80 + au*16,          Abh + (size_t)ar*D_ + koff + au*8);
            CP16(stA + 10240 + ar*80 + au*16,  Abl + (size_t)ar*D_ + koff + au*8);
            CP16(stW + wr0*80 + wu0*16,         Wbh + (size_t)wr0*D_ + koff + wu0*8);
            CP16(stW + 20480 + wr0*80 + wu0*16, Wbl + (size_t)wr0*D_ + koff + wu0*8);
            CP16(stW + wr1*80 + wu1*16,         Wbh + (size_t)wr1*D_ + koff + wu1*8);
            CP16(stW + 20480 + wr1*80 + wu1*16, Wbl + (size_t)wr1*D_ + koff + wu1*8);
            CP_COMMIT();
            CP_WAIT1();
        } else {
            CP_WAIT0();
        }
        __syncthreads();

        const uint32_t aH = sb + s*GC_STAGE;
        const uint32_t aL = aH + 10240;
        const uint32_t bH = aH + 20480;
        const uint32_t bL = aH + 40960;

        #pragma unroll
        for (int ks = 0; ks < 2; ++ks) {
            uint32_t af[4][4], bhF[2][4], blF[2][4];
            #pragma unroll
            for (int mt = 0; mt < 4; ++mt) {
                uint32_t off = (uint32_t)(((wm*64 + mt*16 + arow)*AST + ks*16 + acolsel)*2);
                LDSM_X4(af[mt][0], af[mt][1], af[mt][2], af[mt][3], aH + off);
            }
            #pragma unroll
            for (int bp = 0; bp < 2; ++bp) {
                uint32_t off = (uint32_t)(((wn*32 + bp*16 + brow)*AST + ks*16 + bcolsel)*2);
                LDSM_X4(bhF[bp][0], bhF[bp][1], bhF[bp][2], bhF[bp][3], bH + off);
                LDSM_X4(blF[bp][0], blF[bp][1], blF[bp][2], blF[bp][3], bL + off);
            }
            #pragma unroll
            for (int mt = 0; mt < 4; ++mt)
                #pragma unroll
                for (int nt = 0; nt < 4; ++nt) {
                    MMA_BF16(acc[mt][nt], af[mt], bhF[nt>>1][(nt&1)*2], bhF[nt>>1][(nt&1)*2+1]);
                    MMA_BF16(acc[mt][nt], af[mt], blF[nt>>1][(nt&1)*2], blF[nt>>1][(nt&1)*2+1]);
                }
            #pragma unroll
            for (int mt = 0; mt < 4; ++mt) {
                uint32_t off = (uint32_t)(((wm*64 + mt*16 + arow)*AST + ks*16 + acolsel)*2);
                LDSM_X4(af[mt][0], af[mt][1], af[mt][2], af[mt][3], aL + off);
            }
            #pragma unroll
            for (int mt = 0; mt < 4; ++mt)
                #pragma unroll
                for (int nt = 0; nt < 4; ++nt)
                    MMA_BF16(acc[mt][nt], af[mt], bhF[nt>>1][(nt&1)*2], bhF[nt>>1][(nt&1)*2+1]);
        }
    }
    #pragma unroll
    for (int mt = 0; mt < 4; ++mt) {
        size_t r0 = mbase + wm*64 + mt*16 + (lane >> 2);
        #pragma unroll
        for (int nt = 0; nt < 4; ++nt) {
            int col = (int)nbase + wn*32 + nt*8 + 2*(lane & 3);
            float bx = bias[col], by = bias[col+1];
            *(float2*)(C + r0*D_ + col)     = make_float2(acc[mt][nt][0]+bx, acc[mt][nt][1]+by);
            *(float2*)(C + (r0+8)*D_ + col) = make_float2(acc[mt][nt][2]+bx, acc[mt][nt][3]+by);
        }
    }
}

// ---------------- init / hk ----------------
__global__ void init_kernel() { if (threadIdx.x == 0) g_kstab = 0xFF800000u; }

__global__ __launch_bounds__(256) void hk_kernel() {
    int gid = blockIdx.x * 256 + threadIdx.x;
    int b = gid / (H_*L_), rem = gid % (H_*L_), h = rem / L_, l = rem % L_;
    const float4* row = (const float4*)(g_Kp + (size_t)(b*L_ + l)*D_ + h*DH_);
    float s = 0.f;
    #pragma unroll
    for (int t = 0; t < 16; ++t) {
        float4 v = row[t];
        s = fmaf(v.x,v.x,s); s = fmaf(v.y,v.y,s); s = fmaf(v.z,v.z,s); s = fmaf(v.w,v.w,s);
    }
    float hk = -0.5f * SCALE2 * s;
    g_hk[gid] = hk;
    float m = hk;
    #pragma unroll
    for (int o = 16; o > 0; o >>= 1) m = fmaxf(m, __shfl_xor_sync(0xffffffffu, m, o));
    __shared__ float wmax[8];
    if ((threadIdx.x & 31) == 0) wmax[threadIdx.x >> 5] = m;
    __syncthreads();
    if (threadIdx.x == 0) {
        float bm = wmax[0];
        #pragma unroll
        for (int w = 1; w < 8; ++w) bm = fmaxf(bm, wmax[w]);
        atomicMin(&g_kstab, __float_as_uint(bm));
    }
}

// ================= fused kv kernel (unchanged) =================
#define KST 296
#define KW_WFH 0
#define KW_WFL 41472
#define KW_XH  82944
#define KW_XL  92160
#define KW_KH  101376
#define KW_KL  139264
#define KW_VH  177152
#define KW_VL  186368
#define KW_HK  195584
#define KW_MS  195840
#define KW_SMEM 196096

__global__ __launch_bounds__(288, 1) void kv_mma(const float* __restrict__ Wf,
                                                 const float* __restrict__ mask) {
    extern __shared__ char sm[];
    const uint32_t sb = smem_u32(sm);
    const int tid = threadIdx.x, lane = tid & 31, w = tid >> 5;
    const int split = blockIdx.x, bh = blockIdx.y;
    const int b = bh / H_, h = bh % H_;
    const int arow = lane & 15, acolsel = (lane >> 4) << 3;
    const int brow = (lane & 7) + ((lane >> 4) << 3), bcolsel = ((lane >> 3) & 1) << 3;

    for (int i = tid; i < 288*18; i += 288) {
        int r = i / 18, u = i % 18;
        float4 v = make_float4(0.f,0.f,0.f,0.f);
        if (r < 266 && u < 16) v = *(const float4*)(Wf + r*64 + u*4);
        uint32_t h01,h23,l01,l23; cvt_split(v,h01,h23,l01,l23);
        *(uint2*)(sm + KW_WFH + (r*72 + u*4)*2) = make_uint2(h01,h23);
        *(uint2*)(sm + KW_WFL + (r*72 + u*4)*2) = make_uint2(l01,l23);
    }
    float kstab = __uint_as_float(g_kstab);

    float acc[2][9][4];
    #pragma unroll
    for (int t = 0; t < 2; ++t)
        #pragma unroll
        for (int n = 0; n < 9; ++n)
            #pragma unroll
            for (int k = 0; k < 4; ++k) acc[t][n][k] = 0.f;

    for (int c = 0; c < 8; ++c) {
        int lb = split*512 + c*64;
        __syncthreads();
        for (int i = tid; i < 64*16; i += 288) {
            int r = i >> 4, u = i & 15;
            float4 v = *(const float4*)(g_Kp + (size_t)(b*L_+lb+r)*D_ + h*64 + u*4);
            v.x*=SCALE; v.y*=SCALE; v.z*=SCALE; v.w*=SCALE;
            uint32_t h01,h23,l01,l23; cvt_split(v,h01,h23,l01,l23);
            *(uint2*)(sm + KW_XH + (r*72 + u*4)*2) = make_uint2(h01,h23);
            *(uint2*)(sm + KW_XL + (r*72 + u*4)*2) = make_uint2(l01,l23);
        }
        for (int i = tid; i < 64*18; i += 288) {
            int r = i / 18, u = i % 18;
            float4 v;
            if (u < 16) v = *(const float4*)(g_Vp + (size_t)(b*L_+lb+r)*D_ + h*64 + u*4);
            else if (u == 16) v = make_float4(1.f,0.f,0.f,0.f);
            else v = make_float4(0.f,0.f,0.f,0.f);
            uint32_t h01,h23,l01,l23; cvt_split(v,h01,h23,l01,l23);
            *(uint2*)(sm + KW_VH + (r*72 + u*4)*2) = make_uint2(h01,h23);
            *(uint2*)(sm + KW_VL + (r*72 + u*4)*2) = make_uint2(l01,l23);
        }
        if (tid < 64) {
            ((float*)(sm + KW_HK))[tid] = g_hk[(size_t)bh*L_ + lb + tid] - kstab;
            ((float*)(sm + KW_MS))[tid] = mask[b*L_ + lb + tid];
        }
        __syncthreads();
        const int r0 = lane >> 2, cb2 = (lane & 3)*2;
        #pragma unroll
        for (int lt = 0; lt < 4; ++lt) {
            float pa[4][4];
            #pragma unroll
            for (int n = 0; n < 4; ++n)
                #pragma unroll
                for (int k = 0; k < 4; ++k) pa[n][k] = 0.f;
            #pragma unroll
            for (int ks = 0; ks < 4; ++ks) {
                uint32_t ah[4], al[4];
                uint32_t aoff = (uint32_t)(((lt*16 + arow)*72 + ks*16 + acolsel)*2);
                LDSM_X4(ah[0],ah[1],ah[2],ah[3], sb + KW_XH + aoff);
                LDSM_X4(al[0],al[1],al[2],al[3], sb + KW_XL + aoff);
                #pragma unroll
                for (int g = 0; g < 2; ++g) {
                    uint32_t boff = (uint32_t)((((2*w+g)*16 + brow)*72 + ks*16 + bcolsel)*2);
                    uint32_t bh_[4], bl_[4];
                    LDSM_X4(bh_[0],bh_[1],bh_[2],bh_[3], sb + KW_WFH + boff);
                    LDSM_X4(bl_[0],bl_[1],bl_[2],bl_[3], sb + KW_WFL + boff);
                    #pragma unroll
                    for (int half = 0; half < 2; ++half) {
                        int nt = 2*g + half;
                        MMA_BF16(pa[nt], ah, bh_[half*2], bh_[half*2+1]);
                        MMA_BF16(pa[nt], ah, bl_[half*2], bl_[half*2+1]);
                        MMA_BF16(pa[nt], al, bh_[half*2], bh_[half*2+1]);
                    }
                }
            }
            int ra = lt*16 + r0, rb = ra + 8;
            float ha = ((float*)(sm + KW_HK))[ra], hb = ((float*)(sm + KW_HK))[rb];
            float ma = ((float*)(sm + KW_MS))[ra], mb = ((float*)(sm + KW_MS))[rb];
            #pragma unroll
            for (int nt = 0; nt < 4; ++nt) {
                int c0 = 32*w + nt*8 + cb2;
                float e0=0.f,e1=0.f,e2=0.f,e3=0.f;
                if (c0 < M_)   { e0 = NC*(__expf(pa[nt][0]+ha)+KEPS)*ma; e2 = NC*(__expf(pa[nt][2]+hb)+KEPS)*mb; }
                if (c0+1 < M_) { e1 = NC*(__expf(pa[nt][1]+ha)+KEPS)*ma; e3 = NC*(__expf(pa[nt][3]+hb)+KEPS)*mb; }
                uint32_t hh, ll;
                cvt_split2(e0, e1, hh, ll);
                *(uint32_t*)(sm + KW_KH + (ra*KST + c0)*2) = hh;
                *(uint32_t*)(sm + KW_KL + (ra*KST + c0)*2) = ll;
                cvt_split2(e2, e3, hh, ll);
                *(uint32_t*)(sm + KW_KH + (rb*KST + c0)*2) = hh;
                *(uint32_t*)(sm + KW_KL + (rb*KST + c0)*2) = ll;
            }
        }
        __syncthreads();
        #pragma unroll
        for (int ks = 0; ks < 4; ++ks) {
            uint32_t ah2[2][4], al2[2][4];
            #pragma unroll
            for (int t = 0; t < 2; ++t) {
                uint32_t off = (uint32_t)(((ks*16 + brow)*KST + (2*w + t)*16 + bcolsel)*2);
                LDSM_X4T(ah2[t][0],ah2[t][1],ah2[t][2],ah2[t][3], sb + KW_KH + off);
                LDSM_X4T(al2[t][0],al2[t][1],al2[t][2],al2[t][3], sb + KW_KL + off);
            }
            uint32_t bh4[4][4], bl4[4][4], bh2[2], bl2[2];
            #pragma unroll
            for (int g = 0; g < 4; ++g) {
                uint32_t off = (uint32_t)(((ks*16 + arow)*72 + g*16 + acolsel)*2);
                LDSM_X4T(bh4[g][0],bh4[g][1],bh4[g][2],bh4[g][3], sb + KW_VH + off);
                LDSM_X4T(bl4[g][0],bl4[g][1],bl4[g][2],bl4[g][3], sb + KW_VL + off);
            }
            uint32_t off2 = (uint32_t)(((ks*16 + (lane & 15))*72 + 64)*2);
            LDSM_X2T(bh2[0], bh2[1], sb + KW_VH + off2);
            LDSM_X2T(bl2[0], bl2[1], sb + KW_VL + off2);
            #pragma unroll
            for (int t = 0; t < 2; ++t)
                #pragma unroll
                for (int nt = 0; nt < 9; ++nt) {
                    uint32_t p0 = (nt < 8) ? bh4[nt>>1][(nt&1)*2]   : bh2[0];
                    uint32_t p1 = (nt < 8) ? bh4[nt>>1][(nt&1)*2+1] : bh2[1];
                    uint32_t q0 = (nt < 8) ? bl4[nt>>1][(nt&1)*2]   : bl2[0];
                    uint32_t q1 = (nt < 8) ? bl4[nt>>1][(nt&1)*2+1] : bl2[1];
                    MMA_BF16(acc[t][nt], ah2[t], p0, p1);
                    MMA_BF16(acc[t][nt], ah2[t], q0, q1);
                    MMA_BF16(acc[t][nt], al2[t], p0, p1);
                }
        }
    }
    float* base = g_kvpart + (size_t)(split*BH + bh)*KVROW*KVCOL;
    #pragma unroll
    for (int t = 0; t < 2; ++t) {
        int m0 = w*32 + t*16;
        if (m0 < KVROW) {
            int r0 = m0 + (lane >> 2);
            #pragma unroll
            for (int nt = 0; nt < 9; ++nt) {
                int c0 = nt*8 + (lane & 3)*2;
                *(float2*)(base + (size_t)r0*KVCOL + c0)     = make_float2(acc[t][nt][0], acc[t][nt][1]);
                *(float2*)(base + (size_t)(r0+8)*KVCOL + c0) = make_float2(acc[t][nt][2], acc[t][nt][3]);
            }
        }
    }
}

__global__ void kv_reduce() {
    int idx = blockIdx.x * 256 + threadIdx.x;
    if (idx < KVSZ2) {
        float s = 0.f;
        #pragma unroll
        for (int p = 0; p < SPLIT; ++p) s += g_kvpart[(size_t)p*KVSZ2 + idx];
        g_kv[idx] = s;
    }
}

// ================= fused out kernel (unchanged) =================
#define OW_KVH 0
#define OW_KVL 41472
#define OW_XH  82944
#define OW_XL  101376
#define OW_QH  119808
#define OW_QL  130048
#define OW_WFH 140288
#define OW_WFL 144896
#define OW_SMEM 149504

__global__ __launch_bounds__(256, 1) void out_mma(const float* __restrict__ Wf) {
    extern __shared__ char sm[];
    const uint32_t sb = smem_u32(sm);
    const int tid = threadIdx.x, lane = tid & 31, w = tid >> 5;
    const int h = blockIdx.y, b = blockIdx.z, bh = b*H_ + h;
    const int l0 = blockIdx.x * 128;
    const int arow = lane & 15, acolsel = (lane >> 4) << 3;
    const int brow = (lane & 7) + ((lane >> 4) << 3), bcolsel = ((lane >> 3) & 1) << 3;

    for (int i = tid; i < 82944/4; i += 256) ((uint32_t*)sm)[i] = 0;
    __syncthreads();
    for (int i = tid; i < KVROW*18; i += 256) {
        int r = i / 18, u = i % 18;
        float4 v = *(const float4*)(g_kv + ((size_t)bh*KVROW + r)*KVCOL + u*4);
        uint32_t h01,h23,l01,l23; cvt_split(v,h01,h23,l01,l23);
        *(uint2*)(sm + OW_KVH + (r*72 + u*4)*2) = make_uint2(h01,h23);
        *(uint2*)(sm + OW_KVL + (r*72 + u*4)*2) = make_uint2(l01,l23);
    }
    for (int i = tid; i < 128*16; i += 256) {
        int r = i >> 4, u = i & 15;
        float4 v = *(const float4*)(g_Qp + (size_t)(b*L_+l0+r)*D_ + h*64 + u*4);
        v.x*=SCALE; v.y*=SCALE; v.z*=SCALE; v.w*=SCALE;
        uint32_t h01,h23,l01,l23; cvt_split(v,h01,h23,l01,l23);
        *(uint2*)(sm + OW_XH + (r*72 + u*4)*2) = make_uint2(h01,h23);
        *(uint2*)(sm + OW_XL + (r*72 + u*4)*2) = make_uint2(l01,l23);
    }

    float acc[9][4];
    #pragma unroll
    for (int n = 0; n < 9; ++n)
        #pragma unroll
        for (int k = 0; k < 4; ++k) acc[n][k] = 0.f;

    const int r0 = lane >> 2, cb2 = (lane & 3)*2;

    for (int mc = 0; mc < 9; ++mc) {
        __syncthreads();
        for (int i = tid; i < 32*18; i += 256) {
            int r = i / 18, u = i % 18;
            int gr = mc*32 + r;
            float4 v = make_float4(0.f,0.f,0.f,0.f);
            if (gr < 266 && u < 16) v = *(const float4*)(Wf + gr*64 + u*4);
            uint32_t h01,h23,l01,l23; cvt_split(v,h01,h23,l01,l23);
            *(uint2*)(sm + OW_WFH + (r*72 + u*4)*2) = make_uint2(h01,h23);
            *(uint2*)(sm + OW_WFL + (r*72 + u*4)*2) = make_uint2(l01,l23);
        }
        __syncthreads();
        float pa[4][4];
        #pragma unroll
        for (int n = 0; n < 4; ++n)
            #pragma unroll
            for (int k = 0; k < 4; ++k) pa[n][k] = 0.f;
        #pragma unroll
        for (int ks = 0; ks < 4; ++ks) {
            uint32_t ah[4], al[4];
            uint32_t aoff = (uint32_t)(((w*16 + arow)*72 + ks*16 + acolsel)*2);
            LDSM_X4(ah[0],ah[1],ah[2],ah[3], sb + OW_XH + aoff);
            LDSM_X4(al[0],al[1],al[2],al[3], sb + OW_XL + aoff);
            #pragma unroll
            for (int g = 0; g < 2; ++g) {
                uint32_t boff = (uint32_t)(((g*16 + brow)*72 + ks*16 + bcolsel)*2);
                uint32_t bh_[4], bl_[4];
                LDSM_X4(bh_[0],bh_[1],bh_[2],bh_[3], sb + OW_WFH + boff);
                LDSM_X4(bl_[0],bl_[1],bl_[2],bl_[3], sb + OW_WFL + boff);
                #pragma unroll
                for (int half = 0; half < 2; ++half) {
                    int nt = 2*g + half;
                    MMA_BF16(pa[nt], ah, bh_[half*2], bh_[half*2+1]);
                    MMA_BF16(pa[nt], ah, bl_[half*2], bl_[half*2+1]);
                    MMA_BF16(pa[nt], al, bh_[half*2], bh_[half*2+1]);
                }
            }
        }
        {
            int ra = w*16 + r0, rb = ra + 8;
            #pragma unroll
            for (int nt = 0; nt < 4; ++nt) {
                int lc = nt*8 + cb2;
                int gc = mc*32 + lc;
                float e0=0.f,e1=0.f,e2=0.f,e3=0.f;
                if (gc < M_)   { e0 = NC*(__expf(pa[nt][0])+KEPS); e2 = NC*(__expf(pa[nt][2])+KEPS); }
                if (gc+1 < M_) { e1 = NC*(__expf(pa[nt][1])+KEPS); e3 = NC*(__expf(pa[nt][3])+KEPS); }
                uint32_t hh, ll;
                cvt_split2(e0, e1, hh, ll);
                *(uint32_t*)(sm + OW_QH + (ra*40 + lc)*2) = hh;
                *(uint32_t*)(sm + OW_QL + (ra*40 + lc)*2) = ll;
                cvt_split2(e2, e3, hh, ll);
                *(uint32_t*)(sm + OW_QH + (rb*40 + lc)*2) = hh;
                *(uint32_t*)(sm + OW_QL + (rb*40 + lc)*2) = ll;
            }
        }
        __syncthreads();
        #pragma unroll
        for (int ks = 0; ks < 2; ++ks) {
            int gk = mc*32 + ks*16;
            uint32_t ah[4], al[4];
            uint32_t aoff = (uint32_t)(((w*16 + arow)*40 + ks*16 + acolsel)*2);
            LDSM_X4(ah[0],ah[1],ah[2],ah[3], sb + OW_QH + aoff);
            LDSM_X4(al[0],al[1],al[2],al[3], sb + OW_QL + aoff);
            uint32_t bh4[4][4], bl4[4][4], bh2[2], bl2[2];
            #pragma unroll
            for (int g = 0; g < 4; ++g) {
                uint32_t off = (uint32_t)(((gk + arow)*72 + g*16 + acolsel)*2);
                LDSM_X4T(bh4[g][0],bh4[g][1],bh4[g][2],bh4[g][3], sb + OW_KVH + off);
                LDSM_X4T(bl4[g][0],bl4[g][1],bl4[g][2],bl4[g][3], sb + OW_KVL + off);
            }
            uint32_t off2 = (uint32_t)(((gk + (lane & 15))*72 + 64)*2);
            LDSM_X2T(bh2[0], bh2[1], sb + OW_KVH + off2);
            LDSM_X2T(bl2[0], bl2[1], sb + OW_KVL + off2);
            #pragma unroll
            for (int nt = 0; nt < 9; ++nt) {
                uint32_t p0 = (nt < 8) ? bh4[nt>>1][(nt&1)*2]   : bh2[0];
                uint32_t p1 = (nt < 8) ? bh4[nt>>1][(nt&1)*2+1] : bh2[1];
                uint32_t q0 = (nt < 8) ? bl4[nt>>1][(nt&1)*2]   : bl2[0];
                uint32_t q1 = (nt < 8) ? bl4[nt>>1][(nt&1)*2+1] : bl2[1];
                MMA_BF16(acc[nt], ah, p0, p1);
                MMA_BF16(acc[nt], ah, q0, q1);
                MMA_BF16(acc[nt], al, p0, p1);
            }
        }
    }
    float den0 = __shfl_sync(0xffffffffu, acc[8][0], lane & ~3);
    float den1 = __shfl_sync(0xffffffffu, acc[8][2], lane & ~3);
    if (fabsf(den0) <= NSTAB) den0 += 2.f*NSTAB;
    if (fabsf(den1) <= NSTAB) den1 += 2.f*NSTAB;
    float inv0 = 1.f/den0, inv1 = 1.f/den1;
    int rr = w*16 + r0;
    size_t gl0 = (size_t)(b*L_ + l0 + rr), gl1 = gl0 + 8;
    #pragma unroll
    for (int nt = 0; nt < 8; ++nt) {
        int c0 = nt*8 + cb2;
        uint32_t hh, ll;
        cvt_split2(acc[nt][0]*inv0, acc[nt][1]*inv0, hh, ll);
        *(uint32_t*)(g_ctxh + gl0*D_ + h*64 + c0) = hh;
        *(uint32_t*)(g_ctxl + gl0*D_ + h*64 + c0) = ll;
        cvt_split2(acc[nt][2]*inv1, acc[nt][3]*inv1, hh, ll);
        *(uint32_t*)(g_ctxh + gl1*D_ + h*64 + c0) = hh;
        *(uint32_t*)(g_ctxl + gl1*D_ + h*64 + c0) = ll;
    }
}

// ---------------- launch ----------------
extern "C" void kernel_launch(void* const* d_in, const int* in_sizes, int n_in,
                              void* d_out, int out_size) {
    const float* query = (const float*)d_in[0];
    const float* key   = (const float*)d_in[1];
    const float* value = (const float*)d_in[2];
    const float* mask  = (const float*)d_in[3];
    const float* Wq = (const float*)d_in[4];
    const float* bq = (const float*)d_in[5];
    const float* Wk = (const float*)d_in[6];
    const float* bk = (const float*)d_in[7];
    const float* Wv = (const float*)d_in[8];
    const float* bv = (const float*)d_in[9];
    const float* Wo = (const float*)d_in[10];
    const float* bo = (const float*)d_in[11];
    const float* Wf = (const float*)d_in[12];

    float *Qp, *Kp, *Vp;
    __nv_bfloat16 *ah, *al, *wh, *wl, *cth, *ctl;
    cudaGetSymbolAddress((void**)&Qp,  g_Qp);
    cudaGetSymbolAddress((void**)&Kp,  g_Kp);
    cudaGetSymbolAddress((void**)&Vp,  g_Vp);
    cudaGetSymbolAddress((void**)&ah,  g_ah);
    cudaGetSymbolAddress((void**)&al,  g_al);
    cudaGetSymbolAddress((void**)&wh,  g_wh);
    cudaGetSymbolAddress((void**)&wl,  g_wl);
    cudaGetSymbolAddress((void**)&cth, g_ctxh);
    cudaGetSymbolAddress((void**)&ctl, g_ctxl);

    cudaFuncSetAttribute(gemm_mma_c, cudaFuncAttributeMaxDynamicSharedMemorySize, GC_SMEM);
    cudaFuncSetAttribute(kv_mma,     cudaFuncAttributeMaxDynamicSharedMemorySize, KW_SMEM);
    cudaFuncSetAttribute(out_mma,    cudaFuncAttributeMaxDynamicSharedMemorySize, OW_SMEM);

    init_kernel<<<1, 32>>>();

    const int nA4 = BL*D_/4, nW4 = D_*D_/4;
    dim3 gg(D_/256, BL/128);

    split_kernel<<<nW4/256, 256>>>(Wq, wh, wl, nW4);
    split_kernel<<<nA4/256, 256>>>(query, ah, al, nA4);
    gemm_mma_c<<<gg, 512, GC_SMEM>>>(ah, al, wh, wl, bq, Qp);

    split_kernel<<<nW4/256, 256>>>(Wk, wh, wl, nW4);
    split_kernel<<<nA4/256, 256>>>(key, ah, al, nA4);
    gemm_mma_c<<<gg, 512, GC_SMEM>>>(ah, al, wh, wl, bk, Kp);

    split_kernel<<<nW4/256, 256>>>(Wv, wh, wl, nW4);
    split_kernel<<<nA4/256, 256>>>(value, ah, al, nA4);
    gemm_mma_c<<<gg, 512, GC_SMEM>>>(ah, al, wh, wl, bv, Vp);

    hk_kernel<<<(BH*L_)/256, 256>>>();

    kv_mma<<<dim3(SPLIT, BH), 288, KW_SMEM>>>(Wf, mask);
    kv_reduce<<<(KVSZ2 + 255)/256, 256>>>();

    out_mma<<<dim3(L_/128, H_, B_), 256, OW_SMEM>>>(Wf);

    split_kernel<<<nW4/256, 256>>>(Wo, wh, wl, nW4);
    gemm_mma_c<<<gg, 512, GC_SMEM>>>(cth, ctl, wh, wl, bo, (float*)d_out);
}

// round 13
// speedup vs baseline: 1.1379x; 1.1379x over previous
#include <cuda_runtime.h>
#include <cuda_bf16.h>
#include <cstdint>
#include <math.h>

#define B_   2
#define L_   8192
#define D_   1024
#define H_   16
#define DH_  64
#define M_   266
#define BL   (B_*L_)
#define BH   (B_*H_)

#define SCALE  0.17677669529663687f
#define SCALE2 0.03125f
#define NC     0.061313932f
#define KEPS   1e-4f
#define NSTAB  1e-6f

#define SPLIT  16
#define KVROW  272
#define KVCOL  72
#define KVSZ2  (BH*KVROW*KVCOL)

// ---------------- device scratch ----------------
__device__ float g_Qp[BL*D_];
__device__ float g_Kp[BL*D_];
__device__ float g_Vp[BL*D_];
__device__ float g_hk[BH*L_];
__device__ unsigned int g_kstab;
__device__ float g_kv[KVSZ2];
__device__ float g_kvpart[(size_t)SPLIT*KVSZ2];
// bf16 split buffers (separate per operand so split overlaps consumers safely)
__device__ __nv_bfloat16 g_qah[BL*D_], g_qal[BL*D_];
__device__ __nv_bfloat16 g_kah[BL*D_], g_kal[BL*D_];
__device__ __nv_bfloat16 g_vah[BL*D_], g_vaL[BL*D_];
__device__ __nv_bfloat16 g_wqh[D_*D_], g_wql[D_*D_];
__device__ __nv_bfloat16 g_wkh[D_*D_], g_wkl[D_*D_];
__device__ __nv_bfloat16 g_wvh[D_*D_], g_wvl[D_*D_];
__device__ __nv_bfloat16 g_woh[D_*D_], g_wol[D_*D_];
__device__ __nv_bfloat16 g_ctxh[BL*D_], g_ctxl[BL*D_];

// ================= helpers =================
__device__ __forceinline__ uint32_t smem_u32(const void* p) {
    uint32_t a;
    asm("{ .reg .u64 t; cvta.to.shared.u64 t, %1; cvt.u32.u64 %0, t; }" : "=r"(a) : "l"(p));
    return a;
}
__device__ __forceinline__ void cvt_split(float4 v, uint32_t& h01, uint32_t& h23,
                                          uint32_t& l01, uint32_t& l23) {
    asm("cvt.rn.bf16x2.f32 %0, %1, %2;" : "=r"(h01) : "f"(v.y), "f"(v.x));
    asm("cvt.rn.bf16x2.f32 %0, %1, %2;" : "=r"(h23) : "f"(v.w), "f"(v.z));
    float r0 = v.x - __uint_as_float(h01 << 16);
    float r1 = v.y - __uint_as_float(h01 & 0xffff0000u);
    float r2 = v.z - __uint_as_float(h23 << 16);
    float r3 = v.w - __uint_as_float(h23 & 0xffff0000u);
    asm("cvt.rn.bf16x2.f32 %0, %1, %2;" : "=r"(l01) : "f"(r1), "f"(r0));
    asm("cvt.rn.bf16x2.f32 %0, %1, %2;" : "=r"(l23) : "f"(r3), "f"(r2));
}
__device__ __forceinline__ void cvt_split2(float a, float b, uint32_t& hh, uint32_t& ll) {
    asm("cvt.rn.bf16x2.f32 %0, %1, %2;" : "=r"(hh) : "f"(b), "f"(a));
    float ra = a - __uint_as_float(hh << 16);
    float rb = b - __uint_as_float(hh & 0xffff0000u);
    asm("cvt.rn.bf16x2.f32 %0, %1, %2;" : "=r"(ll) : "f"(rb), "f"(ra));
}
#define LDSM_X4(r0,r1,r2,r3,addr) \
    asm volatile("ldmatrix.sync.aligned.m8n8.x4.shared.b16 {%0,%1,%2,%3}, [%4];" \
        : "=r"(r0),"=r"(r1),"=r"(r2),"=r"(r3) : "r"(addr))
#define LDSM_X4T(r0,r1,r2,r3,addr) \
    asm volatile("ldmatrix.sync.aligned.m8n8.x4.trans.shared.b16 {%0,%1,%2,%3}, [%4];" \
        : "=r"(r0),"=r"(r1),"=r"(r2),"=r"(r3) : "r"(addr))
#define LDSM_X2T(r0,r1,addr) \
    asm volatile("ldmatrix.sync.aligned.m8n8.x2.trans.shared.b16 {%0,%1}, [%2];" \
        : "=r"(r0),"=r"(r1) : "r"(addr))
#define MMA_BF16(d,a,b0_,b1_) \
    asm volatile("mma.sync.aligned.m16n8k16.row.col.f32.bf16.bf16.f32 " \
        "{%0,%1,%2,%3}, {%4,%5,%6,%7}, {%8,%9}, {%0,%1,%2,%3};" \
        : "+f"((d)[0]),"+f"((d)[1]),"+f"((d)[2]),"+f"((d)[3]) \
        : "r"((a)[0]),"r"((a)[1]),"r"((a)[2]),"r"((a)[3]),"r"(b0_),"r"(b1_))
#define CP16(dst, src) \
    asm volatile("cp.async.cg.shared.global [%0], [%1], 16;" :: "r"(dst), "l"(src))
#define CP_COMMIT() asm volatile("cp.async.commit_group;" ::: "memory")
#define CP_WAIT1()  asm volatile("cp.async.wait_group 1;" ::: "memory")
#define CP_WAIT0()  asm volatile("cp.async.wait_group 0;" ::: "memory")

// ================= fp32 -> bf16 hi/lo split (streaming) =================
__global__ __launch_bounds__(256) void split_kernel(const float* __restrict__ X,
                                                    __nv_bfloat16* __restrict__ hi,
                                                    __nv_bfloat16* __restrict__ lo,
                                                    int n4) {
    int i = blockIdx.x * 256 + threadIdx.x;
    if (i < n4) {
        float4 v = ((const float4*)X)[i];
        uint32_t h01, h23, l01, l23;
        cvt_split(v, h01, h23, l01, l23);
        ((uint2*)hi)[i] = make_uint2(h01, h23);
        ((uint2*)lo)[i] = make_uint2(l01, l23);
    }
}

// ================= bf16x3 GEMM, pre-split operands (R11 proven: 269.7us) =================
#define AST 40
#define GB_STAGE 40960
#define GB_SMEM  81920

__global__ __launch_bounds__(256, 2) void gemm_mma_b(const __nv_bfloat16* __restrict__ Ah_,
                                                     const __nv_bfloat16* __restrict__ Al_,
                                                     const __nv_bfloat16* __restrict__ Wh_,
                                                     const __nv_bfloat16* __restrict__ Wl_,
                                                     const float* __restrict__ bias,
                                                     float* __restrict__ C) {
    extern __shared__ char smg[];
    const uint32_t sb = smem_u32(smg);
    const int tid = threadIdx.x, lane = tid & 31, wid = tid >> 5;
    const int wm = wid & 1, wn = wid >> 1;
    const size_t mbase = (size_t)blockIdx.y * 128, nbase = (size_t)blockIdx.x * 128;
    const __nv_bfloat16* Abh = Ah_ + mbase * D_;
    const __nv_bfloat16* Abl = Al_ + mbase * D_;
    const __nv_bfloat16* Wbh = Wh_ + nbase * D_;
    const __nv_bfloat16* Wbl = Wl_ + nbase * D_;

    const int arow = lane & 15, acolsel = (lane >> 4) << 3;
    const int brow = (lane & 7) + ((lane >> 4) << 3), bcolsel = ((lane >> 3) & 1) << 3;

    const int pr0 = tid >> 2,         pu0 = tid & 3;
    const int pr1 = (tid + 256) >> 2, pu1 = (tid + 256) & 3;

    float acc[4][4][4];
    #pragma unroll
    for (int i = 0; i < 4; ++i)
        #pragma unroll
        for (int j = 0; j < 4; ++j)
            #pragma unroll
            for (int k = 0; k < 4; ++k) acc[i][j][k] = 0.f;

    {
        uint32_t d0 = sb + pr0*80 + pu0*16;
        uint32_t d1 = sb + pr1*80 + pu1*16;
        size_t s0 = (size_t)pr0*D_ + pu0*8;
        size_t s1 = (size_t)pr1*D_ + pu1*8;
        CP16(d0,          Abh + s0); CP16(d0 + 10240, Abl + s0);
        CP16(d0 + 20480,  Wbh + s0); CP16(d0 + 30720, Wbl + s0);
        CP16(d1,          Abh + s1); CP16(d1 + 10240, Abl + s1);
        CP16(d1 + 20480,  Wbh + s1); CP16(d1 + 30720, Wbl + s1);
        CP_COMMIT();
    }

    for (int kc = 0; kc < 32; ++kc) {
        int s = kc & 1;
        if (kc) __syncthreads();
        if (kc + 1 < 32) {
            uint32_t base = sb + (s^1)*GB_STAGE;
            int koff = (kc + 1) * 32;
            uint32_t d0 = base + pr0*80 + pu0*16;
            uint32_t d1 = base + pr1*80 + pu1*16;
            size_t s0 = (size_t)pr0*D_ + koff + pu0*8;
            size_t s1 = (size_t)pr1*D_ + koff + pu1*8;
            CP16(d0,          Abh + s0); CP16(d0 + 10240, Abl + s0);
            CP16(d0 + 20480,  Wbh + s0); CP16(d0 + 30720, Wbl + s0);
            CP16(d1,          Abh + s1); CP16(d1 + 10240, Abl + s1);
            CP16(d1 + 20480,  Wbh + s1); CP16(d1 + 30720, Wbl + s1);
            CP_COMMIT();
            CP_WAIT1();
        } else {
            CP_WAIT0();
        }
        __syncthreads();

        const uint32_t aH = sb + s*GB_STAGE;
        const uint32_t aL = aH + 10240;
        const uint32_t bH = aH + 20480;
        const uint32_t bL = aH + 30720;

        #pragma unroll
        for (int ks = 0; ks < 2; ++ks) {
            uint32_t af[4][4], bhF[2][4], blF[2][4];
            #pragma unroll
            for (int mt = 0; mt < 4; ++mt) {
                uint32_t off = (uint32_t)(((wm*64 + mt*16 + arow)*AST + ks*16 + acolsel)*2);
                LDSM_X4(af[mt][0], af[mt][1], af[mt][2], af[mt][3], aH + off);
            }
            #pragma unroll
            for (int bp = 0; bp < 2; ++bp) {
                uint32_t off = (uint32_t)(((wn*32 + bp*16 + brow)*AST + ks*16 + bcolsel)*2);
                LDSM_X4(bhF[bp][0], bhF[bp][1], bhF[bp][2], bhF[bp][3], bH + off);
                LDSM_X4(blF[bp][0], blF[bp][1], blF[bp][2], blF[bp][3], bL + off);
            }
            #pragma unroll
            for (int mt = 0; mt < 4; ++mt)
                #pragma unroll
                for (int nt = 0; nt < 4; ++nt) {
                    MMA_BF16(acc[mt][nt], af[mt], bhF[nt>>1][(nt&1)*2], bhF[nt>>1][(nt&1)*2+1]);
                    MMA_BF16(acc[mt][nt], af[mt], blF[nt>>1][(nt&1)*2], blF[nt>>1][(nt&1)*2+1]);
                }
            #pragma unroll
            for (int mt = 0; mt < 4; ++mt) {
                uint32_t off = (uint32_t)(((wm*64 + mt*16 + arow)*AST + ks*16 + acolsel)*2);
                LDSM_X4(af[mt][0], af[mt][1], af[mt][2], af[mt][3], aL + off);
            }
            #pragma unroll
            for (int mt = 0; mt < 4; ++mt)
                #pragma unroll
                for (int nt = 0; nt < 4; ++nt)
                    MMA_BF16(acc[mt][nt], af[mt], bhF[nt>>1][(nt&1)*2], bhF[nt>>1][(nt&1)*2+1]);
        }
    }
    #pragma unroll
    for (int mt = 0; mt < 4; ++mt) {
        size_t r0 = mbase + wm*64 + mt*16 + (lane >> 2);
        #pragma unroll
        for (int nt = 0; nt < 4; ++nt) {
            int col = (int)nbase + wn*32 + nt*8 + 2*(lane & 3);
            float bx = bias[col], by = bias[col+1];
            *(float2*)(C + r0*D_ + col)     = make_float2(acc[mt][nt][0]+bx, acc[mt][nt][1]+by);
            *(float2*)(C + (r0+8)*D_ + col) = make_float2(acc[mt][nt][2]+bx, acc[mt][nt][3]+by);
        }
    }
}

// ---------------- init / hk ----------------
__global__ void init_kernel() { if (threadIdx.x == 0) g_kstab = 0xFF800000u; }

__global__ __launch_bounds__(256) void hk_kernel() {
    int gid = blockIdx.x * 256 + threadIdx.x;
    int b = gid / (H_*L_), rem = gid % (H_*L_), h = rem / L_, l = rem % L_;
    const float4* row = (const float4*)(g_Kp + (size_t)(b*L_ + l)*D_ + h*DH_);
    float s = 0.f;
    #pragma unroll
    for (int t = 0; t < 16; ++t) {
        float4 v = row[t];
        s = fmaf(v.x,v.x,s); s = fmaf(v.y,v.y,s); s = fmaf(v.z,v.z,s); s = fmaf(v.w,v.w,s);
    }
    float hk = -0.5f * SCALE2 * s;
    g_hk[gid] = hk;
    float m = hk;
    #pragma unroll
    for (int o = 16; o > 0; o >>= 1) m = fmaxf(m, __shfl_xor_sync(0xffffffffu, m, o));
    __shared__ float wmax[8];
    if ((threadIdx.x & 31) == 0) wmax[threadIdx.x >> 5] = m;
    __syncthreads();
    if (threadIdx.x == 0) {
        float bm = wmax[0];
        #pragma unroll
        for (int w = 1; w < 8; ++w) bm = fmaxf(bm, wmax[w]);
        atomicMin(&g_kstab, __float_as_uint(bm));
    }
}

// ================= fused kv kernel (R11 proven) =================
#define KST 296
#define KW_WFH 0
#define KW_WFL 41472
#define KW_XH  82944
#define KW_XL  92160
#define KW_KH  101376
#define KW_KL  139264
#define KW_VH  177152
#define KW_VL  186368
#define KW_HK  195584
#define KW_MS  195840
#define KW_SMEM 196096

__global__ __launch_bounds__(288, 1) void kv_mma(const float* __restrict__ Wf,
                                                 const float* __restrict__ mask) {
    extern __shared__ char sm[];
    const uint32_t sb = smem_u32(sm);
    const int tid = threadIdx.x, lane = tid & 31, w = tid >> 5;
    const int split = blockIdx.x, bh = blockIdx.y;
    const int b = bh / H_, h = bh % H_;
    const int arow = lane & 15, acolsel = (lane >> 4) << 3;
    const int brow = (lane & 7) + ((lane >> 4) << 3), bcolsel = ((lane >> 3) & 1) << 3;

    for (int i = tid; i < 288*18; i += 288) {
        int r = i / 18, u = i % 18;
        float4 v = make_float4(0.f,0.f,0.f,0.f);
        if (r < 266 && u < 16) v = *(const float4*)(Wf + r*64 + u*4);
        uint32_t h01,h23,l01,l23; cvt_split(v,h01,h23,l01,l23);
        *(uint2*)(sm + KW_WFH + (r*72 + u*4)*2) = make_uint2(h01,h23);
        *(uint2*)(sm + KW_WFL + (r*72 + u*4)*2) = make_uint2(l01,l23);
    }
    float kstab = __uint_as_float(g_kstab);

    float acc[2][9][4];
    #pragma unroll
    for (int t = 0; t < 2; ++t)
        #pragma unroll
        for (int n = 0; n < 9; ++n)
            #pragma unroll
            for (int k = 0; k < 4; ++k) acc[t][n][k] = 0.f;

    for (int c = 0; c < 8; ++c) {
        int lb = split*512 + c*64;
        __syncthreads();
        for (int i = tid; i < 64*16; i += 288) {
            int r = i >> 4, u = i & 15;
            float4 v = *(const float4*)(g_Kp + (size_t)(b*L_+lb+r)*D_ + h*64 + u*4);
            v.x*=SCALE; v.y*=SCALE; v.z*=SCALE; v.w*=SCALE;
            uint32_t h01,h23,l01,l23; cvt_split(v,h01,h23,l01,l23);
            *(uint2*)(sm + KW_XH + (r*72 + u*4)*2) = make_uint2(h01,h23);
            *(uint2*)(sm + KW_XL + (r*72 + u*4)*2) = make_uint2(l01,l23);
        }
        for (int i = tid; i < 64*18; i += 288) {
            int r = i / 18, u = i % 18;
            float4 v;
            if (u < 16) v = *(const float4*)(g_Vp + (size_t)(b*L_+lb+r)*D_ + h*64 + u*4);
            else if (u == 16) v = make_float4(1.f,0.f,0.f,0.f);
            else v = make_float4(0.f,0.f,0.f,0.f);
            uint32_t h01,h23,l01,l23; cvt_split(v,h01,h23,l01,l23);
            *(uint2*)(sm + KW_VH + (r*72 + u*4)*2) = make_uint2(h01,h23);
            *(uint2*)(sm + KW_VL + (r*72 + u*4)*2) = make_uint2(l01,l23);
        }
        if (tid < 64) {
            ((float*)(sm + KW_HK))[tid] = g_hk[(size_t)bh*L_ + lb + tid] - kstab;
            ((float*)(sm + KW_MS))[tid] = mask[b*L_ + lb + tid];
        }
        __syncthreads();
        const int r0 = lane >> 2, cb2 = (lane & 3)*2;
        #pragma unroll
        for (int lt = 0; lt < 4; ++lt) {
            float pa[4][4];
            #pragma unroll
            for (int n = 0; n < 4; ++n)
                #pragma unroll
                for (int k = 0; k < 4; ++k) pa[n][k] = 0.f;
            #pragma unroll
            for (int ks = 0; ks < 4; ++ks) {
                uint32_t ah[4], al[4];
                uint32_t aoff = (uint32_t)(((lt*16 + arow)*72 + ks*16 + acolsel)*2);
                LDSM_X4(ah[0],ah[1],ah[2],ah[3], sb + KW_XH + aoff);
                LDSM_X4(al[0],al[1],al[2],al[3], sb + KW_XL + aoff);
                #pragma unroll
                for (int g = 0; g < 2; ++g) {
                    uint32_t boff = (uint32_t)((((2*w+g)*16 + brow)*72 + ks*16 + bcolsel)*2);
                    uint32_t bh_[4], bl_[4];
                    LDSM_X4(bh_[0],bh_[1],bh_[2],bh_[3], sb + KW_WFH + boff);
                    LDSM_X4(bl_[0],bl_[1],bl_[2],bl_[3], sb + KW_WFL + boff);
                    #pragma unroll
                    for (int half = 0; half < 2; ++half) {
                        int nt = 2*g + half;
                        MMA_BF16(pa[nt], ah, bh_[half*2], bh_[half*2+1]);
                        MMA_BF16(pa[nt], ah, bl_[half*2], bl_[half*2+1]);
                        MMA_BF16(pa[nt], al, bh_[half*2], bh_[half*2+1]);
                    }
                }
            }
            int ra = lt*16 + r0, rb = ra + 8;
            float ha = ((float*)(sm + KW_HK))[ra], hb = ((float*)(sm + KW_HK))[rb];
            float ma = ((float*)(sm + KW_MS))[ra], mb = ((float*)(sm + KW_MS))[rb];
            #pragma unroll
            for (int nt = 0; nt < 4; ++nt) {
                int c0 = 32*w + nt*8 + cb2;
                float e0=0.f,e1=0.f,e2=0.f,e3=0.f;
                if (c0 < M_)   { e0 = NC*(__expf(pa[nt][0]+ha)+KEPS)*ma; e2 = NC*(__expf(pa[nt][2]+hb)+KEPS)*mb; }
                if (c0+1 < M_) { e1 = NC*(__expf(pa[nt][1]+ha)+KEPS)*ma; e3 = NC*(__expf(pa[nt][3]+hb)+KEPS)*mb; }
                uint32_t hh, ll;
                cvt_split2(e0, e1, hh, ll);
                *(uint32_t*)(sm + KW_KH + (ra*KST + c0)*2) = hh;
                *(uint32_t*)(sm + KW_KL + (ra*KST + c0)*2) = ll;
                cvt_split2(e2, e3, hh, ll);
                *(uint32_t*)(sm + KW_KH + (rb*KST + c0)*2) = hh;
                *(uint32_t*)(sm + KW_KL + (rb*KST + c0)*2) = ll;
            }
        }
        __syncthreads();
        #pragma unroll
        for (int ks = 0; ks < 4; ++ks) {
            uint32_t ah2[2][4], al2[2][4];
            #pragma unroll
            for (int t = 0; t < 2; ++t) {
                uint32_t off = (uint32_t)(((ks*16 + brow)*KST + (2*w + t)*16 + bcolsel)*2);
                LDSM_X4T(ah2[t][0],ah2[t][1],ah2[t][2],ah2[t][3], sb + KW_KH + off);
                LDSM_X4T(al2[t][0],al2[t][1],al2[t][2],al2[t][3], sb + KW_KL + off);
            }
            uint32_t bh4[4][4], bl4[4][4], bh2[2], bl2[2];
            #pragma unroll
            for (int g = 0; g < 4; ++g) {
                uint32_t off = (uint32_t)(((ks*16 + arow)*72 + g*16 + acolsel)*2);
                LDSM_X4T(bh4[g][0],bh4[g][1],bh4[g][2],bh4[g][3], sb + KW_VH + off);
                LDSM_X4T(bl4[g][0],bl4[g][1],bl4[g][2],bl4[g][3], sb + KW_VL + off);
            }
            uint32_t off2 = (uint32_t)(((ks*16 + (lane & 15))*72 + 64)*2);
            LDSM_X2T(bh2[0], bh2[1], sb + KW_VH + off2);
            LDSM_X2T(bl2[0], bl2[1], sb + KW_VL + off2);
            #pragma unroll
            for (int t = 0; t < 2; ++t)
                #pragma unroll
                for (int nt = 0; nt < 9; ++nt) {
                    uint32_t p0 = (nt < 8) ? bh4[nt>>1][(nt&1)*2]   : bh2[0];
                    uint32_t p1 = (nt < 8) ? bh4[nt>>1][(nt&1)*2+1] : bh2[1];
                    uint32_t q0 = (nt < 8) ? bl4[nt>>1][(nt&1)*2]   : bl2[0];
                    uint32_t q1 = (nt < 8) ? bl4[nt>>1][(nt&1)*2+1] : bl2[1];
                    MMA_BF16(acc[t][nt], ah2[t], p0, p1);
                    MMA_BF16(acc[t][nt], ah2[t], q0, q1);
                    MMA_BF16(acc[t][nt], al2[t], p0, p1);
                }
        }
    }
    float* base = g_kvpart + (size_t)(split*BH + bh)*KVROW*KVCOL;
    #pragma unroll
    for (int t = 0; t < 2; ++t) {
        int m0 = w*32 + t*16;
        if (m0 < KVROW) {
            int r0 = m0 + (lane >> 2);
            #pragma unroll
            for (int nt = 0; nt < 9; ++nt) {
                int c0 = nt*8 + (lane & 3)*2;
                *(float2*)(base + (size_t)r0*KVCOL + c0)     = make_float2(acc[t][nt][0], acc[t][nt][1]);
                *(float2*)(base + (size_t)(r0+8)*KVCOL + c0) = make_float2(acc[t][nt][2], acc[t][nt][3]);
            }
        }
    }
}

__global__ void kv_reduce() {
    int idx = blockIdx.x * 256 + threadIdx.x;
    if (idx < KVSZ2) {
        float s = 0.f;
        #pragma unroll
        for (int p = 0; p < SPLIT; ++p) s += g_kvpart[(size_t)p*KVSZ2 + idx];
        g_kv[idx] = s;
    }
}

// ================= fused out kernel (R11 proven) =================
#define OW_KVH 0
#define OW_KVL 41472
#define OW_XH  82944
#define OW_XL  101376
#define OW_QH  119808
#define OW_QL  130048
#define OW_WFH 140288
#define OW_WFL 144896
#define OW_SMEM 149504

__global__ __launch_bounds__(256, 1) void out_mma(const float* __restrict__ Wf) {
    extern __shared__ char sm[];
    const uint32_t sb = smem_u32(sm);
    const int tid = threadIdx.x, lane = tid & 31, w = tid >> 5;
    const int h = blockIdx.y, b = blockIdx.z, bh = b*H_ + h;
    const int l0 = blockIdx.x * 128;
    const int arow = lane & 15, acolsel = (lane >> 4) << 3;
    const int brow = (lane & 7) + ((lane >> 4) << 3), bcolsel = ((lane >> 3) & 1) << 3;

    for (int i = tid; i < 82944/4; i += 256) ((uint32_t*)sm)[i] = 0;
    __syncthreads();
    for (int i = tid; i < KVROW*18; i += 256) {
        int r = i / 18, u = i % 18;
        float4 v = *(const float4*)(g_kv + ((size_t)bh*KVROW + r)*KVCOL + u*4);
        uint32_t h01,h23,l01,l23; cvt_split(v,h01,h23,l01,l23);
        *(uint2*)(sm + OW_KVH + (r*72 + u*4)*2) = make_uint2(h01,h23);
        *(uint2*)(sm + OW_KVL + (r*72 + u*4)*2) = make_uint2(l01,l23);
    }
    for (int i = tid; i < 128*16; i += 256) {
        int r = i >> 4, u = i & 15;
        float4 v = *(const float4*)(g_Qp + (size_t)(b*L_+l0+r)*D_ + h*64 + u*4);
        v.x*=SCALE; v.y*=SCALE; v.z*=SCALE; v.w*=SCALE;
        uint32_t h01,h23,l01,l23; cvt_split(v,h01,h23,l01,l23);
        *(uint2*)(sm + OW_XH + (r*72 + u*4)*2) = make_uint2(h01,h23);
        *(uint2*)(sm + OW_XL + (r*72 + u*4)*2) = make_uint2(l01,l23);
    }

    float acc[9][4];
    #pragma unroll
    for (int n = 0; n < 9; ++n)
        #pragma unroll
        for (int k = 0; k < 4; ++k) acc[n][k] = 0.f;

    const int r0 = lane >> 2, cb2 = (lane & 3)*2;

    for (int mc = 0; mc < 9; ++mc) {
        __syncthreads();
        for (int i = tid; i < 32*18; i += 256) {
            int r = i / 18, u = i % 18;
            int gr = mc*32 + r;
            float4 v = make_float4(0.f,0.f,0.f,0.f);
            if (gr < 266 && u < 16) v = *(const float4*)(Wf + gr*64 + u*4);
            uint32_t h01,h23,l01,l23; cvt_split(v,h01,h23,l01,l23);
            *(uint2*)(sm + OW_WFH + (r*72 + u*4)*2) = make_uint2(h01,h23);
            *(uint2*)(sm + OW_WFL + (r*72 + u*4)*2) = make_uint2(l01,l23);
        }
        __syncthreads();
        float pa[4][4];
        #pragma unroll
        for (int n = 0; n < 4; ++n)
            #pragma unroll
            for (int k = 0; k < 4; ++k) pa[n][k] = 0.f;
        #pragma unroll
        for (int ks = 0; ks < 4; ++ks) {
            uint32_t ah[4], al[4];
            uint32_t aoff = (uint32_t)(((w*16 + arow)*72 + ks*16 + acolsel)*2);
            LDSM_X4(ah[0],ah[1],ah[2],ah[3], sb + OW_XH + aoff);
            LDSM_X4(al[0],al[1],al[2],al[3], sb + OW_XL + aoff);
            #pragma unroll
            for (int g = 0; g < 2; ++g) {
                uint32_t boff = (uint32_t)(((g*16 + brow)*72 + ks*16 + bcolsel)*2);
                uint32_t bh_[4], bl_[4];
                LDSM_X4(bh_[0],bh_[1],bh_[2],bh_[3], sb + OW_WFH + boff);
                LDSM_X4(bl_[0],bl_[1],bl_[2],bl_[3], sb + OW_WFL + boff);
                #pragma unroll
                for (int half = 0; half < 2; ++half) {
                    int nt = 2*g + half;
                    MMA_BF16(pa[nt], ah, bh_[half*2], bh_[half*2+1]);
                    MMA_BF16(pa[nt], ah, bl_[half*2], bl_[half*2+1]);
                    MMA_BF16(pa[nt], al, bh_[half*2], bh_[half*2+1]);
                }
            }
        }
        {
            int ra = w*16 + r0, rb = ra + 8;
            #pragma unroll
            for (int nt = 0; nt < 4; ++nt) {
                int lc = nt*8 + cb2;
                int gc = mc*32 + lc;
                float e0=0.f,e1=0.f,e2=0.f,e3=0.f;
                if (gc < M_)   { e0 = NC*(__expf(pa[nt][0])+KEPS); e2 = NC*(__expf(pa[nt][2])+KEPS); }
                if (gc+1 < M_) { e1 = NC*(__expf(pa[nt][1])+KEPS); e3 = NC*(__expf(pa[nt][3])+KEPS); }
                uint32_t hh, ll;
                cvt_split2(e0, e1, hh, ll);
                *(uint32_t*)(sm + OW_QH + (ra*40 + lc)*2) = hh;
                *(uint32_t*)(sm + OW_QL + (ra*40 + lc)*2) = ll;
                cvt_split2(e2, e3, hh, ll);
                *(uint32_t*)(sm + OW_QH + (rb*40 + lc)*2) = hh;
                *(uint32_t*)(sm + OW_QL + (rb*40 + lc)*2) = ll;
            }
        }
        __syncthreads();
        #pragma unroll
        for (int ks = 0; ks < 2; ++ks) {
            int gk = mc*32 + ks*16;
            uint32_t ah[4], al[4];
            uint32_t aoff = (uint32_t)(((w*16 + arow)*40 + ks*16 + acolsel)*2);
            LDSM_X4(ah[0],ah[1],ah[2],ah[3], sb + OW_QH + aoff);
            LDSM_X4(al[0],al[1],al[2],al[3], sb + OW_QL + aoff);
            uint32_t bh4[4][4], bl4[4][4], bh2[2], bl2[2];
            #pragma unroll
            for (int g = 0; g < 4; ++g) {
                uint32_t off = (uint32_t)(((gk + arow)*72 + g*16 + acolsel)*2);
                LDSM_X4T(bh4[g][0],bh4[g][1],bh4[g][2],bh4[g][3], sb + OW_KVH + off);
                LDSM_X4T(bl4[g][0],bl4[g][1],bl4[g][2],bl4[g][3], sb + OW_KVL + off);
            }
            uint32_t off2 = (uint32_t)(((gk + (lane & 15))*72 + 64)*2);
            LDSM_X2T(bh2[0], bh2[1], sb + OW_KVH + off2);
            LDSM_X2T(bl2[0], bl2[1], sb + OW_KVL + off2);
            #pragma unroll
            for (int nt = 0; nt < 9; ++nt) {
                uint32_t p0 = (nt < 8) ? bh4[nt>>1][(nt&1)*2]   : bh2[0];
                uint32_t p1 = (nt < 8) ? bh4[nt>>1][(nt&1)*2+1] : bh2[1];
                uint32_t q0 = (nt < 8) ? bl4[nt>>1][(nt&1)*2]   : bl2[0];
                uint32_t q1 = (nt < 8) ? bl4[nt>>1][(nt&1)*2+1] : bl2[1];
                MMA_BF16(acc[nt], ah, p0, p1);
                MMA_BF16(acc[nt], ah, q0, q1);
                MMA_BF16(acc[nt], al, p0, p1);
            }
        }
    }
    float den0 = __shfl_sync(0xffffffffu, acc[8][0], lane & ~3);
    float den1 = __shfl_sync(0xffffffffu, acc[8][2], lane & ~3);
    if (fabsf(den0) <= NSTAB) den0 += 2.f*NSTAB;
    if (fabsf(den1) <= NSTAB) den1 += 2.f*NSTAB;
    float inv0 = 1.f/den0, inv1 = 1.f/den1;
    int rr = w*16 + r0;
    size_t gl0 = (size_t)(b*L_ + l0 + rr), gl1 = gl0 + 8;
    #pragma unroll
    for (int nt = 0; nt < 8; ++nt) {
        int c0 = nt*8 + cb2;
        uint32_t hh, ll;
        cvt_split2(acc[nt][0]*inv0, acc[nt][1]*inv0, hh, ll);
        *(uint32_t*)(g_ctxh + gl0*D_ + h*64 + c0) = hh;
        *(uint32_t*)(g_ctxl + gl0*D_ + h*64 + c0) = ll;
        cvt_split2(acc[nt][2]*inv1, acc[nt][3]*inv1, hh, ll);
        *(uint32_t*)(g_ctxh + gl1*D_ + h*64 + c0) = hh;
        *(uint32_t*)(g_ctxl + gl1*D_ + h*64 + c0) = ll;
    }
}

// ---------------- launch (dual-stream overlap of splits/hk with GEMMs) ----------------
extern "C" void kernel_launch(void* const* d_in, const int* in_sizes, int n_in,
                              void* d_out, int out_size) {
    const float* query = (const float*)d_in[0];
    const float* key   = (const float*)d_in[1];
    const float* value = (const float*)d_in[2];
    const float* mask  = (const float*)d_in[3];
    const float* Wq = (const float*)d_in[4];
    const float* bq = (const float*)d_in[5];
    const float* Wk = (const float*)d_in[6];
    const float* bk = (const float*)d_in[7];
    const float* Wv = (const float*)d_in[8];
    const float* bv = (const float*)d_in[9];
    const float* Wo = (const float*)d_in[10];
    const float* bo = (const float*)d_in[11];
    const float* Wf = (const float*)d_in[12];

    float *Qp, *Kp, *Vp;
    __nv_bfloat16 *qah,*qal,*kah,*kal,*vah,*vaL;
    __nv_bfloat16 *wqh,*wql,*wkh,*wkl,*wvh,*wvl,*woh,*wol,*cth,*ctl;
    cudaGetSymbolAddress((void**)&Qp,  g_Qp);
    cudaGetSymbolAddress((void**)&Kp,  g_Kp);
    cudaGetSymbolAddress((void**)&Vp,  g_Vp);
    cudaGetSymbolAddress((void**)&qah, g_qah); cudaGetSymbolAddress((void**)&qal, g_qal);
    cudaGetSymbolAddress((void**)&kah, g_kah); cudaGetSymbolAddress((void**)&kal, g_kal);
    cudaGetSymbolAddress((void**)&vah, g_vah); cudaGetSymbolAddress((void**)&vaL, g_vaL);
    cudaGetSymbolAddress((void**)&wqh, g_wqh); cudaGetSymbolAddress((void**)&wql, g_wql);
    cudaGetSymbolAddress((void**)&wkh, g_wkh); cudaGetSymbolAddress((void**)&wkl, g_wkl);
    cudaGetSymbolAddress((void**)&wvh, g_wvh); cudaGetSymbolAddress((void**)&wvl, g_wvl);
    cudaGetSymbolAddress((void**)&woh, g_woh); cudaGetSymbolAddress((void**)&wol, g_wol);
    cudaGetSymbolAddress((void**)&cth, g_ctxh); cudaGetSymbolAddress((void**)&ctl, g_ctxl);

    cudaFuncSetAttribute(gemm_mma_b, cudaFuncAttributeMaxDynamicSharedMemorySize, GB_SMEM);
    cudaFuncSetAttribute(kv_mma,     cudaFuncAttributeMaxDynamicSharedMemorySize, KW_SMEM);
    cudaFuncSetAttribute(out_mma,    cudaFuncAttributeMaxDynamicSharedMemorySize, OW_SMEM);

    // one-time side-stream + events (same device work every call; created on
    // the non-captured correctness run, reused identically during capture)
    static cudaStream_t s1 = nullptr;
    static cudaEvent_t eS, eQ, eK, eV, eWo, eG2, eHK;
    if (!s1) {
        cudaStreamCreateWithFlags(&s1, cudaStreamNonBlocking);
        cudaEventCreateWithFlags(&eS,  cudaEventDisableTiming);
        cudaEventCreateWithFlags(&eQ,  cudaEventDisableTiming);
        cudaEventCreateWithFlags(&eK,  cudaEventDisableTiming);
        cudaEventCreateWithFlags(&eV,  cudaEventDisableTiming);
        cudaEventCreateWithFlags(&eWo, cudaEventDisableTiming);
        cudaEventCreateWithFlags(&eG2, cudaEventDisableTiming);
        cudaEventCreateWithFlags(&eHK, cudaEventDisableTiming);
    }

    const int nA4 = BL*D_/4, nW4 = D_*D_/4;
    dim3 gg(D_/128, BL/128);

    init_kernel<<<1, 32>>>();
    cudaEventRecord(eS, 0);
    cudaStreamWaitEvent(s1, eS, 0);

    // side stream: all splits, then hk (after gemm2)
    split_kernel<<<nW4/256, 256, 0, s1>>>(Wq, wqh, wql, nW4);
    split_kernel<<<nA4/256, 256, 0, s1>>>(query, qah, qal, nA4);
    cudaEventRecord(eQ, s1);
    split_kernel<<<nW4/256, 256, 0, s1>>>(Wk, wkh, wkl, nW4);
    split_kernel<<<nA4/256, 256, 0, s1>>>(key, kah, kal, nA4);
    cudaEventRecord(eK, s1);
    split_kernel<<<nW4/256, 256, 0, s1>>>(Wv, wvh, wvl, nW4);
    split_kernel<<<nA4/256, 256, 0, s1>>>(value, vah, vaL, nA4);
    cudaEventRecord(eV, s1);
    split_kernel<<<nW4/256, 256, 0, s1>>>(Wo, woh, wol, nW4);
    cudaEventRecord(eWo, s1);

    // main stream: GEMMs
    cudaStreamWaitEvent(0, eQ, 0);
    gemm_mma_b<<<gg, 256, GB_SMEM>>>(qah, qal, wqh, wql, bq, Qp);
    cudaStreamWaitEvent(0, eK, 0);
    gemm_mma_b<<<gg, 256, GB_SMEM>>>(kah, kal, wkh, wkl, bk, Kp);
    cudaEventRecord(eG2, 0);
    cudaStreamWaitEvent(0, eV, 0);
    gemm_mma_b<<<gg, 256, GB_SMEM>>>(vah, vaL, wvh, wvl, bv, Vp);

    // hk on side stream, concurrent with gemm3
    cudaStreamWaitEvent(s1, eG2, 0);
    hk_kernel<<<(BH*L_)/256, 256, 0, s1>>>();
    cudaEventRecord(eHK, s1);

    // main stream: FAVOR+ chain + output GEMM
    cudaStreamWaitEvent(0, eHK, 0);
    kv_mma<<<dim3(SPLIT, BH), 288, KW_SMEM>>>(Wf, mask);
    kv_reduce<<<(KVSZ2 + 255)/256, 256>>>();
    out_mma<<<dim3(L_/128, H_, B_), 256, OW_SMEM>>>(Wf);
    cudaStreamWaitEvent(0, eWo, 0);
    gemm_mma_b<<<gg, 256, GB_SMEM>>>(cth, ctl, woh, wol, bo, (float*)d_out);
}

// round 14
// speedup vs baseline: 1.2017x; 1.0561x over previous
#include <cuda_runtime.h>
#include <cuda_bf16.h>
#include <cstdint>
#include <math.h>

#define B_   2
#define L_   8192
#define D_   1024
#define H_   16
#define DH_  64
#define M_   266
#define BL   (B_*L_)
#define BH   (B_*H_)

#define SCALE  0.17677669529663687f
#define SCALE2 0.03125f
#define NC     0.061313932f
#define KEPS   1e-4f
#define NSTAB  1e-6f

#define SPLIT  16
#define KVROW  272
#define KVCOL  72
#define KVSZ2  (BH*KVROW*KVCOL)

// ---------------- device scratch ----------------
__device__ float g_Qp[BL*D_];
__device__ float g_Kp[BL*D_];
__device__ float g_Vp[BL*D_];
__device__ float g_hk[BH*L_];
__device__ unsigned int g_kstab;
__device__ float g_kv[KVSZ2];
__device__ float g_kvpart[(size_t)SPLIT*KVSZ2];
__device__ __nv_bfloat16 g_qah[BL*D_], g_qal[BL*D_];
__device__ __nv_bfloat16 g_kah[BL*D_], g_kal[BL*D_];
__device__ __nv_bfloat16 g_vah[BL*D_], g_vaL[BL*D_];
__device__ __nv_bfloat16 g_wqh[D_*D_], g_wql[D_*D_];
__device__ __nv_bfloat16 g_wkh[D_*D_], g_wkl[D_*D_];
__device__ __nv_bfloat16 g_wvh[D_*D_], g_wvl[D_*D_];
__device__ __nv_bfloat16 g_woh[D_*D_], g_wol[D_*D_];
__device__ __nv_bfloat16 g_ctxh[BL*D_], g_ctxl[BL*D_];

// ================= helpers =================
__device__ __forceinline__ uint32_t smem_u32(const void* p) {
    uint32_t a;
    asm("{ .reg .u64 t; cvta.to.shared.u64 t, %1; cvt.u32.u64 %0, t; }" : "=r"(a) : "l"(p));
    return a;
}
__device__ __forceinline__ void cvt_split(float4 v, uint32_t& h01, uint32_t& h23,
                                          uint32_t& l01, uint32_t& l23) {
    asm("cvt.rn.bf16x2.f32 %0, %1, %2;" : "=r"(h01) : "f"(v.y), "f"(v.x));
    asm("cvt.rn.bf16x2.f32 %0, %1, %2;" : "=r"(h23) : "f"(v.w), "f"(v.z));
    float r0 = v.x - __uint_as_float(h01 << 16);
    float r1 = v.y - __uint_as_float(h01 & 0xffff0000u);
    float r2 = v.z - __uint_as_float(h23 << 16);
    float r3 = v.w - __uint_as_float(h23 & 0xffff0000u);
    asm("cvt.rn.bf16x2.f32 %0, %1, %2;" : "=r"(l01) : "f"(r1), "f"(r0));
    asm("cvt.rn.bf16x2.f32 %0, %1, %2;" : "=r"(l23) : "f"(r3), "f"(r2));
}
__device__ __forceinline__ void cvt_split2(float a, float b, uint32_t& hh, uint32_t& ll) {
    asm("cvt.rn.bf16x2.f32 %0, %1, %2;" : "=r"(hh) : "f"(b), "f"(a));
    float ra = a - __uint_as_float(hh << 16);
    float rb = b - __uint_as_float(hh & 0xffff0000u);
    asm("cvt.rn.bf16x2.f32 %0, %1, %2;" : "=r"(ll) : "f"(rb), "f"(ra));
}
#define LDSM_X4(r0,r1,r2,r3,addr) \
    asm volatile("ldmatrix.sync.aligned.m8n8.x4.shared.b16 {%0,%1,%2,%3}, [%4];" \
        : "=r"(r0),"=r"(r1),"=r"(r2),"=r"(r3) : "r"(addr))
#define LDSM_X4T(r0,r1,r2,r3,addr) \
    asm volatile("ldmatrix.sync.aligned.m8n8.x4.trans.shared.b16 {%0,%1,%2,%3}, [%4];" \
        : "=r"(r0),"=r"(r1),"=r"(r2),"=r"(r3) : "r"(addr))
#define LDSM_X2T(r0,r1,addr) \
    asm volatile("ldmatrix.sync.aligned.m8n8.x2.trans.shared.b16 {%0,%1}, [%2];" \
        : "=r"(r0),"=r"(r1) : "r"(addr))
#define MMA_BF16(d,a,b0_,b1_) \
    asm volatile("mma.sync.aligned.m16n8k16.row.col.f32.bf16.bf16.f32 " \
        "{%0,%1,%2,%3}, {%4,%5,%6,%7}, {%8,%9}, {%0,%1,%2,%3};" \
        : "+f"((d)[0]),"+f"((d)[1]),"+f"((d)[2]),"+f"((d)[3]) \
        : "r"((a)[0]),"r"((a)[1]),"r"((a)[2]),"r"((a)[3]),"r"(b0_),"r"(b1_))
#define CP16(dst, src) \
    asm volatile("cp.async.cg.shared.global [%0], [%1], 16;" :: "r"(dst), "l"(src))
#define CP_COMMIT() asm volatile("cp.async.commit_group;" ::: "memory")
#define CP_WAIT1()  asm volatile("cp.async.wait_group 1;" ::: "memory")
#define CP_WAIT0()  asm volatile("cp.async.wait_group 0;" ::: "memory")

// ================= fp32 -> bf16 hi/lo split =================
__global__ __launch_bounds__(256) void split_kernel(const float* __restrict__ X,
                                                    __nv_bfloat16* __restrict__ hi,
                                                    __nv_bfloat16* __restrict__ lo,
                                                    int n4) {
    int i = blockIdx.x * 256 + threadIdx.x;
    if (i < n4) {
        float4 v = ((const float4*)X)[i];
        uint32_t h01, h23, l01, l23;
        cvt_split(v, h01, h23, l01, l23);
        ((uint2*)hi)[i] = make_uint2(h01, h23);
        ((uint2*)lo)[i] = make_uint2(l01, l23);
    }
}

// ================= bf16x3 GEMM (R11 proven) =================
#define AST 40
#define GB_STAGE 40960
#define GB_SMEM  81920

__global__ __launch_bounds__(256, 2) void gemm_mma_b(const __nv_bfloat16* __restrict__ Ah_,
                                                     const __nv_bfloat16* __restrict__ Al_,
                                                     const __nv_bfloat16* __restrict__ Wh_,
                                                     const __nv_bfloat16* __restrict__ Wl_,
                                                     const float* __restrict__ bias,
                                                     float* __restrict__ C) {
    extern __shared__ char smg[];
    const uint32_t sb = smem_u32(smg);
    const int tid = threadIdx.x, lane = tid & 31, wid = tid >> 5;
    const int wm = wid & 1, wn = wid >> 1;
    const size_t mbase = (size_t)blockIdx.y * 128, nbase = (size_t)blockIdx.x * 128;
    const __nv_bfloat16* Abh = Ah_ + mbase * D_;
    const __nv_bfloat16* Abl = Al_ + mbase * D_;
    const __nv_bfloat16* Wbh = Wh_ + nbase * D_;
    const __nv_bfloat16* Wbl = Wl_ + nbase * D_;

    const int arow = lane & 15, acolsel = (lane >> 4) << 3;
    const int brow = (lane & 7) + ((lane >> 4) << 3), bcolsel = ((lane >> 3) & 1) << 3;

    const int pr0 = tid >> 2,         pu0 = tid & 3;
    const int pr1 = (tid + 256) >> 2, pu1 = (tid + 256) & 3;

    float acc[4][4][4];
    #pragma unroll
    for (int i = 0; i < 4; ++i)
        #pragma unroll
        for (int j = 0; j < 4; ++j)
            #pragma unroll
            for (int k = 0; k < 4; ++k) acc[i][j][k] = 0.f;

    {
        uint32_t d0 = sb + pr0*80 + pu0*16;
        uint32_t d1 = sb + pr1*80 + pu1*16;
        size_t s0 = (size_t)pr0*D_ + pu0*8;
        size_t s1 = (size_t)pr1*D_ + pu1*8;
        CP16(d0,          Abh + s0); CP16(d0 + 10240, Abl + s0);
        CP16(d0 + 20480,  Wbh + s0); CP16(d0 + 30720, Wbl + s0);
        CP16(d1,          Abh + s1); CP16(d1 + 10240, Abl + s1);
        CP16(d1 + 20480,  Wbh + s1); CP16(d1 + 30720, Wbl + s1);
        CP_COMMIT();
    }

    for (int kc = 0; kc < 32; ++kc) {
        int s = kc & 1;
        if (kc) __syncthreads();
        if (kc + 1 < 32) {
            uint32_t base = sb + (s^1)*GB_STAGE;
            int koff = (kc + 1) * 32;
            uint32_t d0 = base + pr0*80 + pu0*16;
            uint32_t d1 = base + pr1*80 + pu1*16;
            size_t s0 = (size_t)pr0*D_ + koff + pu0*8;
            size_t s1 = (size_t)pr1*D_ + koff + pu1*8;
            CP16(d0,          Abh + s0); CP16(d0 + 10240, Abl + s0);
            CP16(d0 + 20480,  Wbh + s0); CP16(d0 + 30720, Wbl + s0);
            CP16(d1,          Abh + s1); CP16(d1 + 10240, Abl + s1);
            CP16(d1 + 20480,  Wbh + s1); CP16(d1 + 30720, Wbl + s1);
            CP_COMMIT();
            CP_WAIT1();
        } else {
            CP_WAIT0();
        }
        __syncthreads();

        const uint32_t aH = sb + s*GB_STAGE;
        const uint32_t aL = aH + 10240;
        const uint32_t bH = aH + 20480;
        const uint32_t bL = aH + 30720;

        #pragma unroll
        for (int ks = 0; ks < 2; ++ks) {
            uint32_t af[4][4], bhF[2][4], blF[2][4];
            #pragma unroll
            for (int mt = 0; mt < 4; ++mt) {
                uint32_t off = (uint32_t)(((wm*64 + mt*16 + arow)*AST + ks*16 + acolsel)*2);
                LDSM_X4(af[mt][0], af[mt][1], af[mt][2], af[mt][3], aH + off);
            }
            #pragma unroll
            for (int bp = 0; bp < 2; ++bp) {
                uint32_t off = (uint32_t)(((wn*32 + bp*16 + brow)*AST + ks*16 + bcolsel)*2);
                LDSM_X4(bhF[bp][0], bhF[bp][1], bhF[bp][2], bhF[bp][3], bH + off);
                LDSM_X4(blF[bp][0], blF[bp][1], blF[bp][2], blF[bp][3], bL + off);
            }
            #pragma unroll
            for (int mt = 0; mt < 4; ++mt)
                #pragma unroll
                for (int nt = 0; nt < 4; ++nt) {
                    MMA_BF16(acc[mt][nt], af[mt], bhF[nt>>1][(nt&1)*2], bhF[nt>>1][(nt&1)*2+1]);
                    MMA_BF16(acc[mt][nt], af[mt], blF[nt>>1][(nt&1)*2], blF[nt>>1][(nt&1)*2+1]);
                }
            #pragma unroll
            for (int mt = 0; mt < 4; ++mt) {
                uint32_t off = (uint32_t)(((wm*64 + mt*16 + arow)*AST + ks*16 + acolsel)*2);
                LDSM_X4(af[mt][0], af[mt][1], af[mt][2], af[mt][3], aL + off);
            }
            #pragma unroll
            for (int mt = 0; mt < 4; ++mt)
                #pragma unroll
                for (int nt = 0; nt < 4; ++nt)
                    MMA_BF16(acc[mt][nt], af[mt], bhF[nt>>1][(nt&1)*2], bhF[nt>>1][(nt&1)*2+1]);
        }
    }
    #pragma unroll
    for (int mt = 0; mt < 4; ++mt) {
        size_t r0 = mbase + wm*64 + mt*16 + (lane >> 2);
        #pragma unroll
        for (int nt = 0; nt < 4; ++nt) {
            int col = (int)nbase + wn*32 + nt*8 + 2*(lane & 3);
            float bx = bias[col], by = bias[col+1];
            *(float2*)(C + r0*D_ + col)     = make_float2(acc[mt][nt][0]+bx, acc[mt][nt][1]+by);
            *(float2*)(C + (r0+8)*D_ + col) = make_float2(acc[mt][nt][2]+bx, acc[mt][nt][3]+by);
        }
    }
}

// ---------------- init / hk ----------------
__global__ void init_kernel() { if (threadIdx.x == 0) g_kstab = 0xFF800000u; }

__global__ __launch_bounds__(256) void hk_kernel() {
    int gid = blockIdx.x * 256 + threadIdx.x;
    int b = gid / (H_*L_), rem = gid % (H_*L_), h = rem / L_, l = rem % L_;
    const float4* row = (const float4*)(g_Kp + (size_t)(b*L_ + l)*D_ + h*DH_);
    float s = 0.f;
    #pragma unroll
    for (int t = 0; t < 16; ++t) {
        float4 v = row[t];
        s = fmaf(v.x,v.x,s); s = fmaf(v.y,v.y,s); s = fmaf(v.z,v.z,s); s = fmaf(v.w,v.w,s);
    }
    float hk = -0.5f * SCALE2 * s;
    g_hk[gid] = hk;
    float m = hk;
    #pragma unroll
    for (int o = 16; o > 0; o >>= 1) m = fmaxf(m, __shfl_xor_sync(0xffffffffu, m, o));
    __shared__ float wmax[8];
    if ((threadIdx.x & 31) == 0) wmax[threadIdx.x >> 5] = m;
    __syncthreads();
    if (threadIdx.x == 0) {
        float bm = wmax[0];
        #pragma unroll
        for (int w = 1; w < 8; ++w) bm = fmaxf(bm, wmax[w]);
        atomicMin(&g_kstab, __float_as_uint(bm));
    }
}

// ================= fused kv kernel: 576 threads / 18 warps =================
#define KVNT 576
#define KST 296
#define KW_WFH 0
#define KW_WFL 41472
#define KW_XH  82944
#define KW_XL  92160
#define KW_KH  101376
#define KW_KL  139264
#define KW_VH  177152
#define KW_VL  186368
#define KW_HK  195584
#define KW_MS  195840
#define KW_SMEM 196096

__global__ __launch_bounds__(KVNT, 1) void kv_mma(const float* __restrict__ Wf,
                                                  const float* __restrict__ mask) {
    extern __shared__ char sm[];
    const uint32_t sb = smem_u32(sm);
    const int tid = threadIdx.x, lane = tid & 31, w = tid >> 5;   // 18 warps
    const int split = blockIdx.x, bh = blockIdx.y;
    const int b = bh / H_, h = bh % H_;
    const int arow = lane & 15, acolsel = (lane >> 4) << 3;
    const int brow = (lane & 7) + ((lane >> 4) << 3), bcolsel = ((lane >> 3) & 1) << 3;

    for (int i = tid; i < 288*18; i += KVNT) {
        int r = i / 18, u = i % 18;
        float4 v = make_float4(0.f,0.f,0.f,0.f);
        if (r < 266 && u < 16) v = *(const float4*)(Wf + r*64 + u*4);
        uint32_t h01,h23,l01,l23; cvt_split(v,h01,h23,l01,l23);
        *(uint2*)(sm + KW_WFH + (r*72 + u*4)*2) = make_uint2(h01,h23);
        *(uint2*)(sm + KW_WFL + (r*72 + u*4)*2) = make_uint2(l01,l23);
    }
    float kstab = __uint_as_float(g_kstab);

    float acc[9][4];
    #pragma unroll
    for (int n = 0; n < 9; ++n)
        #pragma unroll
        for (int k = 0; k < 4; ++k) acc[n][k] = 0.f;

    for (int c = 0; c < 8; ++c) {
        int lb = split*512 + c*64;
        __syncthreads();
        for (int i = tid; i < 64*16; i += KVNT) {
            int r = i >> 4, u = i & 15;
            float4 v = *(const float4*)(g_Kp + (size_t)(b*L_+lb+r)*D_ + h*64 + u*4);
            v.x*=SCALE; v.y*=SCALE; v.z*=SCALE; v.w*=SCALE;
            uint32_t h01,h23,l01,l23; cvt_split(v,h01,h23,l01,l23);
            *(uint2*)(sm + KW_XH + (r*72 + u*4)*2) = make_uint2(h01,h23);
            *(uint2*)(sm + KW_XL + (r*72 + u*4)*2) = make_uint2(l01,l23);
        }
        for (int i = tid; i < 64*18; i += KVNT) {
            int r = i / 18, u = i % 18;
            float4 v;
            if (u < 16) v = *(const float4*)(g_Vp + (size_t)(b*L_+lb+r)*D_ + h*64 + u*4);
            else if (u == 16) v = make_float4(1.f,0.f,0.f,0.f);
            else v = make_float4(0.f,0.f,0.f,0.f);
            uint32_t h01,h23,l01,l23; cvt_split(v,h01,h23,l01,l23);
            *(uint2*)(sm + KW_VH + (r*72 + u*4)*2) = make_uint2(h01,h23);
            *(uint2*)(sm + KW_VL + (r*72 + u*4)*2) = make_uint2(l01,l23);
        }
        if (tid < 64) {
            ((float*)(sm + KW_HK))[tid] = g_hk[(size_t)bh*L_ + lb + tid] - kstab;
            ((float*)(sm + KW_MS))[tid] = mask[b*L_ + lb + tid];
        }
        __syncthreads();
        // proj: warp w owns feature cols 16w..16w+15 (288 = 18*16)
        const int r0 = lane >> 2, cb2 = (lane & 3)*2;
        #pragma unroll
        for (int lt = 0; lt < 4; ++lt) {
            float pa[2][4];
            #pragma unroll
            for (int n = 0; n < 2; ++n)
                #pragma unroll
                for (int k = 0; k < 4; ++k) pa[n][k] = 0.f;
            #pragma unroll
            for (int ks = 0; ks < 4; ++ks) {
                uint32_t ah[4], al[4];
                uint32_t aoff = (uint32_t)(((lt*16 + arow)*72 + ks*16 + acolsel)*2);
                LDSM_X4(ah[0],ah[1],ah[2],ah[3], sb + KW_XH + aoff);
                LDSM_X4(al[0],al[1],al[2],al[3], sb + KW_XL + aoff);
                uint32_t boff = (uint32_t)(((w*16 + brow)*72 + ks*16 + bcolsel)*2);
                uint32_t bh_[4], bl_[4];
                LDSM_X4(bh_[0],bh_[1],bh_[2],bh_[3], sb + KW_WFH + boff);
                LDSM_X4(bl_[0],bl_[1],bl_[2],bl_[3], sb + KW_WFL + boff);
                #pragma unroll
                for (int half = 0; half < 2; ++half) {
                    MMA_BF16(pa[half], ah, bh_[half*2], bh_[half*2+1]);
                    MMA_BF16(pa[half], ah, bl_[half*2], bl_[half*2+1]);
                    MMA_BF16(pa[half], al, bh_[half*2], bh_[half*2+1]);
                }
            }
            int ra = lt*16 + r0, rb = ra + 8;
            float ha = ((float*)(sm + KW_HK))[ra], hb = ((float*)(sm + KW_HK))[rb];
            float ma = ((float*)(sm + KW_MS))[ra], mb = ((float*)(sm + KW_MS))[rb];
            #pragma unroll
            for (int nt = 0; nt < 2; ++nt) {
                int c0 = 16*w + nt*8 + cb2;
                float e0=0.f,e1=0.f,e2=0.f,e3=0.f;
                if (c0 < M_)   { e0 = NC*(__expf(pa[nt][0]+ha)+KEPS)*ma; e2 = NC*(__expf(pa[nt][2]+hb)+KEPS)*mb; }
                if (c0+1 < M_) { e1 = NC*(__expf(pa[nt][1]+ha)+KEPS)*ma; e3 = NC*(__expf(pa[nt][3]+hb)+KEPS)*mb; }
                uint32_t hh, ll;
                cvt_split2(e0, e1, hh, ll);
                *(uint32_t*)(sm + KW_KH + (ra*KST + c0)*2) = hh;
                *(uint32_t*)(sm + KW_KL + (ra*KST + c0)*2) = ll;
                cvt_split2(e2, e3, hh, ll);
                *(uint32_t*)(sm + KW_KH + (rb*KST + c0)*2) = hh;
                *(uint32_t*)(sm + KW_KL + (rb*KST + c0)*2) = ll;
            }
        }
        __syncthreads();
        // kv: warp w owns m-tile w (m = 16w..16w+15); warp 17 computes zero tile
        #pragma unroll
        for (int ks = 0; ks < 4; ++ks) {
            uint32_t ah1[4], al1[4];
            uint32_t offA = (uint32_t)(((ks*16 + brow)*KST + w*16 + bcolsel)*2);
            LDSM_X4T(ah1[0],ah1[1],ah1[2],ah1[3], sb + KW_KH + offA);
            LDSM_X4T(al1[0],al1[1],al1[2],al1[3], sb + KW_KL + offA);
            uint32_t bh4[4][4], bl4[4][4], bh2[2], bl2[2];
            #pragma unroll
            for (int g = 0; g < 4; ++g) {
                uint32_t off = (uint32_t)(((ks*16 + arow)*72 + g*16 + acolsel)*2);
                LDSM_X4T(bh4[g][0],bh4[g][1],bh4[g][2],bh4[g][3], sb + KW_VH + off);
                LDSM_X4T(bl4[g][0],bl4[g][1],bl4[g][2],bl4[g][3], sb + KW_VL + off);
            }
            uint32_t off2 = (uint32_t)(((ks*16 + (lane & 15))*72 + 64)*2);
            LDSM_X2T(bh2[0], bh2[1], sb + KW_VH + off2);
            LDSM_X2T(bl2[0], bl2[1], sb + KW_VL + off2);
            #pragma unroll
            for (int nt = 0; nt < 9; ++nt) {
                uint32_t p0 = (nt < 8) ? bh4[nt>>1][(nt&1)*2]   : bh2[0];
                uint32_t p1 = (nt < 8) ? bh4[nt>>1][(nt&1)*2+1] : bh2[1];
                uint32_t q0 = (nt < 8) ? bl4[nt>>1][(nt&1)*2]   : bl2[0];
                uint32_t q1 = (nt < 8) ? bl4[nt>>1][(nt&1)*2+1] : bl2[1];
                MMA_BF16(acc[nt], ah1, p0, p1);
                MMA_BF16(acc[nt], ah1, q0, q1);
                MMA_BF16(acc[nt], al1, p0, p1);
            }
        }
    }
    if (w < 17) {
        float* base = g_kvpart + (size_t)(split*BH + bh)*KVROW*KVCOL;
        int r0 = w*16 + (lane >> 2);
        #pragma unroll
        for (int nt = 0; nt < 9; ++nt) {
            int c0 = nt*8 + (lane & 3)*2;
            *(float2*)(base + (size_t)r0*KVCOL + c0)     = make_float2(acc[nt][0], acc[nt][1]);
            *(float2*)(base + (size_t)(r0+8)*KVCOL + c0) = make_float2(acc[nt][2], acc[nt][3]);
        }
    }
}

__global__ void kv_reduce() {
    int idx = blockIdx.x * 256 + threadIdx.x;
    if (idx < KVSZ2) {
        float s = 0.f;
        #pragma unroll
        for (int p = 0; p < SPLIT; ++p) s += g_kvpart[(size_t)p*KVSZ2 + idx];
        g_kv[idx] = s;
    }
}

// ================= fused out kernel (R11 proven) =================
#define OW_KVH 0
#define OW_KVL 41472
#define OW_XH  82944
#define OW_XL  101376
#define OW_QH  119808
#define OW_QL  130048
#define OW_WFH 140288
#define OW_WFL 144896
#define OW_SMEM 149504

__global__ __launch_bounds__(256, 1) void out_mma(const float* __restrict__ Wf) {
    extern __shared__ char sm[];
    const uint32_t sb = smem_u32(sm);
    const int tid = threadIdx.x, lane = tid & 31, w = tid >> 5;
    const int h = blockIdx.y, b = blockIdx.z, bh = b*H_ + h;
    const int l0 = blockIdx.x * 128;
    const int arow = lane & 15, acolsel = (lane >> 4) << 3;
    const int brow = (lane & 7) + ((lane >> 4) << 3), bcolsel = ((lane >> 3) & 1) << 3;

    for (int i = tid; i < 82944/4; i += 256) ((uint32_t*)sm)[i] = 0;
    __syncthreads();
    for (int i = tid; i < KVROW*18; i += 256) {
        int r = i / 18, u = i % 18;
        float4 v = *(const float4*)(g_kv + ((size_t)bh*KVROW + r)*KVCOL + u*4);
        uint32_t h01,h23,l01,l23; cvt_split(v,h01,h23,l01,l23);
        *(uint2*)(sm + OW_KVH + (r*72 + u*4)*2) = make_uint2(h01,h23);
        *(uint2*)(sm + OW_KVL + (r*72 + u*4)*2) = make_uint2(l01,l23);
    }
    for (int i = tid; i < 128*16; i += 256) {
        int r = i >> 4, u = i & 15;
        float4 v = *(const float4*)(g_Qp + (size_t)(b*L_+l0+r)*D_ + h*64 + u*4);
        v.x*=SCALE; v.y*=SCALE; v.z*=SCALE; v.w*=SCALE;
        uint32_t h01,h23,l01,l23; cvt_split(v,h01,h23,l01,l23);
        *(uint2*)(sm + OW_XH + (r*72 + u*4)*2) = make_uint2(h01,h23);
        *(uint2*)(sm + OW_XL + (r*72 + u*4)*2) = make_uint2(l01,l23);
    }

    float acc[9][4];
    #pragma unroll
    for (int n = 0; n < 9; ++n)
        #pragma unroll
        for (int k = 0; k < 4; ++k) acc[n][k] = 0.f;

    const int r0 = lane >> 2, cb2 = (lane & 3)*2;

    for (int mc = 0; mc < 9; ++mc) {
        __syncthreads();
        for (int i = tid; i < 32*18; i += 256) {
            int r = i / 18, u = i % 18;
            int gr = mc*32 + r;
            float4 v = make_float4(0.f,0.f,0.f,0.f);
            if (gr < 266 && u < 16) v = *(const float4*)(Wf + gr*64 + u*4);
            uint32_t h01,h23,l01,l23; cvt_split(v,h01,h23,l01,l23);
            *(uint2*)(sm + OW_WFH + (r*72 + u*4)*2) = make_uint2(h01,h23);
            *(uint2*)(sm + OW_WFL + (r*72 + u*4)*2) = make_uint2(l01,l23);
        }
        __syncthreads();
        float pa[4][4];
        #pragma unroll
        for (int n = 0; n < 4; ++n)
            #pragma unroll
            for (int k = 0; k < 4; ++k) pa[n][k] = 0.f;
        #pragma unroll
        for (int ks = 0; ks < 4; ++ks) {
            uint32_t ah[4], al[4];
            uint32_t aoff = (uint32_t)(((w*16 + arow)*72 + ks*16 + acolsel)*2);
            LDSM_X4(ah[0],ah[1],ah[2],ah[3], sb + OW_XH + aoff);
            LDSM_X4(al[0],al[1],al[2],al[3], sb + OW_XL + aoff);
            #pragma unroll
            for (int g = 0; g < 2; ++g) {
                uint32_t boff = (uint32_t)(((g*16 + brow)*72 + ks*16 + bcolsel)*2);
                uint32_t bh_[4], bl_[4];
                LDSM_X4(bh_[0],bh_[1],bh_[2],bh_[3], sb + OW_WFH + boff);
                LDSM_X4(bl_[0],bl_[1],bl_[2],bl_[3], sb + OW_WFL + boff);
                #pragma unroll
                for (int half = 0; half < 2; ++half) {
                    int nt = 2*g + half;
                    MMA_BF16(pa[nt], ah, bh_[half*2], bh_[half*2+1]);
                    MMA_BF16(pa[nt], ah, bl_[half*2], bl_[half*2+1]);
                    MMA_BF16(pa[nt], al, bh_[half*2], bh_[half*2+1]);
                }
            }
        }
        {
            int ra = w*16 + r0, rb = ra + 8;
            #pragma unroll
            for (int nt = 0; nt < 4; ++nt) {
                int lc = nt*8 + cb2;
                int gc = mc*32 + lc;
                float e0=0.f,e1=0.f,e2=0.f,e3=0.f;
                if (gc < M_)   { e0 = NC*(__expf(pa[nt][0])+KEPS); e2 = NC*(__expf(pa[nt][2])+KEPS); }
                if (gc+1 < M_) { e1 = NC*(__expf(pa[nt][1])+KEPS); e3 = NC*(__expf(pa[nt][3])+KEPS); }
                uint32_t hh, ll;
                cvt_split2(e0, e1, hh, ll);
                *(uint32_t*)(sm + OW_QH + (ra*40 + lc)*2) = hh;
                *(uint32_t*)(sm + OW_QL + (ra*40 + lc)*2) = ll;
                cvt_split2(e2, e3, hh, ll);
                *(uint32_t*)(sm + OW_QH + (rb*40 + lc)*2) = hh;
                *(uint32_t*)(sm + OW_QL + (rb*40 + lc)*2) = ll;
            }
        }
        __syncthreads();
        #pragma unroll
        for (int ks = 0; ks < 2; ++ks) {
            int gk = mc*32 + ks*16;
            uint32_t ah[4], al[4];
            uint32_t aoff = (uint32_t)(((w*16 + arow)*40 + ks*16 + acolsel)*2);
            LDSM_X4(ah[0],ah[1],ah[2],ah[3], sb + OW_QH + aoff);
            LDSM_X4(al[0],al[1],al[2],al[3], sb + OW_QL + aoff);
            uint32_t bh4[4][4], bl4[4][4], bh2[2], bl2[2];
            #pragma unroll
            for (int g = 0; g < 4; ++g) {
                uint32_t off = (uint32_t)(((gk + arow)*72 + g*16 + acolsel)*2);
                LDSM_X4T(bh4[g][0],bh4[g][1],bh4[g][2],bh4[g][3], sb + OW_KVH + off);
                LDSM_X4T(bl4[g][0],bl4[g][1],bl4[g][2],bl4[g][3], sb + OW_KVL + off);
            }
            uint32_t off2 = (uint32_t)(((gk + (lane & 15))*72 + 64)*2);
            LDSM_X2T(bh2[0], bh2[1], sb + OW_KVH + off2);
            LDSM_X2T(bl2[0], bl2[1], sb + OW_KVL + off2);
            #pragma unroll
            for (int nt = 0; nt < 9; ++nt) {
                uint32_t p0 = (nt < 8) ? bh4[nt>>1][(nt&1)*2]   : bh2[0];
                uint32_t p1 = (nt < 8) ? bh4[nt>>1][(nt&1)*2+1] : bh2[1];
                uint32_t q0 = (nt < 8) ? bl4[nt>>1][(nt&1)*2]   : bl2[0];
                uint32_t q1 = (nt < 8) ? bl4[nt>>1][(nt&1)*2+1] : bl2[1];
                MMA_BF16(acc[nt], ah, p0, p1);
                MMA_BF16(acc[nt], ah, q0, q1);
                MMA_BF16(acc[nt], al, p0, p1);
            }
        }
    }
    float den0 = __shfl_sync(0xffffffffu, acc[8][0], lane & ~3);
    float den1 = __shfl_sync(0xffffffffu, acc[8][2], lane & ~3);
    if (fabsf(den0) <= NSTAB) den0 += 2.f*NSTAB;
    if (fabsf(den1) <= NSTAB) den1 += 2.f*NSTAB;
    float inv0 = 1.f/den0, inv1 = 1.f/den1;
    int rr = w*16 + r0;
    size_t gl0 = (size_t)(b*L_ + l0 + rr), gl1 = gl0 + 8;
    #pragma unroll
    for (int nt = 0; nt < 8; ++nt) {
        int c0 = nt*8 + cb2;
        uint32_t hh, ll;
        cvt_split2(acc[nt][0]*inv0, acc[nt][1]*inv0, hh, ll);
        *(uint32_t*)(g_ctxh + gl0*D_ + h*64 + c0) = hh;
        *(uint32_t*)(g_ctxl + gl0*D_ + h*64 + c0) = ll;
        cvt_split2(acc[nt][2]*inv1, acc[nt][3]*inv1, hh, ll);
        *(uint32_t*)(g_ctxh + gl1*D_ + h*64 + c0) = hh;
        *(uint32_t*)(g_ctxl + gl1*D_ + h*64 + c0) = ll;
    }
}

// ---------------- launch (dual-stream overlap) ----------------
extern "C" void kernel_launch(void* const* d_in, const int* in_sizes, int n_in,
                              void* d_out, int out_size) {
    const float* query = (const float*)d_in[0];
    const float* key   = (const float*)d_in[1];
    const float* value = (const float*)d_in[2];
    const float* mask  = (const float*)d_in[3];
    const float* Wq = (const float*)d_in[4];
    const float* bq = (const float*)d_in[5];
    const float* Wk = (const float*)d_in[6];
    const float* bk = (const float*)d_in[7];
    const float* Wv = (const float*)d_in[8];
    const float* bv = (const float*)d_in[9];
    const float* Wo = (const float*)d_in[10];
    const float* bo = (const float*)d_in[11];
    const float* Wf = (const float*)d_in[12];

    float *Qp, *Kp, *Vp;
    __nv_bfloat16 *qah,*qal,*kah,*kal,*vah,*vaL;
    __nv_bfloat16 *wqh,*wql,*wkh,*wkl,*wvh,*wvl,*woh,*wol,*cth,*ctl;
    cudaGetSymbolAddress((void**)&Qp,  g_Qp);
    cudaGetSymbolAddress((void**)&Kp,  g_Kp);
    cudaGetSymbolAddress((void**)&Vp,  g_Vp);
    cudaGetSymbolAddress((void**)&qah, g_qah); cudaGetSymbolAddress((void**)&qal, g_qal);
    cudaGetSymbolAddress((void**)&kah, g_kah); cudaGetSymbolAddress((void**)&kal, g_kal);
    cudaGetSymbolAddress((void**)&vah, g_vah); cudaGetSymbolAddress((void**)&vaL, g_vaL);
    cudaGetSymbolAddress((void**)&wqh, g_wqh); cudaGetSymbolAddress((void**)&wql, g_wql);
    cudaGetSymbolAddress((void**)&wkh, g_wkh); cudaGetSymbolAddress((void**)&wkl, g_wkl);
    cudaGetSymbolAddress((void**)&wvh, g_wvh); cudaGetSymbolAddress((void**)&wvl, g_wvl);
    cudaGetSymbolAddress((void**)&woh, g_woh); cudaGetSymbolAddress((void**)&wol, g_wol);
    cudaGetSymbolAddress((void**)&cth, g_ctxh); cudaGetSymbolAddress((void**)&ctl, g_ctxl);

    cudaFuncSetAttribute(gemm_mma_b, cudaFuncAttributeMaxDynamicSharedMemorySize, GB_SMEM);
    cudaFuncSetAttribute(kv_mma,     cudaFuncAttributeMaxDynamicSharedMemorySize, KW_SMEM);
    cudaFuncSetAttribute(out_mma,    cudaFuncAttributeMaxDynamicSharedMemorySize, OW_SMEM);

    static cudaStream_t s1 = nullptr;
    static cudaEvent_t eS, eQ, eK, eV, eWo, eG2, eHK;
    if (!s1) {
        cudaStreamCreateWithFlags(&s1, cudaStreamNonBlocking);
        cudaEventCreateWithFlags(&eS,  cudaEventDisableTiming);
        cudaEventCreateWithFlags(&eQ,  cudaEventDisableTiming);
        cudaEventCreateWithFlags(&eK,  cudaEventDisableTiming);
        cudaEventCreateWithFlags(&eV,  cudaEventDisableTiming);
        cudaEventCreateWithFlags(&eWo, cudaEventDisableTiming);
        cudaEventCreateWithFlags(&eG2, cudaEventDisableTiming);
        cudaEventCreateWithFlags(&eHK, cudaEventDisableTiming);
    }

    const int nA4 = BL*D_/4, nW4 = D_*D_/4;
    dim3 gg(D_/128, BL/128);

    init_kernel<<<1, 32>>>();
    cudaEventRecord(eS, 0);
    cudaStreamWaitEvent(s1, eS, 0);

    split_kernel<<<nW4/256, 256, 0, s1>>>(Wq, wqh, wql, nW4);
    split_kernel<<<nA4/256, 256, 0, s1>>>(query, qah, qal, nA4);
    cudaEventRecord(eQ, s1);
    split_kernel<<<nW4/256, 256, 0, s1>>>(Wk, wkh, wkl, nW4);
    split_kernel<<<nA4/256, 256, 0, s1>>>(key, kah, kal, nA4);
    cudaEventRecord(eK, s1);
    split_kernel<<<nW4/256, 256, 0, s1>>>(Wv, wvh, wvl, nW4);
    split_kernel<<<nA4/256, 256, 0, s1>>>(value, vah, vaL, nA4);
    cudaEventRecord(eV, s1);
    split_kernel<<<nW4/256, 256, 0, s1>>>(Wo, woh, wol, nW4);
    cudaEventRecord(eWo, s1);

    cudaStreamWaitEvent(0, eQ, 0);
    gemm_mma_b<<<gg, 256, GB_SMEM>>>(qah, qal, wqh, wql, bq, Qp);
    cudaStreamWaitEvent(0, eK, 0);
    gemm_mma_b<<<gg, 256, GB_SMEM>>>(kah, kal, wkh, wkl, bk, Kp);
    cudaEventRecord(eG2, 0);
    cudaStreamWaitEvent(0, eV, 0);
    gemm_mma_b<<<gg, 256, GB_SMEM>>>(vah, vaL, wvh, wvl, bv, Vp);

    cudaStreamWaitEvent(s1, eG2, 0);
    hk_kernel<<<(BH*L_)/256, 256, 0, s1>>>();
    cudaEventRecord(eHK, s1);

    cudaStreamWaitEvent(0, eHK, 0);
    kv_mma<<<dim3(SPLIT, BH), KVNT, KW_SMEM>>>(Wf, mask);
    kv_reduce<<<(KVSZ2 + 255)/256, 256>>>();
    out_mma<<<dim3(L_/128, H_, B_), 256, OW_SMEM>>>(Wf);
    cudaStreamWaitEvent(0, eWo, 0);
    gemm_mma_b<<<gg, 256, GB_SMEM>>>(cth, ctl, woh, wol, bo, (float*)d_out);
}

// round 15
// speedup vs baseline: 1.3027x; 1.0840x over previous
#include <cuda_runtime.h>
#include <cuda_bf16.h>
#include <cstdint>
#include <math.h>

#define B_   2
#define L_   8192
#define D_   1024
#define H_   16
#define DH_  64
#define M_   266
#define BL   (B_*L_)
#define BH   (B_*H_)

#define SCALE  0.17677669529663687f
#define SCALE2 0.03125f
#define NC     0.061313932f
#define KEPS   1e-4f
#define NSTAB  1e-6f

#define SPLIT  16
#define KVROW  272
#define KVCOL  72
#define KVSZ2  (BH*KVROW*KVCOL)

// ---------------- device scratch ----------------
__device__ float g_Qp[BL*D_];
__device__ float g_Kp[BL*D_];
__device__ float g_Vp[BL*D_];
__device__ float g_hk[BH*L_];
__device__ unsigned int g_kstab;
__device__ float g_kv[KVSZ2];
__device__ float g_kvpart[(size_t)SPLIT*KVSZ2];
__device__ __nv_bfloat16 g_qah[BL*D_], g_qal[BL*D_];
__device__ __nv_bfloat16 g_kah[BL*D_], g_kal[BL*D_];
__device__ __nv_bfloat16 g_vah[BL*D_], g_vaL[BL*D_];
__device__ __nv_bfloat16 g_wqh[D_*D_], g_wql[D_*D_];
__device__ __nv_bfloat16 g_wkh[D_*D_], g_wkl[D_*D_];
__device__ __nv_bfloat16 g_wvh[D_*D_], g_wvl[D_*D_];
__device__ __nv_bfloat16 g_woh[D_*D_], g_wol[D_*D_];
__device__ __nv_bfloat16 g_ctxh[BL*D_], g_ctxl[BL*D_];

// ================= helpers =================
__device__ __forceinline__ uint32_t smem_u32(const void* p) {
    uint32_t a;
    asm("{ .reg .u64 t; cvta.to.shared.u64 t, %1; cvt.u32.u64 %0, t; }" : "=r"(a) : "l"(p));
    return a;
}
__device__ __forceinline__ void cvt_split(float4 v, uint32_t& h01, uint32_t& h23,
                                          uint32_t& l01, uint32_t& l23) {
    asm("cvt.rn.bf16x2.f32 %0, %1, %2;" : "=r"(h01) : "f"(v.y), "f"(v.x));
    asm("cvt.rn.bf16x2.f32 %0, %1, %2;" : "=r"(h23) : "f"(v.w), "f"(v.z));
    float r0 = v.x - __uint_as_float(h01 << 16);
    float r1 = v.y - __uint_as_float(h01 & 0xffff0000u);
    float r2 = v.z - __uint_as_float(h23 << 16);
    float r3 = v.w - __uint_as_float(h23 & 0xffff0000u);
    asm("cvt.rn.bf16x2.f32 %0, %1, %2;" : "=r"(l01) : "f"(r1), "f"(r0));
    asm("cvt.rn.bf16x2.f32 %0, %1, %2;" : "=r"(l23) : "f"(r3), "f"(r2));
}
__device__ __forceinline__ void cvt_split2(float a, float b, uint32_t& hh, uint32_t& ll) {
    asm("cvt.rn.bf16x2.f32 %0, %1, %2;" : "=r"(hh) : "f"(b), "f"(a));
    float ra = a - __uint_as_float(hh << 16);
    float rb = b - __uint_as_float(hh & 0xffff0000u);
    asm("cvt.rn.bf16x2.f32 %0, %1, %2;" : "=r"(ll) : "f"(rb), "f"(ra));
}
#define LDSM_X4(r0,r1,r2,r3,addr) \
    asm volatile("ldmatrix.sync.aligned.m8n8.x4.shared.b16 {%0,%1,%2,%3}, [%4];" \
        : "=r"(r0),"=r"(r1),"=r"(r2),"=r"(r3) : "r"(addr))
#define LDSM_X4T(r0,r1,r2,r3,addr) \
    asm volatile("ldmatrix.sync.aligned.m8n8.x4.trans.shared.b16 {%0,%1,%2,%3}, [%4];" \
        : "=r"(r0),"=r"(r1),"=r"(r2),"=r"(r3) : "r"(addr))
#define LDSM_X2T(r0,r1,addr) \
    asm volatile("ldmatrix.sync.aligned.m8n8.x2.trans.shared.b16 {%0,%1}, [%2];" \
        : "=r"(r0),"=r"(r1) : "r"(addr))
#define MMA_BF16(d,a,b0_,b1_) \
    asm volatile("mma.sync.aligned.m16n8k16.row.col.f32.bf16.bf16.f32 " \
        "{%0,%1,%2,%3}, {%4,%5,%6,%7}, {%8,%9}, {%0,%1,%2,%3};" \
        : "+f"((d)[0]),"+f"((d)[1]),"+f"((d)[2]),"+f"((d)[3]) \
        : "r"((a)[0]),"r"((a)[1]),"r"((a)[2]),"r"((a)[3]),"r"(b0_),"r"(b1_))
#define CP16(dst, src) \
    asm volatile("cp.async.cg.shared.global [%0], [%1], 16;" :: "r"(dst), "l"(src))
#define CP_COMMIT() asm volatile("cp.async.commit_group;" ::: "memory")
#define CP_WAIT1()  asm volatile("cp.async.wait_group 1;" ::: "memory")
#define CP_WAIT0()  asm volatile("cp.async.wait_group 0;" ::: "memory")

// ================= fp32 -> bf16 hi/lo split =================
__global__ __launch_bounds__(256) void split_kernel(const float* __restrict__ X,
                                                    __nv_bfloat16* __restrict__ hi,
                                                    __nv_bfloat16* __restrict__ lo,
                                                    int n4) {
    int i = blockIdx.x * 256 + threadIdx.x;
    if (i < n4) {
        float4 v = ((const float4*)X)[i];
        uint32_t h01, h23, l01, l23;
        cvt_split(v, h01, h23, l01, l23);
        ((uint2*)hi)[i] = make_uint2(h01, h23);
        ((uint2*)lo)[i] = make_uint2(l01, l23);
    }
}

// ================= bf16x3 GEMM (R11 proven) =================
#define AST 40
#define GB_STAGE 40960
#define GB_SMEM  81920

__global__ __launch_bounds__(256, 2) void gemm_mma_b(const __nv_bfloat16* __restrict__ Ah_,
                                                     const __nv_bfloat16* __restrict__ Al_,
                                                     const __nv_bfloat16* __restrict__ Wh_,
                                                     const __nv_bfloat16* __restrict__ Wl_,
                                                     const float* __restrict__ bias,
                                                     float* __restrict__ C) {
    extern __shared__ char smg[];
    const uint32_t sb = smem_u32(smg);
    const int tid = threadIdx.x, lane = tid & 31, wid = tid >> 5;
    const int wm = wid & 1, wn = wid >> 1;
    const size_t mbase = (size_t)blockIdx.y * 128, nbase = (size_t)blockIdx.x * 128;
    const __nv_bfloat16* Abh = Ah_ + mbase * D_;
    const __nv_bfloat16* Abl = Al_ + mbase * D_;
    const __nv_bfloat16* Wbh = Wh_ + nbase * D_;
    const __nv_bfloat16* Wbl = Wl_ + nbase * D_;

    const int arow = lane & 15, acolsel = (lane >> 4) << 3;
    const int brow = (lane & 7) + ((lane >> 4) << 3), bcolsel = ((lane >> 3) & 1) << 3;

    const int pr0 = tid >> 2,         pu0 = tid & 3;
    const int pr1 = (tid + 256) >> 2, pu1 = (tid + 256) & 3;

    float acc[4][4][4];
    #pragma unroll
    for (int i = 0; i < 4; ++i)
        #pragma unroll
        for (int j = 0; j < 4; ++j)
            #pragma unroll
            for (int k = 0; k < 4; ++k) acc[i][j][k] = 0.f;

    {
        uint32_t d0 = sb + pr0*80 + pu0*16;
        uint32_t d1 = sb + pr1*80 + pu1*16;
        size_t s0 = (size_t)pr0*D_ + pu0*8;
        size_t s1 = (size_t)pr1*D_ + pu1*8;
        CP16(d0,          Abh + s0); CP16(d0 + 10240, Abl + s0);
        CP16(d0 + 20480,  Wbh + s0); CP16(d0 + 30720, Wbl + s0);
        CP16(d1,          Abh + s1); CP16(d1 + 10240, Abl + s1);
        CP16(d1 + 20480,  Wbh + s1); CP16(d1 + 30720, Wbl + s1);
        CP_COMMIT();
    }

    for (int kc = 0; kc < 32; ++kc) {
        int s = kc & 1;
        if (kc) __syncthreads();
        if (kc + 1 < 32) {
            uint32_t base = sb + (s^1)*GB_STAGE;
            int koff = (kc + 1) * 32;
            uint32_t d0 = base + pr0*80 + pu0*16;
            uint32_t d1 = base + pr1*80 + pu1*16;
            size_t s0 = (size_t)pr0*D_ + koff + pu0*8;
            size_t s1 = (size_t)pr1*D_ + koff + pu1*8;
            CP16(d0,          Abh + s0); CP16(d0 + 10240, Abl + s0);
            CP16(d0 + 20480,  Wbh + s0); CP16(d0 + 30720, Wbl + s0);
            CP16(d1,          Abh + s1); CP16(d1 + 10240, Abl + s1);
            CP16(d1 + 20480,  Wbh + s1); CP16(d1 + 30720, Wbl + s1);
            CP_COMMIT();
            CP_WAIT1();
        } else {
            CP_WAIT0();
        }
        __syncthreads();

        const uint32_t aH = sb + s*GB_STAGE;
        const uint32_t aL = aH + 10240;
        const uint32_t bH = aH + 20480;
        const uint32_t bL = aH + 30720;

        #pragma unroll
        for (int ks = 0; ks < 2; ++ks) {
            uint32_t af[4][4], bhF[2][4], blF[2][4];
            #pragma unroll
            for (int mt = 0; mt < 4; ++mt) {
                uint32_t off = (uint32_t)(((wm*64 + mt*16 + arow)*AST + ks*16 + acolsel)*2);
                LDSM_X4(af[mt][0], af[mt][1], af[mt][2], af[mt][3], aH + off);
            }
            #pragma unroll
            for (int bp = 0; bp < 2; ++bp) {
                uint32_t off = (uint32_t)(((wn*32 + bp*16 + brow)*AST + ks*16 + bcolsel)*2);
                LDSM_X4(bhF[bp][0], bhF[bp][1], bhF[bp][2], bhF[bp][3], bH + off);
                LDSM_X4(blF[bp][0], blF[bp][1], blF[bp][2], blF[bp][3], bL + off);
            }
            #pragma unroll
            for (int mt = 0; mt < 4; ++mt)
                #pragma unroll
                for (int nt = 0; nt < 4; ++nt) {
                    MMA_BF16(acc[mt][nt], af[mt], bhF[nt>>1][(nt&1)*2], bhF[nt>>1][(nt&1)*2+1]);
                    MMA_BF16(acc[mt][nt], af[mt], blF[nt>>1][(nt&1)*2], blF[nt>>1][(nt&1)*2+1]);
                }
            #pragma unroll
            for (int mt = 0; mt < 4; ++mt) {
                uint32_t off = (uint32_t)(((wm*64 + mt*16 + arow)*AST + ks*16 + acolsel)*2);
                LDSM_X4(af[mt][0], af[mt][1], af[mt][2], af[mt][3], aL + off);
            }
            #pragma unroll
            for (int mt = 0; mt < 4; ++mt)
                #pragma unroll
                for (int nt = 0; nt < 4; ++nt)
                    MMA_BF16(acc[mt][nt], af[mt], bhF[nt>>1][(nt&1)*2], bhF[nt>>1][(nt&1)*2+1]);
        }
    }
    #pragma unroll
    for (int mt = 0; mt < 4; ++mt) {
        size_t r0 = mbase + wm*64 + mt*16 + (lane >> 2);
        #pragma unroll
        for (int nt = 0; nt < 4; ++nt) {
            int col = (int)nbase + wn*32 + nt*8 + 2*(lane & 3);
            float bx = bias[col], by = bias[col+1];
            *(float2*)(C + r0*D_ + col)     = make_float2(acc[mt][nt][0]+bx, acc[mt][nt][1]+by);
            *(float2*)(C + (r0+8)*D_ + col) = make_float2(acc[mt][nt][2]+bx, acc[mt][nt][3]+by);
        }
    }
}

// ---------------- init / hk ----------------
__global__ void init_kernel() { if (threadIdx.x == 0) g_kstab = 0xFF800000u; }

__global__ __launch_bounds__(256) void hk_kernel() {
    int gid = blockIdx.x * 256 + threadIdx.x;
    int b = gid / (H_*L_), rem = gid % (H_*L_), h = rem / L_, l = rem % L_;
    const float4* row = (const float4*)(g_Kp + (size_t)(b*L_ + l)*D_ + h*DH_);
    float s = 0.f;
    #pragma unroll
    for (int t = 0; t < 16; ++t) {
        float4 v = row[t];
        s = fmaf(v.x,v.x,s); s = fmaf(v.y,v.y,s); s = fmaf(v.z,v.z,s); s = fmaf(v.w,v.w,s);
    }
    float hk = -0.5f * SCALE2 * s;
    g_hk[gid] = hk;
    float m = hk;
    #pragma unroll
    for (int o = 16; o > 0; o >>= 1) m = fmaxf(m, __shfl_xor_sync(0xffffffffu, m, o));
    __shared__ float wmax[8];
    if ((threadIdx.x & 31) == 0) wmax[threadIdx.x >> 5] = m;
    __syncthreads();
    if (threadIdx.x == 0) {
        float bm = wmax[0];
        #pragma unroll
        for (int w = 1; w < 8; ++w) bm = fmaxf(bm, wmax[w]);
        atomicMin(&g_kstab, __float_as_uint(bm));
    }
}

// ================= fused kv kernel: 576 threads / 18 warps (R14 proven) =================
#define KVNT 576
#define KST 296
#define KW_WFH 0
#define KW_WFL 41472
#define KW_XH  82944
#define KW_XL  92160
#define KW_KH  101376
#define KW_KL  139264
#define KW_VH  177152
#define KW_VL  186368
#define KW_HK  195584
#define KW_MS  195840
#define KW_SMEM 196096

__global__ __launch_bounds__(KVNT, 1) void kv_mma(const float* __restrict__ Wf,
                                                  const float* __restrict__ mask) {
    extern __shared__ char sm[];
    const uint32_t sb = smem_u32(sm);
    const int tid = threadIdx.x, lane = tid & 31, w = tid >> 5;
    const int split = blockIdx.x, bh = blockIdx.y;
    const int b = bh / H_, h = bh % H_;
    const int arow = lane & 15, acolsel = (lane >> 4) << 3;
    const int brow = (lane & 7) + ((lane >> 4) << 3), bcolsel = ((lane >> 3) & 1) << 3;

    for (int i = tid; i < 288*18; i += KVNT) {
        int r = i / 18, u = i % 18;
        float4 v = make_float4(0.f,0.f,0.f,0.f);
        if (r < 266 && u < 16) v = *(const float4*)(Wf + r*64 + u*4);
        uint32_t h01,h23,l01,l23; cvt_split(v,h01,h23,l01,l23);
        *(uint2*)(sm + KW_WFH + (r*72 + u*4)*2) = make_uint2(h01,h23);
        *(uint2*)(sm + KW_WFL + (r*72 + u*4)*2) = make_uint2(l01,l23);
    }
    float kstab = __uint_as_float(g_kstab);

    float acc[9][4];
    #pragma unroll
    for (int n = 0; n < 9; ++n)
        #pragma unroll
        for (int k = 0; k < 4; ++k) acc[n][k] = 0.f;

    for (int c = 0; c < 8; ++c) {
        int lb = split*512 + c*64;
        __syncthreads();
        for (int i = tid; i < 64*16; i += KVNT) {
            int r = i >> 4, u = i & 15;
            float4 v = *(const float4*)(g_Kp + (size_t)(b*L_+lb+r)*D_ + h*64 + u*4);
            v.x*=SCALE; v.y*=SCALE; v.z*=SCALE; v.w*=SCALE;
            uint32_t h01,h23,l01,l23; cvt_split(v,h01,h23,l01,l23);
            *(uint2*)(sm + KW_XH + (r*72 + u*4)*2) = make_uint2(h01,h23);
            *(uint2*)(sm + KW_XL + (r*72 + u*4)*2) = make_uint2(l01,l23);
        }
        for (int i = tid; i < 64*18; i += KVNT) {
            int r = i / 18, u = i % 18;
            float4 v;
            if (u < 16) v = *(const float4*)(g_Vp + (size_t)(b*L_+lb+r)*D_ + h*64 + u*4);
            else if (u == 16) v = make_float4(1.f,0.f,0.f,0.f);
            else v = make_float4(0.f,0.f,0.f,0.f);
            uint32_t h01,h23,l01,l23; cvt_split(v,h01,h23,l01,l23);
            *(uint2*)(sm + KW_VH + (r*72 + u*4)*2) = make_uint2(h01,h23);
            *(uint2*)(sm + KW_VL + (r*72 + u*4)*2) = make_uint2(l01,l23);
        }
        if (tid < 64) {
            ((float*)(sm + KW_HK))[tid] = g_hk[(size_t)bh*L_ + lb + tid] - kstab;
            ((float*)(sm + KW_MS))[tid] = mask[b*L_ + lb + tid];
        }
        __syncthreads();
        const int r0 = lane >> 2, cb2 = (lane & 3)*2;
        #pragma unroll
        for (int lt = 0; lt < 4; ++lt) {
            float pa[2][4];
            #pragma unroll
            for (int n = 0; n < 2; ++n)
                #pragma unroll
                for (int k = 0; k < 4; ++k) pa[n][k] = 0.f;
            #pragma unroll
            for (int ks = 0; ks < 4; ++ks) {
                uint32_t ah[4], al[4];
                uint32_t aoff = (uint32_t)(((lt*16 + arow)*72 + ks*16 + acolsel)*2);
                LDSM_X4(ah[0],ah[1],ah[2],ah[3], sb + KW_XH + aoff);
                LDSM_X4(al[0],al[1],al[2],al[3], sb + KW_XL + aoff);
                uint32_t boff = (uint32_t)(((w*16 + brow)*72 + ks*16 + bcolsel)*2);
                uint32_t bh_[4], bl_[4];
                LDSM_X4(bh_[0],bh_[1],bh_[2],bh_[3], sb + KW_WFH + boff);
                LDSM_X4(bl_[0],bl_[1],bl_[2],bl_[3], sb + KW_WFL + boff);
                #pragma unroll
                for (int half = 0; half < 2; ++half) {
                    MMA_BF16(pa[half], ah, bh_[half*2], bh_[half*2+1]);
                    MMA_BF16(pa[half], ah, bl_[half*2], bl_[half*2+1]);
                    MMA_BF16(pa[half], al, bh_[half*2], bh_[half*2+1]);
                }
            }
            int ra = lt*16 + r0, rb = ra + 8;
            float ha = ((float*)(sm + KW_HK))[ra], hb = ((float*)(sm + KW_HK))[rb];
            float ma = ((float*)(sm + KW_MS))[ra], mb = ((float*)(sm + KW_MS))[rb];
            #pragma unroll
            for (int nt = 0; nt < 2; ++nt) {
                int c0 = 16*w + nt*8 + cb2;
                float e0=0.f,e1=0.f,e2=0.f,e3=0.f;
                if (c0 < M_)   { e0 = NC*(__expf(pa[nt][0]+ha)+KEPS)*ma; e2 = NC*(__expf(pa[nt][2]+hb)+KEPS)*mb; }
                if (c0+1 < M_) { e1 = NC*(__expf(pa[nt][1]+ha)+KEPS)*ma; e3 = NC*(__expf(pa[nt][3]+hb)+KEPS)*mb; }
                uint32_t hh, ll;
                cvt_split2(e0, e1, hh, ll);
                *(uint32_t*)(sm + KW_KH + (ra*KST + c0)*2) = hh;
                *(uint32_t*)(sm + KW_KL + (ra*KST + c0)*2) = ll;
                cvt_split2(e2, e3, hh, ll);
                *(uint32_t*)(sm + KW_KH + (rb*KST + c0)*2) = hh;
                *(uint32_t*)(sm + KW_KL + (rb*KST + c0)*2) = ll;
            }
        }
        __syncthreads();
        #pragma unroll
        for (int ks = 0; ks < 4; ++ks) {
            uint32_t ah1[4], al1[4];
            uint32_t offA = (uint32_t)(((ks*16 + brow)*KST + w*16 + bcolsel)*2);
            LDSM_X4T(ah1[0],ah1[1],ah1[2],ah1[3], sb + KW_KH + offA);
            LDSM_X4T(al1[0],al1[1],al1[2],al1[3], sb + KW_KL + offA);
            uint32_t bh4[4][4], bl4[4][4], bh2[2], bl2[2];
            #pragma unroll
            for (int g = 0; g < 4; ++g) {
                uint32_t off = (uint32_t)(((ks*16 + arow)*72 + g*16 + acolsel)*2);
                LDSM_X4T(bh4[g][0],bh4[g][1],bh4[g][2],bh4[g][3], sb + KW_VH + off);
                LDSM_X4T(bl4[g][0],bl4[g][1],bl4[g][2],bl4[g][3], sb + KW_VL + off);
            }
            uint32_t off2 = (uint32_t)(((ks*16 + (lane & 15))*72 + 64)*2);
            LDSM_X2T(bh2[0], bh2[1], sb + KW_VH + off2);
            LDSM_X2T(bl2[0], bl2[1], sb + KW_VL + off2);
            #pragma unroll
            for (int nt = 0; nt < 9; ++nt) {
                uint32_t p0 = (nt < 8) ? bh4[nt>>1][(nt&1)*2]   : bh2[0];
                uint32_t p1 = (nt < 8) ? bh4[nt>>1][(nt&1)*2+1] : bh2[1];
                uint32_t q0 = (nt < 8) ? bl4[nt>>1][(nt&1)*2]   : bl2[0];
                uint32_t q1 = (nt < 8) ? bl4[nt>>1][(nt&1)*2+1] : bl2[1];
                MMA_BF16(acc[nt], ah1, p0, p1);
                MMA_BF16(acc[nt], ah1, q0, q1);
                MMA_BF16(acc[nt], al1, p0, p1);
            }
        }
    }
    if (w < 17) {
        float* base = g_kvpart + (size_t)(split*BH + bh)*KVROW*KVCOL;
        int r0 = w*16 + (lane >> 2);
        #pragma unroll
        for (int nt = 0; nt < 9; ++nt) {
            int c0 = nt*8 + (lane & 3)*2;
            *(float2*)(base + (size_t)r0*KVCOL + c0)     = make_float2(acc[nt][0], acc[nt][1]);
            *(float2*)(base + (size_t)(r0+8)*KVCOL + c0) = make_float2(acc[nt][2], acc[nt][3]);
        }
    }
}

__global__ void kv_reduce() {
    int idx = blockIdx.x * 256 + threadIdx.x;
    if (idx < KVSZ2) {
        float s = 0.f;
        #pragma unroll
        for (int p = 0; p < SPLIT; ++p) s += g_kvpart[(size_t)p*KVSZ2 + idx];
        g_kv[idx] = s;
    }
}

// ================= fused out kernel: 512 threads / 16 warps / 256 rows =================
#define OUNT 512
#define OW_KVH 0
#define OW_KVL 41472
#define OW_XH  82944
#define OW_XL  119808
#define OW_QH  156672
#define OW_QL  177152
#define OW_WFH 197632
#define OW_WFL 202240
#define OW_SMEM 206848

__global__ __launch_bounds__(OUNT, 1) void out_mma(const float* __restrict__ Wf) {
    extern __shared__ char sm[];
    const uint32_t sb = smem_u32(sm);
    const int tid = threadIdx.x, lane = tid & 31, w = tid >> 5;   // 16 warps
    const int h = blockIdx.y, b = blockIdx.z, bh = b*H_ + h;
    const int l0 = blockIdx.x * 256;
    const int arow = lane & 15, acolsel = (lane >> 4) << 3;
    const int brow = (lane & 7) + ((lane >> 4) << 3), bcolsel = ((lane >> 3) & 1) << 3;

    // zero kv buffers (covers rows 272..287 and cols 65..71)
    for (int i = tid; i < 82944/4; i += OUNT) ((uint32_t*)sm)[i] = 0;
    __syncthreads();
    for (int i = tid; i < KVROW*18; i += OUNT) {
        int r = i / 18, u = i % 18;
        float4 v = *(const float4*)(g_kv + ((size_t)bh*KVROW + r)*KVCOL + u*4);
        uint32_t h01,h23,l01,l23; cvt_split(v,h01,h23,l01,l23);
        *(uint2*)(sm + OW_KVH + (r*72 + u*4)*2) = make_uint2(h01,h23);
        *(uint2*)(sm + OW_KVL + (r*72 + u*4)*2) = make_uint2(l01,l23);
    }
    // Q block (scaled) -> XH/XL [256][72]
    for (int i = tid; i < 256*16; i += OUNT) {
        int r = i >> 4, u = i & 15;
        float4 v = *(const float4*)(g_Qp + (size_t)(b*L_+l0+r)*D_ + h*64 + u*4);
        v.x*=SCALE; v.y*=SCALE; v.z*=SCALE; v.w*=SCALE;
        uint32_t h01,h23,l01,l23; cvt_split(v,h01,h23,l01,l23);
        *(uint2*)(sm + OW_XH + (r*72 + u*4)*2) = make_uint2(h01,h23);
        *(uint2*)(sm + OW_XL + (r*72 + u*4)*2) = make_uint2(l01,l23);
    }

    float acc[9][4];
    #pragma unroll
    for (int n = 0; n < 9; ++n)
        #pragma unroll
        for (int k = 0; k < 4; ++k) acc[n][k] = 0.f;

    const int r0 = lane >> 2, cb2 = (lane & 3)*2;

    for (int mc = 0; mc < 9; ++mc) {
        __syncthreads();
        for (int i = tid; i < 32*18; i += OUNT) {
            int r = i / 18, u = i % 18;
            int gr = mc*32 + r;
            float4 v = make_float4(0.f,0.f,0.f,0.f);
            if (gr < 266 && u < 16) v = *(const float4*)(Wf + gr*64 + u*4);
            uint32_t h01,h23,l01,l23; cvt_split(v,h01,h23,l01,l23);
            *(uint2*)(sm + OW_WFH + (r*72 + u*4)*2) = make_uint2(h01,h23);
            *(uint2*)(sm + OW_WFL + (r*72 + u*4)*2) = make_uint2(l01,l23);
        }
        __syncthreads();
        float pa[4][4];
        #pragma unroll
        for (int n = 0; n < 4; ++n)
            #pragma unroll
            for (int k = 0; k < 4; ++k) pa[n][k] = 0.f;
        #pragma unroll
        for (int ks = 0; ks < 4; ++ks) {
            uint32_t ah[4], al[4];
            uint32_t aoff = (uint32_t)(((w*16 + arow)*72 + ks*16 + acolsel)*2);
            LDSM_X4(ah[0],ah[1],ah[2],ah[3], sb + OW_XH + aoff);
            LDSM_X4(al[0],al[1],al[2],al[3], sb + OW_XL + aoff);
            #pragma unroll
            for (int g = 0; g < 2; ++g) {
                uint32_t boff = (uint32_t)(((g*16 + brow)*72 + ks*16 + bcolsel)*2);
                uint32_t bh_[4], bl_[4];
                LDSM_X4(bh_[0],bh_[1],bh_[2],bh_[3], sb + OW_WFH + boff);
                LDSM_X4(bl_[0],bl_[1],bl_[2],bl_[3], sb + OW_WFL + boff);
                #pragma unroll
                for (int half = 0; half < 2; ++half) {
                    int nt = 2*g + half;
                    MMA_BF16(pa[nt], ah, bh_[half*2], bh_[half*2+1]);
                    MMA_BF16(pa[nt], ah, bl_[half*2], bl_[half*2+1]);
                    MMA_BF16(pa[nt], al, bh_[half*2], bh_[half*2+1]);
                }
            }
        }
        {
            int ra = w*16 + r0, rb = ra + 8;
            #pragma unroll
            for (int nt = 0; nt < 4; ++nt) {
                int lc = nt*8 + cb2;
                int gc = mc*32 + lc;
                float e0=0.f,e1=0.f,e2=0.f,e3=0.f;
                if (gc < M_)   { e0 = NC*(__expf(pa[nt][0])+KEPS); e2 = NC*(__expf(pa[nt][2])+KEPS); }
                if (gc+1 < M_) { e1 = NC*(__expf(pa[nt][1])+KEPS); e3 = NC*(__expf(pa[nt][3])+KEPS); }
                uint32_t hh, ll;
                cvt_split2(e0, e1, hh, ll);
                *(uint32_t*)(sm + OW_QH + (ra*40 + lc)*2) = hh;
                *(uint32_t*)(sm + OW_QL + (ra*40 + lc)*2) = ll;
                cvt_split2(e2, e3, hh, ll);
                *(uint32_t*)(sm + OW_QH + (rb*40 + lc)*2) = hh;
                *(uint32_t*)(sm + OW_QL + (rb*40 + lc)*2) = ll;
            }
        }
        __syncthreads();
        #pragma unroll
        for (int ks = 0; ks < 2; ++ks) {
            int gk = mc*32 + ks*16;
            uint32_t ah[4], al[4];
            uint32_t aoff = (uint32_t)(((w*16 + arow)*40 + ks*16 + acolsel)*2);
            LDSM_X4(ah[0],ah[1],ah[2],ah[3], sb + OW_QH + aoff);
            LDSM_X4(al[0],al[1],al[2],al[3], sb + OW_QL + aoff);
            uint32_t bh4[4][4], bl4[4][4], bh2[2], bl2[2];
            #pragma unroll
            for (int g = 0; g < 4; ++g) {
                uint32_t off = (uint32_t)(((gk + arow)*72 + g*16 + acolsel)*2);
                LDSM_X4T(bh4[g][0],bh4[g][1],bh4[g][2],bh4[g][3], sb + OW_KVH + off);
                LDSM_X4T(bl4[g][0],bl4[g][1],bl4[g][2],bl4[g][3], sb + OW_KVL + off);
            }
            uint32_t off2 = (uint32_t)(((gk + (lane & 15))*72 + 64)*2);
            LDSM_X2T(bh2[0], bh2[1], sb + OW_KVH + off2);
            LDSM_X2T(bl2[0], bl2[1], sb + OW_KVL + off2);
            #pragma unroll
            for (int nt = 0; nt < 9; ++nt) {
                uint32_t p0 = (nt < 8) ? bh4[nt>>1][(nt&1)*2]   : bh2[0];
                uint32_t p1 = (nt < 8) ? bh4[nt>>1][(nt&1)*2+1] : bh2[1];
                uint32_t q0 = (nt < 8) ? bl4[nt>>1][(nt&1)*2]   : bl2[0];
                uint32_t q1 = (nt < 8) ? bl4[nt>>1][(nt&1)*2+1] : bl2[1];
                MMA_BF16(acc[nt], ah, p0, p1);
                MMA_BF16(acc[nt], ah, q0, q1);
                MMA_BF16(acc[nt], al, p0, p1);
            }
        }
    }
    float den0 = __shfl_sync(0xffffffffu, acc[8][0], lane & ~3);
    float den1 = __shfl_sync(0xffffffffu, acc[8][2], lane & ~3);
    if (fabsf(den0) <= NSTAB) den0 += 2.f*NSTAB;
    if (fabsf(den1) <= NSTAB) den1 += 2.f*NSTAB;
    float inv0 = 1.f/den0, inv1 = 1.f/den1;
    int rr = w*16 + r0;
    size_t gl0 = (size_t)(b*L_ + l0 + rr), gl1 = gl0 + 8;
    #pragma unroll
    for (int nt = 0; nt < 8; ++nt) {
        int c0 = nt*8 + cb2;
        uint32_t hh, ll;
        cvt_split2(acc[nt][0]*inv0, acc[nt][1]*inv0, hh, ll);
        *(uint32_t*)(g_ctxh + gl0*D_ + h*64 + c0) = hh;
        *(uint32_t*)(g_ctxl + gl0*D_ + h*64 + c0) = ll;
        cvt_split2(acc[nt][2]*inv1, acc[nt][3]*inv1, hh, ll);
        *(uint32_t*)(g_ctxh + gl1*D_ + h*64 + c0) = hh;
        *(uint32_t*)(g_ctxl + gl1*D_ + h*64 + c0) = ll;
    }
}

// ---------------- launch (dual-stream overlap) ----------------
extern "C" void kernel_launch(void* const* d_in, const int* in_sizes, int n_in,
                              void* d_out, int out_size) {
    const float* query = (const float*)d_in[0];
    const float* key   = (const float*)d_in[1];
    const float* value = (const float*)d_in[2];
    const float* mask  = (const float*)d_in[3];
    const float* Wq = (const float*)d_in[4];
    const float* bq = (const float*)d_in[5];
    const float* Wk = (const float*)d_in[6];
    const float* bk = (const float*)d_in[7];
    const float* Wv = (const float*)d_in[8];
    const float* bv = (const float*)d_in[9];
    const float* Wo = (const float*)d_in[10];
    const float* bo = (const float*)d_in[11];
    const float* Wf = (const float*)d_in[12];

    float *Qp, *Kp, *Vp;
    __nv_bfloat16 *qah,*qal,*kah,*kal,*vah,*vaL;
    __nv_bfloat16 *wqh,*wql,*wkh,*wkl,*wvh,*wvl,*woh,*wol,*cth,*ctl;
    cudaGetSymbolAddress((void**)&Qp,  g_Qp);
    cudaGetSymbolAddress((void**)&Kp,  g_Kp);
    cudaGetSymbolAddress((void**)&Vp,  g_Vp);
    cudaGetSymbolAddress((void**)&qah, g_qah); cudaGetSymbolAddress((void**)&qal, g_qal);
    cudaGetSymbolAddress((void**)&kah, g_kah); cudaGetSymbolAddress((void**)&kal, g_kal);
    cudaGetSymbolAddress((void**)&vah, g_vah); cudaGetSymbolAddress((void**)&vaL, g_vaL);
    cudaGetSymbolAddress((void**)&wqh, g_wqh); cudaGetSymbolAddress((void**)&wql, g_wql);
    cudaGetSymbolAddress((void**)&wkh, g_wkh); cudaGetSymbolAddress((void**)&wkl, g_wkl);
    cudaGetSymbolAddress((void**)&wvh, g_wvh); cudaGetSymbolAddress((void**)&wvl, g_wvl);
    cudaGetSymbolAddress((void**)&woh, g_woh); cudaGetSymbolAddress((void**)&wol, g_wol);
    cudaGetSymbolAddress((void**)&cth, g_ctxh); cudaGetSymbolAddress((void**)&ctl, g_ctxl);

    cudaFuncSetAttribute(gemm_mma_b, cudaFuncAttributeMaxDynamicSharedMemorySize, GB_SMEM);
    cudaFuncSetAttribute(kv_mma,     cudaFuncAttributeMaxDynamicSharedMemorySize, KW_SMEM);
    cudaFuncSetAttribute(out_mma,    cudaFuncAttributeMaxDynamicSharedMemorySize, OW_SMEM);

    static cudaStream_t s1 = nullptr;
    static cudaEvent_t eS, eQ, eK, eV, eWo, eG2, eHK;
    if (!s1) {
        cudaStreamCreateWithFlags(&s1, cudaStreamNonBlocking);
        cudaEventCreateWithFlags(&eS,  cudaEventDisableTiming);
        cudaEventCreateWithFlags(&eQ,  cudaEventDisableTiming);
        cudaEventCreateWithFlags(&eK,  cudaEventDisableTiming);
        cudaEventCreateWithFlags(&eV,  cudaEventDisableTiming);
        cudaEventCreateWithFlags(&eWo, cudaEventDisableTiming);
        cudaEventCreateWithFlags(&eG2, cudaEventDisableTiming);
        cudaEventCreateWithFlags(&eHK, cudaEventDisableTiming);
    }

    const int nA4 = BL*D_/4, nW4 = D_*D_/4;
    dim3 gg(D_/128, BL/128);

    init_kernel<<<1, 32>>>();
    cudaEventRecord(eS, 0);
    cudaStreamWaitEvent(s1, eS, 0);

    split_kernel<<<nW4/256, 256, 0, s1>>>(Wq, wqh, wql, nW4);
    split_kernel<<<nA4/256, 256, 0, s1>>>(query, qah, qal, nA4);
    cudaEventRecord(eQ, s1);
    split_kernel<<<nW4/256, 256, 0, s1>>>(Wk, wkh, wkl, nW4);
    split_kernel<<<nA4/256, 256, 0, s1>>>(key, kah, kal, nA4);
    cudaEventRecord(eK, s1);
    split_kernel<<<nW4/256, 256, 0, s1>>>(Wv, wvh, wvl, nW4);
    split_kernel<<<nA4/256, 256, 0, s1>>>(value, vah, vaL, nA4);
    cudaEventRecord(eV, s1);
    split_kernel<<<nW4/256, 256, 0, s1>>>(Wo, woh, wol, nW4);
    cudaEventRecord(eWo, s1);

    cudaStreamWaitEvent(0, eQ, 0);
    gemm_mma_b<<<gg, 256, GB_SMEM>>>(qah, qal, wqh, wql, bq, Qp);
    cudaStreamWaitEvent(0, eK, 0);
    gemm_mma_b<<<gg, 256, GB_SMEM>>>(kah, kal, wkh, wkl, bk, Kp);
    cudaEventRecord(eG2, 0);
    cudaStreamWaitEvent(0, eV, 0);
    gemm_mma_b<<<gg, 256, GB_SMEM>>>(vah, vaL, wvh, wvl, bv, Vp);

    cudaStreamWaitEvent(s1, eG2, 0);
    hk_kernel<<<(BH*L_)/256, 256, 0, s1>>>();
    cudaEventRecord(eHK, s1);

    cudaStreamWaitEvent(0, eHK, 0);
    kv_mma<<<dim3(SPLIT, BH), KVNT, KW_SMEM>>>(Wf, mask);
    kv_reduce<<<(KVSZ2 + 255)/256, 256>>>();
    out_mma<<<dim3(L_/256, H_, B_), OUNT, OW_SMEM>>>(Wf);
    cudaStreamWaitEvent(0, eWo, 0);
    gemm_mma_b<<<gg, 256, GB_SMEM>>>(cth, ctl, woh, wol, bo, (float*)d_out);
}

// round 16
// speedup vs baseline: 1.5211x; 1.1677x over previous
#include <cuda_runtime.h>
#include <cuda_bf16.h>
#include <cuda_fp16.h>
#include <cstdint>
#include <math.h>

#define B_   2
#define L_   8192
#define D_   1024
#define H_   16
#define DH_  64
#define M_   266
#define BL   (B_*L_)
#define BH   (B_*H_)

#define SCALE  0.17677669529663687f
#define SCALE2 0.03125f
#define NC     0.061313932f
#define KEPS   1e-4f
#define NSTAB  1e-6f

#define SPLIT  16
#define KVROW  272
#define KVCOL  72
#define KVSZ2  (BH*KVROW*KVCOL)

// ---------------- device scratch ----------------
__device__ float g_Qp[BL*D_];
__device__ float g_Kp[BL*D_];
__device__ float g_Vp[BL*D_];
__device__ float g_hk[BH*L_];
__device__ unsigned int g_kstab;
__device__ float g_kv[KVSZ2];
__device__ float g_kvpart[(size_t)SPLIT*KVSZ2];
// fp16 GEMM operand buffers
__device__ __half g_qah[BL*D_], g_qal[BL*D_];
__device__ __half g_kah[BL*D_], g_kal[BL*D_];
__device__ __half g_vah[BL*D_], g_vaL[BL*D_];
__device__ __half g_wqh[D_*D_];
__device__ __half g_wkh[D_*D_];
__device__ __half g_wvh[D_*D_];
__device__ __half g_woh[D_*D_];
__device__ __half g_ctxh[BL*D_], g_ctxl[BL*D_];

// ================= helpers =================
__device__ __forceinline__ uint32_t smem_u32(const void* p) {
    uint32_t a;
    asm("{ .reg .u64 t; cvta.to.shared.u64 t, %1; cvt.u32.u64 %0, t; }" : "=r"(a) : "l"(p));
    return a;
}
// bf16 split (FAVOR chain, unchanged)
__device__ __forceinline__ void cvt_split(float4 v, uint32_t& h01, uint32_t& h23,
                                          uint32_t& l01, uint32_t& l23) {
    asm("cvt.rn.bf16x2.f32 %0, %1, %2;" : "=r"(h01) : "f"(v.y), "f"(v.x));
    asm("cvt.rn.bf16x2.f32 %0, %1, %2;" : "=r"(h23) : "f"(v.w), "f"(v.z));
    float r0 = v.x - __uint_as_float(h01 << 16);
    float r1 = v.y - __uint_as_float(h01 & 0xffff0000u);
    float r2 = v.z - __uint_as_float(h23 << 16);
    float r3 = v.w - __uint_as_float(h23 & 0xffff0000u);
    asm("cvt.rn.bf16x2.f32 %0, %1, %2;" : "=r"(l01) : "f"(r1), "f"(r0));
    asm("cvt.rn.bf16x2.f32 %0, %1, %2;" : "=r"(l23) : "f"(r3), "f"(r2));
}
__device__ __forceinline__ void cvt_split2(float a, float b, uint32_t& hh, uint32_t& ll) {
    asm("cvt.rn.bf16x2.f32 %0, %1, %2;" : "=r"(hh) : "f"(b), "f"(a));
    float ra = a - __uint_as_float(hh << 16);
    float rb = b - __uint_as_float(hh & 0xffff0000u);
    asm("cvt.rn.bf16x2.f32 %0, %1, %2;" : "=r"(ll) : "f"(rb), "f"(ra));
}
// fp16 splits (GEMM path)
__device__ __forceinline__ void cvt_splitH(float4 v, uint32_t& h01, uint32_t& h23,
                                           uint32_t& l01, uint32_t& l23) {
    __half2 a = __floats2half2_rn(v.x, v.y);
    __half2 b = __floats2half2_rn(v.z, v.w);
    float r0 = v.x - __half2float(__low2half(a));
    float r1 = v.y - __half2float(__high2half(a));
    float r2 = v.z - __half2float(__low2half(b));
    float r3 = v.w - __half2float(__high2half(b));
    __half2 c = __floats2half2_rn(r0, r1);
    __half2 d = __floats2half2_rn(r2, r3);
    h01 = *(uint32_t*)&a; h23 = *(uint32_t*)&b;
    l01 = *(uint32_t*)&c; l23 = *(uint32_t*)&d;
}
__device__ __forceinline__ void cvt_split2H(float a, float b, uint32_t& hh, uint32_t& ll) {
    __half2 p = __floats2half2_rn(a, b);
    float ra = a - __half2float(__low2half(p));
    float rb = b - __half2float(__high2half(p));
    __half2 q = __floats2half2_rn(ra, rb);
    hh = *(uint32_t*)&p; ll = *(uint32_t*)&q;
}
#define LDSM_X4(r0,r1,r2,r3,addr) \
    asm volatile("ldmatrix.sync.aligned.m8n8.x4.shared.b16 {%0,%1,%2,%3}, [%4];" \
        : "=r"(r0),"=r"(r1),"=r"(r2),"=r"(r3) : "r"(addr))
#define LDSM_X4T(r0,r1,r2,r3,addr) \
    asm volatile("ldmatrix.sync.aligned.m8n8.x4.trans.shared.b16 {%0,%1,%2,%3}, [%4];" \
        : "=r"(r0),"=r"(r1),"=r"(r2),"=r"(r3) : "r"(addr))
#define LDSM_X2T(r0,r1,addr) \
    asm volatile("ldmatrix.sync.aligned.m8n8.x2.trans.shared.b16 {%0,%1}, [%2];" \
        : "=r"(r0),"=r"(r1) : "r"(addr))
#define MMA_BF16(d,a,b0_,b1_) \
    asm volatile("mma.sync.aligned.m16n8k16.row.col.f32.bf16.bf16.f32 " \
        "{%0,%1,%2,%3}, {%4,%5,%6,%7}, {%8,%9}, {%0,%1,%2,%3};" \
        : "+f"((d)[0]),"+f"((d)[1]),"+f"((d)[2]),"+f"((d)[3]) \
        : "r"((a)[0]),"r"((a)[1]),"r"((a)[2]),"r"((a)[3]),"r"(b0_),"r"(b1_))
#define MMA_F16(d,a,b0_,b1_) \
    asm volatile("mma.sync.aligned.m16n8k16.row.col.f32.f16.f16.f32 " \
        "{%0,%1,%2,%3}, {%4,%5,%6,%7}, {%8,%9}, {%0,%1,%2,%3};" \
        : "+f"((d)[0]),"+f"((d)[1]),"+f"((d)[2]),"+f"((d)[3]) \
        : "r"((a)[0]),"r"((a)[1]),"r"((a)[2]),"r"((a)[3]),"r"(b0_),"r"(b1_))
#define CP16(dst, src) \
    asm volatile("cp.async.cg.shared.global [%0], [%1], 16;" :: "r"(dst), "l"(src))
#define CP_COMMIT() asm volatile("cp.async.commit_group;" ::: "memory")
#define CP_WAIT1()  asm volatile("cp.async.wait_group 1;" ::: "memory")
#define CP_WAIT0()  asm volatile("cp.async.wait_group 0;" ::: "memory")

// ================= fp32 -> fp16 hi/lo split (activations) =================
__global__ __launch_bounds__(256) void split_f16(const float* __restrict__ X,
                                                 __half* __restrict__ hi,
                                                 __half* __restrict__ lo,
                                                 int n4) {
    int i = blockIdx.x * 256 + threadIdx.x;
    if (i < n4) {
        float4 v = ((const float4*)X)[i];
        uint32_t h01, h23, l01, l23;
        cvt_splitH(v, h01, h23, l01, l23);
        ((uint2*)hi)[i] = make_uint2(h01, h23);
        ((uint2*)lo)[i] = make_uint2(l01, l23);
    }
}
// fp32 -> single fp16 (weights)
__global__ __launch_bounds__(256) void cvtw_f16(const float* __restrict__ X,
                                                __half* __restrict__ out, int n4) {
    int i = blockIdx.x * 256 + threadIdx.x;
    if (i < n4) {
        float4 v = ((const float4*)X)[i];
        __half2 a = __floats2half2_rn(v.x, v.y);
        __half2 b = __floats2half2_rn(v.z, v.w);
        ((uint2*)out)[i] = make_uint2(*(uint32_t*)&a, *(uint32_t*)&b);
    }
}

// ======== fp16x2-A x fp16-W GEMM: 2 mma passes, cp.async double-buffer ========
#define AST 40
#define GH_STAGE 30720   /* Ah 10240 | Al 10240 | Wh 10240 */
#define GH_SMEM  61440

__global__ __launch_bounds__(256, 2) void gemm_mma_h(const __half* __restrict__ Ah_,
                                                     const __half* __restrict__ Al_,
                                                     const __half* __restrict__ Wh_,
                                                     const float* __restrict__ bias,
                                                     float* __restrict__ C) {
    extern __shared__ char smg[];
    const uint32_t sb = smem_u32(smg);
    const int tid = threadIdx.x, lane = tid & 31, wid = tid >> 5;
    const int wm = wid & 1, wn = wid >> 1;
    const size_t mbase = (size_t)blockIdx.y * 128, nbase = (size_t)blockIdx.x * 128;
    const __half* Abh = Ah_ + mbase * D_;
    const __half* Abl = Al_ + mbase * D_;
    const __half* Wbh = Wh_ + nbase * D_;

    const int arow = lane & 15, acolsel = (lane >> 4) << 3;
    const int brow = (lane & 7) + ((lane >> 4) << 3), bcolsel = ((lane >> 3) & 1) << 3;

    const int pr0 = tid >> 2,         pu0 = tid & 3;
    const int pr1 = (tid + 256) >> 2, pu1 = (tid + 256) & 3;

    float acc[4][4][4];
    #pragma unroll
    for (int i = 0; i < 4; ++i)
        #pragma unroll
        for (int j = 0; j < 4; ++j)
            #pragma unroll
            for (int k = 0; k < 4; ++k) acc[i][j][k] = 0.f;

    {
        uint32_t d0 = sb + pr0*80 + pu0*16;
        uint32_t d1 = sb + pr1*80 + pu1*16;
        size_t s0 = (size_t)pr0*D_ + pu0*8;
        size_t s1 = (size_t)pr1*D_ + pu1*8;
        CP16(d0,          Abh + s0); CP16(d0 + 10240, Abl + s0); CP16(d0 + 20480, Wbh + s0);
        CP16(d1,          Abh + s1); CP16(d1 + 10240, Abl + s1); CP16(d1 + 20480, Wbh + s1);
        CP_COMMIT();
    }

    for (int kc = 0; kc < 32; ++kc) {
        int s = kc & 1;
        if (kc) __syncthreads();
        if (kc + 1 < 32) {
            uint32_t base = sb + (s^1)*GH_STAGE;
            int koff = (kc + 1) * 32;
            uint32_t d0 = base + pr0*80 + pu0*16;
            uint32_t d1 = base + pr1*80 + pu1*16;
            size_t s0 = (size_t)pr0*D_ + koff + pu0*8;
            size_t s1 = (size_t)pr1*D_ + koff + pu1*8;
            CP16(d0,          Abh + s0); CP16(d0 + 10240, Abl + s0); CP16(d0 + 20480, Wbh + s0);
            CP16(d1,          Abh + s1); CP16(d1 + 10240, Abl + s1); CP16(d1 + 20480, Wbh + s1);
            CP_COMMIT();
            CP_WAIT1();
        } else {
            CP_WAIT0();
        }
        __syncthreads();

        const uint32_t aH = sb + s*GH_STAGE;
        const uint32_t aL = aH + 10240;
        const uint32_t bH = aH + 20480;

        #pragma unroll
        for (int ks = 0; ks < 2; ++ks) {
            uint32_t af[4][4], bhF[2][4];
            #pragma unroll
            for (int mt = 0; mt < 4; ++mt) {
                uint32_t off = (uint32_t)(((wm*64 + mt*16 + arow)*AST + ks*16 + acolsel)*2);
                LDSM_X4(af[mt][0], af[mt][1], af[mt][2], af[mt][3], aH + off);
            }
            #pragma unroll
            for (int bp = 0; bp < 2; ++bp) {
                uint32_t off = (uint32_t)(((wn*32 + bp*16 + brow)*AST + ks*16 + bcolsel)*2);
                LDSM_X4(bhF[bp][0], bhF[bp][1], bhF[bp][2], bhF[bp][3], bH + off);
            }
            #pragma unroll
            for (int mt = 0; mt < 4; ++mt)
                #pragma unroll
                for (int nt = 0; nt < 4; ++nt)
                    MMA_F16(acc[mt][nt], af[mt], bhF[nt>>1][(nt&1)*2], bhF[nt>>1][(nt&1)*2+1]);
            #pragma unroll
            for (int mt = 0; mt < 4; ++mt) {
                uint32_t off = (uint32_t)(((wm*64 + mt*16 + arow)*AST + ks*16 + acolsel)*2);
                LDSM_X4(af[mt][0], af[mt][1], af[mt][2], af[mt][3], aL + off);
            }
            #pragma unroll
            for (int mt = 0; mt < 4; ++mt)
                #pragma unroll
                for (int nt = 0; nt < 4; ++nt)
                    MMA_F16(acc[mt][nt], af[mt], bhF[nt>>1][(nt&1)*2], bhF[nt>>1][(nt&1)*2+1]);
        }
    }
    #pragma unroll
    for (int mt = 0; mt < 4; ++mt) {
        size_t r0 = mbase + wm*64 + mt*16 + (lane >> 2);
        #pragma unroll
        for (int nt = 0; nt < 4; ++nt) {
            int col = (int)nbase + wn*32 + nt*8 + 2*(lane & 3);
            float bx = bias[col], by = bias[col+1];
            *(float2*)(C + r0*D_ + col)     = make_float2(acc[mt][nt][0]+bx, acc[mt][nt][1]+by);
            *(float2*)(C + (r0+8)*D_ + col) = make_float2(acc[mt][nt][2]+bx, acc[mt][nt][3]+by);
        }
    }
}

// ---------------- init / hk ----------------
__global__ void init_kernel() { if (threadIdx.x == 0) g_kstab = 0xFF800000u; }

__global__ __launch_bounds__(256) void hk_kernel() {
    int gid = blockIdx.x * 256 + threadIdx.x;
    int b = gid / (H_*L_), rem = gid % (H_*L_), h = rem / L_, l = rem % L_;
    const float4* row = (const float4*)(g_Kp + (size_t)(b*L_ + l)*D_ + h*DH_);
    float s = 0.f;
    #pragma unroll
    for (int t = 0; t < 16; ++t) {
        float4 v = row[t];
        s = fmaf(v.x,v.x,s); s = fmaf(v.y,v.y,s); s = fmaf(v.z,v.z,s); s = fmaf(v.w,v.w,s);
    }
    float hk = -0.5f * SCALE2 * s;
    g_hk[gid] = hk;
    float m = hk;
    #pragma unroll
    for (int o = 16; o > 0; o >>= 1) m = fmaxf(m, __shfl_xor_sync(0xffffffffu, m, o));
    __shared__ float wmax[8];
    if ((threadIdx.x & 31) == 0) wmax[threadIdx.x >> 5] = m;
    __syncthreads();
    if (threadIdx.x == 0) {
        float bm = wmax[0];
        #pragma unroll
        for (int w = 1; w < 8; ++w) bm = fmaxf(bm, wmax[w]);
        atomicMin(&g_kstab, __float_as_uint(bm));
    }
}

// ================= fused kv kernel: 576 threads / 18 warps (R14 proven) =================
#define KVNT 576
#define KST 296
#define KW_WFH 0
#define KW_WFL 41472
#define KW_XH  82944
#define KW_XL  92160
#define KW_KH  101376
#define KW_KL  139264
#define KW_VH  177152
#define KW_VL  186368
#define KW_HK  195584
#define KW_MS  195840
#define KW_SMEM 196096

__global__ __launch_bounds__(KVNT, 1) void kv_mma(const float* __restrict__ Wf,
                                                  const float* __restrict__ mask) {
    extern __shared__ char sm[];
    const uint32_t sb = smem_u32(sm);
    const int tid = threadIdx.x, lane = tid & 31, w = tid >> 5;
    const int split = blockIdx.x, bh = blockIdx.y;
    const int b = bh / H_, h = bh % H_;
    const int arow = lane & 15, acolsel = (lane >> 4) << 3;
    const int brow = (lane & 7) + ((lane >> 4) << 3), bcolsel = ((lane >> 3) & 1) << 3;

    for (int i = tid; i < 288*18; i += KVNT) {
        int r = i / 18, u = i % 18;
        float4 v = make_float4(0.f,0.f,0.f,0.f);
        if (r < 266 && u < 16) v = *(const float4*)(Wf + r*64 + u*4);
        uint32_t h01,h23,l01,l23; cvt_split(v,h01,h23,l01,l23);
        *(uint2*)(sm + KW_WFH + (r*72 + u*4)*2) = make_uint2(h01,h23);
        *(uint2*)(sm + KW_WFL + (r*72 + u*4)*2) = make_uint2(l01,l23);
    }
    float kstab = __uint_as_float(g_kstab);

    float acc[9][4];
    #pragma unroll
    for (int n = 0; n < 9; ++n)
        #pragma unroll
        for (int k = 0; k < 4; ++k) acc[n][k] = 0.f;

    for (int c = 0; c < 8; ++c) {
        int lb = split*512 + c*64;
        __syncthreads();
        for (int i = tid; i < 64*16; i += KVNT) {
            int r = i >> 4, u = i & 15;
            float4 v = *(const float4*)(g_Kp + (size_t)(b*L_+lb+r)*D_ + h*64 + u*4);
            v.x*=SCALE; v.y*=SCALE; v.z*=SCALE; v.w*=SCALE;
            uint32_t h01,h23,l01,l23; cvt_split(v,h01,h23,l01,l23);
            *(uint2*)(sm + KW_XH + (r*72 + u*4)*2) = make_uint2(h01,h23);
            *(uint2*)(sm + KW_XL + (r*72 + u*4)*2) = make_uint2(l01,l23);
        }
        for (int i = tid; i < 64*18; i += KVNT) {
            int r = i / 18, u = i % 18;
            float4 v;
            if (u < 16) v = *(const float4*)(g_Vp + (size_t)(b*L_+lb+r)*D_ + h*64 + u*4);
            else if (u == 16) v = make_float4(1.f,0.f,0.f,0.f);
            else v = make_float4(0.f,0.f,0.f,0.f);
            uint32_t h01,h23,l01,l23; cvt_split(v,h01,h23,l01,l23);
            *(uint2*)(sm + KW_VH + (r*72 + u*4)*2) = make_uint2(h01,h23);
            *(uint2*)(sm + KW_VL + (r*72 + u*4)*2) = make_uint2(l01,l23);
        }
        if (tid < 64) {
            ((float*)(sm + KW_HK))[tid] = g_hk[(size_t)bh*L_ + lb + tid] - kstab;
            ((float*)(sm + KW_MS))[tid] = mask[b*L_ + lb + tid];
        }
        __syncthreads();
        const int r0 = lane >> 2, cb2 = (lane & 3)*2;
        #pragma unroll
        for (int lt = 0; lt < 4; ++lt) {
            float pa[2][4];
            #pragma unroll
            for (int n = 0; n < 2; ++n)
                #pragma unroll
                for (int k = 0; k < 4; ++k) pa[n][k] = 0.f;
            #pragma unroll
            for (int ks = 0; ks < 4; ++ks) {
                uint32_t ah[4], al[4];
                uint32_t aoff = (uint32_t)(((lt*16 + arow)*72 + ks*16 + acolsel)*2);
                LDSM_X4(ah[0],ah[1],ah[2],ah[3], sb + KW_XH + aoff);
                LDSM_X4(al[0],al[1],al[2],al[3], sb + KW_XL + aoff);
                uint32_t boff = (uint32_t)(((w*16 + brow)*72 + ks*16 + bcolsel)*2);
                uint32_t bh_[4], bl_[4];
                LDSM_X4(bh_[0],bh_[1],bh_[2],bh_[3], sb + KW_WFH + boff);
                LDSM_X4(bl_[0],bl_[1],bl_[2],bl_[3], sb + KW_WFL + boff);
                #pragma unroll
                for (int half = 0; half < 2; ++half) {
                    MMA_BF16(pa[half], ah, bh_[half*2], bh_[half*2+1]);
                    MMA_BF16(pa[half], ah, bl_[half*2], bl_[half*2+1]);
                    MMA_BF16(pa[half], al, bh_[half*2], bh_[half*2+1]);
                }
            }
            int ra = lt*16 + r0, rb = ra + 8;
            float ha = ((float*)(sm + KW_HK))[ra], hb = ((float*)(sm + KW_HK))[rb];
            float ma = ((float*)(sm + KW_MS))[ra], mb = ((float*)(sm + KW_MS))[rb];
            #pragma unroll
            for (int nt = 0; nt < 2; ++nt) {
                int c0 = 16*w + nt*8 + cb2;
                float e0=0.f,e1=0.f,e2=0.f,e3=0.f;
                if (c0 < M_)   { e0 = NC*(__expf(pa[nt][0]+ha)+KEPS)*ma; e2 = NC*(__expf(pa[nt][2]+hb)+KEPS)*mb; }
                if (c0+1 < M_) { e1 = NC*(__expf(pa[nt][1]+ha)+KEPS)*ma; e3 = NC*(__expf(pa[nt][3]+hb)+KEPS)*mb; }
                uint32_t hh, ll;
                cvt_split2(e0, e1, hh, ll);
                *(uint32_t*)(sm + KW_KH + (ra*KST + c0)*2) = hh;
                *(uint32_t*)(sm + KW_KL + (ra*KST + c0)*2) = ll;
                cvt_split2(e2, e3, hh, ll);
                *(uint32_t*)(sm + KW_KH + (rb*KST + c0)*2) = hh;
                *(uint32_t*)(sm + KW_KL + (rb*KST + c0)*2) = ll;
            }
        }
        __syncthreads();
        #pragma unroll
        for (int ks = 0; ks < 4; ++ks) {
            uint32_t ah1[4], al1[4];
            uint32_t offA = (uint32_t)(((ks*16 + brow)*KST + w*16 + bcolsel)*2);
            LDSM_X4T(ah1[0],ah1[1],ah1[2],ah1[3], sb + KW_KH + offA);
            LDSM_X4T(al1[0],al1[1],al1[2],al1[3], sb + KW_KL + offA);
            uint32_t bh4[4][4], bl4[4][4], bh2[2], bl2[2];
            #pragma unroll
            for (int g = 0; g < 4; ++g) {
                uint32_t off = (uint32_t)(((ks*16 + arow)*72 + g*16 + acolsel)*2);
                LDSM_X4T(bh4[g][0],bh4[g][1],bh4[g][2],bh4[g][3], sb + KW_VH + off);
                LDSM_X4T(bl4[g][0],bl4[g][1],bl4[g][2],bl4[g][3], sb + KW_VL + off);
            }
            uint32_t off2 = (uint32_t)(((ks*16 + (lane & 15))*72 + 64)*2);
            LDSM_X2T(bh2[0], bh2[1], sb + KW_VH + off2);
            LDSM_X2T(bl2[0], bl2[1], sb + KW_VL + off2);
            #pragma unroll
            for (int nt = 0; nt < 9; ++nt) {
                uint32_t p0 = (nt < 8) ? bh4[nt>>1][(nt&1)*2]   : bh2[0];
                uint32_t p1 = (nt < 8) ? bh4[nt>>1][(nt&1)*2+1] : bh2[1];
                uint32_t q0 = (nt < 8) ? bl4[nt>>1][(nt&1)*2]   : bl2[0];
                uint32_t q1 = (nt < 8) ? bl4[nt>>1][(nt&1)*2+1] : bl2[1];
                MMA_BF16(acc[nt], ah1, p0, p1);
                MMA_BF16(acc[nt], ah1, q0, q1);
                MMA_BF16(acc[nt], al1, p0, p1);
            }
        }
    }
    if (w < 17) {
        float* base = g_kvpart + (size_t)(split*BH + bh)*KVROW*KVCOL;
        int r0 = w*16 + (lane >> 2);
        #pragma unroll
        for (int nt = 0; nt < 9; ++nt) {
            int c0 = nt*8 + (lane & 3)*2;
            *(float2*)(base + (size_t)r0*KVCOL + c0)     = make_float2(acc[nt][0], acc[nt][1]);
            *(float2*)(base + (size_t)(r0+8)*KVCOL + c0) = make_float2(acc[nt][2], acc[nt][3]);
        }
    }
}

__global__ void kv_reduce() {
    int idx = blockIdx.x * 256 + threadIdx.x;
    if (idx < KVSZ2) {
        float s = 0.f;
        #pragma unroll
        for (int p = 0; p < SPLIT; ++p) s += g_kvpart[(size_t)p*KVSZ2 + idx];
        g_kv[idx] = s;
    }
}

// ====== fused out kernel: 512 thr / 16 warps / 256 rows (R15 proven, fp16 ctx store) ======
#define OUNT 512
#define OW_KVH 0
#define OW_KVL 41472
#define OW_XH  82944
#define OW_XL  119808
#define OW_QH  156672
#define OW_QL  177152
#define OW_WFH 197632
#define OW_WFL 202240
#define OW_SMEM 206848

__global__ __launch_bounds__(OUNT, 1) void out_mma(const float* __restrict__ Wf) {
    extern __shared__ char sm[];
    const uint32_t sb = smem_u32(sm);
    const int tid = threadIdx.x, lane = tid & 31, w = tid >> 5;
    const int h = blockIdx.y, b = blockIdx.z, bh = b*H_ + h;
    const int l0 = blockIdx.x * 256;
    const int arow = lane & 15, acolsel = (lane >> 4) << 3;
    const int brow = (lane & 7) + ((lane >> 4) << 3), bcolsel = ((lane >> 3) & 1) << 3;

    for (int i = tid; i < 82944/4; i += OUNT) ((uint32_t*)sm)[i] = 0;
    __syncthreads();
    for (int i = tid; i < KVROW*18; i += OUNT) {
        int r = i / 18, u = i % 18;
        float4 v = *(const float4*)(g_kv + ((size_t)bh*KVROW + r)*KVCOL + u*4);
        uint32_t h01,h23,l01,l23; cvt_split(v,h01,h23,l01,l23);
        *(uint2*)(sm + OW_KVH + (r*72 + u*4)*2) = make_uint2(h01,h23);
        *(uint2*)(sm + OW_KVL + (r*72 + u*4)*2) = make_uint2(l01,l23);
    }
    for (int i = tid; i < 256*16; i += OUNT) {
        int r = i >> 4, u = i & 15;
        float4 v = *(const float4*)(g_Qp + (size_t)(b*L_+l0+r)*D_ + h*64 + u*4);
        v.x*=SCALE; v.y*=SCALE; v.z*=SCALE; v.w*=SCALE;
        uint32_t h01,h23,l01,l23; cvt_split(v,h01,h23,l01,l23);
        *(uint2*)(sm + OW_XH + (r*72 + u*4)*2) = make_uint2(h01,h23);
        *(uint2*)(sm + OW_XL + (r*72 + u*4)*2) = make_uint2(l01,l23);
    }

    float acc[9][4];
    #pragma unroll
    for (int n = 0; n < 9; ++n)
        #pragma unroll
        for (int k = 0; k < 4; ++k) acc[n][k] = 0.f;

    const int r0 = lane >> 2, cb2 = (lane & 3)*2;

    for (int mc = 0; mc < 9; ++mc) {
        __syncthreads();
        for (int i = tid; i < 32*18; i += OUNT) {
            int r = i / 18, u = i % 18;
            int gr = mc*32 + r;
            float4 v = make_float4(0.f,0.f,0.f,0.f);
            if (gr < 266 && u < 16) v = *(const float4*)(Wf + gr*64 + u*4);
            uint32_t h01,h23,l01,l23; cvt_split(v,h01,h23,l01,l23);
            *(uint2*)(sm + OW_WFH + (r*72 + u*4)*2) = make_uint2(h01,h23);
            *(uint2*)(sm + OW_WFL + (r*72 + u*4)*2) = make_uint2(l01,l23);
        }
        __syncthreads();
        float pa[4][4];
        #pragma unroll
        for (int n = 0; n < 4; ++n)
            #pragma unroll
            for (int k = 0; k < 4; ++k) pa[n][k] = 0.f;
        #pragma unroll
        for (int ks = 0; ks < 4; ++ks) {
            uint32_t ah[4], al[4];
            uint32_t aoff = (uint32_t)(((w*16 + arow)*72 + ks*16 + acolsel)*2);
            LDSM_X4(ah[0],ah[1],ah[2],ah[3], sb + OW_XH + aoff);
            LDSM_X4(al[0],al[1],al[2],al[3], sb + OW_XL + aoff);
            #pragma unroll
            for (int g = 0; g < 2; ++g) {
                uint32_t boff = (uint32_t)(((g*16 + brow)*72 + ks*16 + bcolsel)*2);
                uint32_t bh_[4], bl_[4];
                LDSM_X4(bh_[0],bh_[1],bh_[2],bh_[3], sb + OW_WFH + boff);
                LDSM_X4(bl_[0],bl_[1],bl_[2],bl_[3], sb + OW_WFL + boff);
                #pragma unroll
                for (int half = 0; half < 2; ++half) {
                    int nt = 2*g + half;
                    MMA_BF16(pa[nt], ah, bh_[half*2], bh_[half*2+1]);
                    MMA_BF16(pa[nt], ah, bl_[half*2], bl_[half*2+1]);
                    MMA_BF16(pa[nt], al, bh_[half*2], bh_[half*2+1]);
                }
            }
        }
        {
            int ra = w*16 + r0, rb = ra + 8;
            #pragma unroll
            for (int nt = 0; nt < 4; ++nt) {
                int lc = nt*8 + cb2;
                int gc = mc*32 + lc;
                float e0=0.f,e1=0.f,e2=0.f,e3=0.f;
                if (gc < M_)   { e0 = NC*(__expf(pa[nt][0])+KEPS); e2 = NC*(__expf(pa[nt][2])+KEPS); }
                if (gc+1 < M_) { e1 = NC*(__expf(pa[nt][1])+KEPS); e3 = NC*(__expf(pa[nt][3])+KEPS); }
                uint32_t hh, ll;
                cvt_split2(e0, e1, hh, ll);
                *(uint32_t*)(sm + OW_QH + (ra*40 + lc)*2) = hh;
                *(uint32_t*)(sm + OW_QL + (ra*40 + lc)*2) = ll;
                cvt_split2(e2, e3, hh, ll);
                *(uint32_t*)(sm + OW_QH + (rb*40 + lc)*2) = hh;
                *(uint32_t*)(sm + OW_QL + (rb*40 + lc)*2) = ll;
            }
        }
        __syncthreads();
        #pragma unroll
        for (int ks = 0; ks < 2; ++ks) {
            int gk = mc*32 + ks*16;
            uint32_t ah[4], al[4];
            uint32_t aoff = (uint32_t)(((w*16 + arow)*40 + ks*16 + acolsel)*2);
            LDSM_X4(ah[0],ah[1],ah[2],ah[3], sb + OW_QH + aoff);
            LDSM_X4(al[0],al[1],al[2],al[3], sb + OW_QL + aoff);
            uint32_t bh4[4][4], bl4[4][4], bh2[2], bl2[2];
            #pragma unroll
            for (int g = 0; g < 4; ++g) {
                uint32_t off = (uint32_t)(((gk + arow)*72 + g*16 + acolsel)*2);
                LDSM_X4T(bh4[g][0],bh4[g][1],bh4[g][2],bh4[g][3], sb + OW_KVH + off);
                LDSM_X4T(bl4[g][0],bl4[g][1],bl4[g][2],bl4[g][3], sb + OW_KVL + off);
            }
            uint32_t off2 = (uint32_t)(((gk + (lane & 15))*72 + 64)*2);
            LDSM_X2T(bh2[0], bh2[1], sb + OW_KVH + off2);
            LDSM_X2T(bl2[0], bl2[1], sb + OW_KVL + off2);
            #pragma unroll
            for (int nt = 0; nt < 9; ++nt) {
                uint32_t p0 = (nt < 8) ? bh4[nt>>1][(nt&1)*2]   : bh2[0];
                uint32_t p1 = (nt < 8) ? bh4[nt>>1][(nt&1)*2+1] : bh2[1];
                uint32_t q0 = (nt < 8) ? bl4[nt>>1][(nt&1)*2]   : bl2[0];
                uint32_t q1 = (nt < 8) ? bl4[nt>>1][(nt&1)*2+1] : bl2[1];
                MMA_BF16(acc[nt], ah, p0, p1);
                MMA_BF16(acc[nt], ah, q0, q1);
                MMA_BF16(acc[nt], al, p0, p1);
            }
        }
    }
    float den0 = __shfl_sync(0xffffffffu, acc[8][0], lane & ~3);
    float den1 = __shfl_sync(0xffffffffu, acc[8][2], lane & ~3);
    if (fabsf(den0) <= NSTAB) den0 += 2.f*NSTAB;
    if (fabsf(den1) <= NSTAB) den1 += 2.f*NSTAB;
    float inv0 = 1.f/den0, inv1 = 1.f/den1;
    int rr = w*16 + r0;
    size_t gl0 = (size_t)(b*L_ + l0 + rr), gl1 = gl0 + 8;
    #pragma unroll
    for (int nt = 0; nt < 8; ++nt) {
        int c0 = nt*8 + cb2;
        uint32_t hh, ll;
        cvt_split2H(acc[nt][0]*inv0, acc[nt][1]*inv0, hh, ll);
        *(uint32_t*)(g_ctxh + gl0*D_ + h*64 + c0) = hh;
        *(uint32_t*)(g_ctxl + gl0*D_ + h*64 + c0) = ll;
        cvt_split2H(acc[nt][2]*inv1, acc[nt][3]*inv1, hh, ll);
        *(uint32_t*)(g_ctxh + gl1*D_ + h*64 + c0) = hh;
        *(uint32_t*)(g_ctxl + gl1*D_ + h*64 + c0) = ll;
    }
}

// ---------------- launch (dual-stream overlap) ----------------
extern "C" void kernel_launch(void* const* d_in, const int* in_sizes, int n_in,
                              void* d_out, int out_size) {
    const float* query = (const float*)d_in[0];
    const float* key   = (const float*)d_in[1];
    const float* value = (const float*)d_in[2];
    const float* mask  = (const float*)d_in[3];
    const float* Wq = (const float*)d_in[4];
    const float* bq = (const float*)d_in[5];
    const float* Wk = (const float*)d_in[6];
    const float* bk = (const float*)d_in[7];
    const float* Wv = (const float*)d_in[8];
    const float* bv = (const float*)d_in[9];
    const float* Wo = (const float*)d_in[10];
    const float* bo = (const float*)d_in[11];
    const float* Wf = (const float*)d_in[12];

    float *Qp, *Kp, *Vp;
    __half *qah,*qal,*kah,*kal,*vah,*vaL;
    __half *wqh,*wkh,*wvh,*woh,*cth,*ctl;
    cudaGetSymbolAddress((void**)&Qp,  g_Qp);
    cudaGetSymbolAddress((void**)&Kp,  g_Kp);
    cudaGetSymbolAddress((void**)&Vp,  g_Vp);
    cudaGetSymbolAddress((void**)&qah, g_qah); cudaGetSymbolAddress((void**)&qal, g_qal);
    cudaGetSymbolAddress((void**)&kah, g_kah); cudaGetSymbolAddress((void**)&kal, g_kal);
    cudaGetSymbolAddress((void**)&vah, g_vah); cudaGetSymbolAddress((void**)&vaL, g_vaL);
    cudaGetSymbolAddress((void**)&wqh, g_wqh);
    cudaGetSymbolAddress((void**)&wkh, g_wkh);
    cudaGetSymbolAddress((void**)&wvh, g_wvh);
    cudaGetSymbolAddress((void**)&woh, g_woh);
    cudaGetSymbolAddress((void**)&cth, g_ctxh); cudaGetSymbolAddress((void**)&ctl, g_ctxl);

    cudaFuncSetAttribute(gemm_mma_h, cudaFuncAttributeMaxDynamicSharedMemorySize, GH_SMEM);
    cudaFuncSetAttribute(kv_mma,     cudaFuncAttributeMaxDynamicSharedMemorySize, KW_SMEM);
    cudaFuncSetAttribute(out_mma,    cudaFuncAttributeMaxDynamicSharedMemorySize, OW_SMEM);

    static cudaStream_t s1 = nullptr;
    static cudaEvent_t eS, eQ, eK, eV, eWo, eG2, eHK;
    if (!s1) {
        cudaStreamCreateWithFlags(&s1, cudaStreamNonBlocking);
        cudaEventCreateWithFlags(&eS,  cudaEventDisableTiming);
        cudaEventCreateWithFlags(&eQ,  cudaEventDisableTiming);
        cudaEventCreateWithFlags(&eK,  cudaEventDisableTiming);
        cudaEventCreateWithFlags(&eV,  cudaEventDisableTiming);
        cudaEventCreateWithFlags(&eWo, cudaEventDisableTiming);
        cudaEventCreateWithFlags(&eG2, cudaEventDisableTiming);
        cudaEventCreateWithFlags(&eHK, cudaEventDisableTiming);
    }

    const int nA4 = BL*D_/4, nW4 = D_*D_/4;
    dim3 gg(D_/128, BL/128);

    init_kernel<<<1, 32>>>();
    cudaEventRecord(eS, 0);
    cudaStreamWaitEvent(s1, eS, 0);

    cvtw_f16<<<nW4/256, 256, 0, s1>>>(Wq, wqh, nW4);
    split_f16<<<nA4/256, 256, 0, s1>>>(query, qah, qal, nA4);
    cudaEventRecord(eQ, s1);
    cvtw_f16<<<nW4/256, 256, 0, s1>>>(Wk, wkh, nW4);
    split_f16<<<nA4/256, 256, 0, s1>>>(key, kah, kal, nA4);
    cudaEventRecord(eK, s1);
    cvtw_f16<<<nW4/256, 256, 0, s1>>>(Wv, wvh, nW4);
    split_f16<<<nA4/256, 256, 0, s1>>>(value, vah, vaL, nA4);
    cudaEventRecord(eV, s1);
    cvtw_f16<<<nW4/256, 256, 0, s1>>>(Wo, woh, nW4);
    cudaEventRecord(eWo, s1);

    cudaStreamWaitEvent(0, eQ, 0);
    gemm_mma_h<<<gg, 256, GH_SMEM>>>(qah, qal, wqh, bq, Qp);
    cudaStreamWaitEvent(0, eK, 0);
    gemm_mma_h<<<gg, 256, GH_SMEM>>>(kah, kal, wkh, bk, Kp);
    cudaEventRecord(eG2, 0);
    cudaStreamWaitEvent(0, eV, 0);
    gemm_mma_h<<<gg, 256, GH_SMEM>>>(vah, vaL, wvh, bv, Vp);

    cudaStreamWaitEvent(s1, eG2, 0);
    hk_kernel<<<(BH*L_)/256, 256, 0, s1>>>();
    cudaEventRecord(eHK, s1);

    cudaStreamWaitEvent(0, eHK, 0);
    kv_mma<<<dim3(SPLIT, BH), KVNT, KW_SMEM>>>(Wf, mask);
    kv_reduce<<<(KVSZ2 + 255)/256, 256>>>();
    out_mma<<<dim3(L_/256, H_, B_), OUNT, OW_SMEM>>>(Wf);
    cudaStreamWaitEvent(0, eWo, 0);
    gemm_mma_h<<<gg, 256, GH_SMEM>>>(cth, ctl, woh, bo, (float*)d_out);
}

// round 17
// speedup vs baseline: 1.6328x; 1.0734x over previous
#include <cuda_runtime.h>
#include <cuda_fp16.h>
#include <cstdint>
#include <math.h>

#define B_   2
#define L_   8192
#define D_   1024
#define H_   16
#define DH_  64
#define M_   266
#define BL   (B_*L_)
#define BH   (B_*H_)

#define SCALE  0.17677669529663687f
#define SCALE2 0.03125f
#define NC     0.061313932f
#define KEPS   1e-4f
#define NSTAB  1e-6f

#define SPLIT  16
#define KVROW  272
#define KVCOL  72
#define KVSZ2  (BH*KVROW*KVCOL)

// ---------------- device scratch ----------------
__device__ float g_Qp[BL*D_];
__device__ float g_Kp[BL*D_];
__device__ float g_Vp[BL*D_];
__device__ float g_hk[BH*L_];
__device__ unsigned int g_kstab;
__device__ float g_kv[KVSZ2];
__device__ float g_kvpart[(size_t)SPLIT*KVSZ2];
__device__ __half g_qah[BL*D_], g_qal[BL*D_];
__device__ __half g_kah[BL*D_], g_kal[BL*D_];
__device__ __half g_vah[BL*D_], g_vaL[BL*D_];
__device__ __half g_wqh[D_*D_];
__device__ __half g_wkh[D_*D_];
__device__ __half g_wvh[D_*D_];
__device__ __half g_woh[D_*D_];
__device__ __half g_ctxh[BL*D_], g_ctxl[BL*D_];

// ================= helpers =================
__device__ __forceinline__ uint32_t smem_u32(const void* p) {
    uint32_t a;
    asm("{ .reg .u64 t; cvta.to.shared.u64 t, %1; cvt.u32.u64 %0, t; }" : "=r"(a) : "l"(p));
    return a;
}
__device__ __forceinline__ void cvt_splitH(float4 v, uint32_t& h01, uint32_t& h23,
                                           uint32_t& l01, uint32_t& l23) {
    __half2 a = __floats2half2_rn(v.x, v.y);
    __half2 b = __floats2half2_rn(v.z, v.w);
    float r0 = v.x - __half2float(__low2half(a));
    float r1 = v.y - __half2float(__high2half(a));
    float r2 = v.z - __half2float(__low2half(b));
    float r3 = v.w - __half2float(__high2half(b));
    __half2 c = __floats2half2_rn(r0, r1);
    __half2 d = __floats2half2_rn(r2, r3);
    h01 = *(uint32_t*)&a; h23 = *(uint32_t*)&b;
    l01 = *(uint32_t*)&c; l23 = *(uint32_t*)&d;
}
__device__ __forceinline__ void cvt_split2H(float a, float b, uint32_t& hh, uint32_t& ll) {
    __half2 p = __floats2half2_rn(a, b);
    float ra = a - __half2float(__low2half(p));
    float rb = b - __half2float(__high2half(p));
    __half2 q = __floats2half2_rn(ra, rb);
    hh = *(uint32_t*)&p; ll = *(uint32_t*)&q;
}
__device__ __forceinline__ uint2 cvt4H(float4 v) {
    __half2 a = __floats2half2_rn(v.x, v.y);
    __half2 b = __floats2half2_rn(v.z, v.w);
    return make_uint2(*(uint32_t*)&a, *(uint32_t*)&b);
}
#define LDSM_X4(r0,r1,r2,r3,addr) \
    asm volatile("ldmatrix.sync.aligned.m8n8.x4.shared.b16 {%0,%1,%2,%3}, [%4];" \
        : "=r"(r0),"=r"(r1),"=r"(r2),"=r"(r3) : "r"(addr))
#define LDSM_X4T(r0,r1,r2,r3,addr) \
    asm volatile("ldmatrix.sync.aligned.m8n8.x4.trans.shared.b16 {%0,%1,%2,%3}, [%4];" \
        : "=r"(r0),"=r"(r1),"=r"(r2),"=r"(r3) : "r"(addr))
#define LDSM_X2T(r0,r1,addr) \
    asm volatile("ldmatrix.sync.aligned.m8n8.x2.trans.shared.b16 {%0,%1}, [%2];" \
        : "=r"(r0),"=r"(r1) : "r"(addr))
#define MMA_F16(d,a,b0_,b1_) \
    asm volatile("mma.sync.aligned.m16n8k16.row.col.f32.f16.f16.f32 " \
        "{%0,%1,%2,%3}, {%4,%5,%6,%7}, {%8,%9}, {%0,%1,%2,%3};" \
        : "+f"((d)[0]),"+f"((d)[1]),"+f"((d)[2]),"+f"((d)[3]) \
        : "r"((a)[0]),"r"((a)[1]),"r"((a)[2]),"r"((a)[3]),"r"(b0_),"r"(b1_))
#define CP16(dst, src) \
    asm volatile("cp.async.cg.shared.global [%0], [%1], 16;" :: "r"(dst), "l"(src))
#define CP_COMMIT() asm volatile("cp.async.commit_group;" ::: "memory")
#define CP_WAIT1()  asm volatile("cp.async.wait_group 1;" ::: "memory")
#define CP_WAIT0()  asm volatile("cp.async.wait_group 0;" ::: "memory")

// ================= fp32 -> fp16 splits =================
__global__ __launch_bounds__(256) void split_f16(const float* __restrict__ X,
                                                 __half* __restrict__ hi,
                                                 __half* __restrict__ lo,
                                                 int n4) {
    int i = blockIdx.x * 256 + threadIdx.x;
    if (i < n4) {
        float4 v = ((const float4*)X)[i];
        uint32_t h01, h23, l01, l23;
        cvt_splitH(v, h01, h23, l01, l23);
        ((uint2*)hi)[i] = make_uint2(h01, h23);
        ((uint2*)lo)[i] = make_uint2(l01, l23);
    }
}
__global__ __launch_bounds__(256) void cvtw_f16(const float* __restrict__ X,
                                                __half* __restrict__ out, int n4) {
    int i = blockIdx.x * 256 + threadIdx.x;
    if (i < n4) ((uint2*)out)[i] = cvt4H(((const float4*)X)[i]);
}

// ======== fp16x2-A x fp16-W GEMM (R16 proven: 2 mma passes) ========
#define AST 40
#define GH_STAGE 30720
#define GH_SMEM  61440

__global__ __launch_bounds__(256, 2) void gemm_mma_h(const __half* __restrict__ Ah_,
                                                     const __half* __restrict__ Al_,
                                                     const __half* __restrict__ Wh_,
                                                     const float* __restrict__ bias,
                                                     float* __restrict__ C) {
    extern __shared__ char smg[];
    const uint32_t sb = smem_u32(smg);
    const int tid = threadIdx.x, lane = tid & 31, wid = tid >> 5;
    const int wm = wid & 1, wn = wid >> 1;
    const size_t mbase = (size_t)blockIdx.y * 128, nbase = (size_t)blockIdx.x * 128;
    const __half* Abh = Ah_ + mbase * D_;
    const __half* Abl = Al_ + mbase * D_;
    const __half* Wbh = Wh_ + nbase * D_;

    const int arow = lane & 15, acolsel = (lane >> 4) << 3;
    const int brow = (lane & 7) + ((lane >> 4) << 3), bcolsel = ((lane >> 3) & 1) << 3;

    const int pr0 = tid >> 2,         pu0 = tid & 3;
    const int pr1 = (tid + 256) >> 2, pu1 = (tid + 256) & 3;

    float acc[4][4][4];
    #pragma unroll
    for (int i = 0; i < 4; ++i)
        #pragma unroll
        for (int j = 0; j < 4; ++j)
            #pragma unroll
            for (int k = 0; k < 4; ++k) acc[i][j][k] = 0.f;

    {
        uint32_t d0 = sb + pr0*80 + pu0*16;
        uint32_t d1 = sb + pr1*80 + pu1*16;
        size_t s0 = (size_t)pr0*D_ + pu0*8;
        size_t s1 = (size_t)pr1*D_ + pu1*8;
        CP16(d0,          Abh + s0); CP16(d0 + 10240, Abl + s0); CP16(d0 + 20480, Wbh + s0);
        CP16(d1,          Abh + s1); CP16(d1 + 10240, Abl + s1); CP16(d1 + 20480, Wbh + s1);
        CP_COMMIT();
    }

    for (int kc = 0; kc < 32; ++kc) {
        int s = kc & 1;
        if (kc) __syncthreads();
        if (kc + 1 < 32) {
            uint32_t base = sb + (s^1)*GH_STAGE;
            int koff = (kc + 1) * 32;
            uint32_t d0 = base + pr0*80 + pu0*16;
            uint32_t d1 = base + pr1*80 + pu1*16;
            size_t s0 = (size_t)pr0*D_ + koff + pu0*8;
            size_t s1 = (size_t)pr1*D_ + koff + pu1*8;
            CP16(d0,          Abh + s0); CP16(d0 + 10240, Abl + s0); CP16(d0 + 20480, Wbh + s0);
            CP16(d1,          Abh + s1); CP16(d1 + 10240, Abl + s1); CP16(d1 + 20480, Wbh + s1);
            CP_COMMIT();
            CP_WAIT1();
        } else {
            CP_WAIT0();
        }
        __syncthreads();

        const uint32_t aH = sb + s*GH_STAGE;
        const uint32_t aL = aH + 10240;
        const uint32_t bH = aH + 20480;

        #pragma unroll
        for (int ks = 0; ks < 2; ++ks) {
            uint32_t af[4][4], bhF[2][4];
            #pragma unroll
            for (int mt = 0; mt < 4; ++mt) {
                uint32_t off = (uint32_t)(((wm*64 + mt*16 + arow)*AST + ks*16 + acolsel)*2);
                LDSM_X4(af[mt][0], af[mt][1], af[mt][2], af[mt][3], aH + off);
            }
            #pragma unroll
            for (int bp = 0; bp < 2; ++bp) {
                uint32_t off = (uint32_t)(((wn*32 + bp*16 + brow)*AST + ks*16 + bcolsel)*2);
                LDSM_X4(bhF[bp][0], bhF[bp][1], bhF[bp][2], bhF[bp][3], bH + off);
            }
            #pragma unroll
            for (int mt = 0; mt < 4; ++mt)
                #pragma unroll
                for (int nt = 0; nt < 4; ++nt)
                    MMA_F16(acc[mt][nt], af[mt], bhF[nt>>1][(nt&1)*2], bhF[nt>>1][(nt&1)*2+1]);
            #pragma unroll
            for (int mt = 0; mt < 4; ++mt) {
                uint32_t off = (uint32_t)(((wm*64 + mt*16 + arow)*AST + ks*16 + acolsel)*2);
                LDSM_X4(af[mt][0], af[mt][1], af[mt][2], af[mt][3], aL + off);
            }
            #pragma unroll
            for (int mt = 0; mt < 4; ++mt)
                #pragma unroll
                for (int nt = 0; nt < 4; ++nt)
                    MMA_F16(acc[mt][nt], af[mt], bhF[nt>>1][(nt&1)*2], bhF[nt>>1][(nt&1)*2+1]);
        }
    }
    #pragma unroll
    for (int mt = 0; mt < 4; ++mt) {
        size_t r0 = mbase + wm*64 + mt*16 + (lane >> 2);
        #pragma unroll
        for (int nt = 0; nt < 4; ++nt) {
            int col = (int)nbase + wn*32 + nt*8 + 2*(lane & 3);
            float bx = bias[col], by = bias[col+1];
            *(float2*)(C + r0*D_ + col)     = make_float2(acc[mt][nt][0]+bx, acc[mt][nt][1]+by);
            *(float2*)(C + (r0+8)*D_ + col) = make_float2(acc[mt][nt][2]+bx, acc[mt][nt][3]+by);
        }
    }
}

// ---------------- init / hk ----------------
__global__ void init_kernel() { if (threadIdx.x == 0) g_kstab = 0xFF800000u; }

__global__ __launch_bounds__(256) void hk_kernel() {
    int gid = blockIdx.x * 256 + threadIdx.x;
    int b = gid / (H_*L_), rem = gid % (H_*L_), h = rem / L_, l = rem % L_;
    const float4* row = (const float4*)(g_Kp + (size_t)(b*L_ + l)*D_ + h*DH_);
    float s = 0.f;
    #pragma unroll
    for (int t = 0; t < 16; ++t) {
        float4 v = row[t];
        s = fmaf(v.x,v.x,s); s = fmaf(v.y,v.y,s); s = fmaf(v.z,v.z,s); s = fmaf(v.w,v.w,s);
    }
    float hk = -0.5f * SCALE2 * s;
    g_hk[gid] = hk;
    float m = hk;
    #pragma unroll
    for (int o = 16; o > 0; o >>= 1) m = fmaxf(m, __shfl_xor_sync(0xffffffffu, m, o));
    __shared__ float wmax[8];
    if ((threadIdx.x & 31) == 0) wmax[threadIdx.x >> 5] = m;
    __syncthreads();
    if (threadIdx.x == 0) {
        float bm = wmax[0];
        #pragma unroll
        for (int w = 1; w < 8; ++w) bm = fmaxf(bm, wmax[w]);
        atomicMin(&g_kstab, __float_as_uint(bm));
    }
}

// ============ fused kv kernel: fp16 2-pass, 576 threads / 18 warps ============
#define KVNT 576
#define KST 296
#define KW_WFH 0
#define KW_XH  41472
#define KW_XL  50688
#define KW_KH  59904
#define KW_KL  97792
#define KW_VH  135680
#define KW_HK  144896
#define KW_MS  145152
#define KW_SMEM 145408

__global__ __launch_bounds__(KVNT, 1) void kv_mma(const float* __restrict__ Wf,
                                                  const float* __restrict__ mask) {
    extern __shared__ char sm[];
    const uint32_t sb = smem_u32(sm);
    const int tid = threadIdx.x, lane = tid & 31, w = tid >> 5;
    const int split = blockIdx.x, bh = blockIdx.y;
    const int b = bh / H_, h = bh % H_;
    const int arow = lane & 15, acolsel = (lane >> 4) << 3;
    const int brow = (lane & 7) + ((lane >> 4) << 3), bcolsel = ((lane >> 3) & 1) << 3;

    for (int i = tid; i < 288*18; i += KVNT) {
        int r = i / 18, u = i % 18;
        float4 v = make_float4(0.f,0.f,0.f,0.f);
        if (r < 266 && u < 16) v = *(const float4*)(Wf + r*64 + u*4);
        *(uint2*)(sm + KW_WFH + (r*72 + u*4)*2) = cvt4H(v);
    }
    float kstab = __uint_as_float(g_kstab);

    float acc[9][4];
    #pragma unroll
    for (int n = 0; n < 9; ++n)
        #pragma unroll
        for (int k = 0; k < 4; ++k) acc[n][k] = 0.f;

    for (int c = 0; c < 8; ++c) {
        int lb = split*512 + c*64;
        __syncthreads();
        for (int i = tid; i < 64*16; i += KVNT) {
            int r = i >> 4, u = i & 15;
            float4 v = *(const float4*)(g_Kp + (size_t)(b*L_+lb+r)*D_ + h*64 + u*4);
            v.x*=SCALE; v.y*=SCALE; v.z*=SCALE; v.w*=SCALE;
            uint32_t h01,h23,l01,l23; cvt_splitH(v,h01,h23,l01,l23);
            *(uint2*)(sm + KW_XH + (r*72 + u*4)*2) = make_uint2(h01,h23);
            *(uint2*)(sm + KW_XL + (r*72 + u*4)*2) = make_uint2(l01,l23);
        }
        for (int i = tid; i < 64*18; i += KVNT) {
            int r = i / 18, u = i % 18;
            float4 v;
            if (u < 16) v = *(const float4*)(g_Vp + (size_t)(b*L_+lb+r)*D_ + h*64 + u*4);
            else if (u == 16) v = make_float4(1.f,0.f,0.f,0.f);
            else v = make_float4(0.f,0.f,0.f,0.f);
            *(uint2*)(sm + KW_VH + (r*72 + u*4)*2) = cvt4H(v);
        }
        if (tid < 64) {
            ((float*)(sm + KW_HK))[tid] = g_hk[(size_t)bh*L_ + lb + tid] - kstab;
            ((float*)(sm + KW_MS))[tid] = mask[b*L_ + lb + tid];
        }
        __syncthreads();
        const int r0 = lane >> 2, cb2 = (lane & 3)*2;
        #pragma unroll
        for (int lt = 0; lt < 4; ++lt) {
            float pa[2][4];
            #pragma unroll
            for (int n = 0; n < 2; ++n)
                #pragma unroll
                for (int k = 0; k < 4; ++k) pa[n][k] = 0.f;
            #pragma unroll
            for (int ks = 0; ks < 4; ++ks) {
                uint32_t ah[4], al[4];
                uint32_t aoff = (uint32_t)(((lt*16 + arow)*72 + ks*16 + acolsel)*2);
                LDSM_X4(ah[0],ah[1],ah[2],ah[3], sb + KW_XH + aoff);
                LDSM_X4(al[0],al[1],al[2],al[3], sb + KW_XL + aoff);
                uint32_t boff = (uint32_t)(((w*16 + brow)*72 + ks*16 + bcolsel)*2);
                uint32_t bh_[4];
                LDSM_X4(bh_[0],bh_[1],bh_[2],bh_[3], sb + KW_WFH + boff);
                #pragma unroll
                for (int half = 0; half < 2; ++half) {
                    MMA_F16(pa[half], ah, bh_[half*2], bh_[half*2+1]);
                    MMA_F16(pa[half], al, bh_[half*2], bh_[half*2+1]);
                }
            }
            int ra = lt*16 + r0, rb = ra + 8;
            float ha = ((float*)(sm + KW_HK))[ra], hb = ((float*)(sm + KW_HK))[rb];
            float ma = ((float*)(sm + KW_MS))[ra], mb = ((float*)(sm + KW_MS))[rb];
            #pragma unroll
            for (int nt = 0; nt < 2; ++nt) {
                int c0 = 16*w + nt*8 + cb2;
                float e0=0.f,e1=0.f,e2=0.f,e3=0.f;
                if (c0 < M_)   { e0 = NC*(__expf(pa[nt][0]+ha)+KEPS)*ma; e2 = NC*(__expf(pa[nt][2]+hb)+KEPS)*mb; }
                if (c0+1 < M_) { e1 = NC*(__expf(pa[nt][1]+ha)+KEPS)*ma; e3 = NC*(__expf(pa[nt][3]+hb)+KEPS)*mb; }
                uint32_t hh, ll;
                cvt_split2H(e0, e1, hh, ll);
                *(uint32_t*)(sm + KW_KH + (ra*KST + c0)*2) = hh;
                *(uint32_t*)(sm + KW_KL + (ra*KST + c0)*2) = ll;
                cvt_split2H(e2, e3, hh, ll);
                *(uint32_t*)(sm + KW_KH + (rb*KST + c0)*2) = hh;
                *(uint32_t*)(sm + KW_KL + (rb*KST + c0)*2) = ll;
            }
        }
        __syncthreads();
        #pragma unroll
        for (int ks = 0; ks < 4; ++ks) {
            uint32_t ah1[4], al1[4];
            uint32_t offA = (uint32_t)(((ks*16 + brow)*KST + w*16 + bcolsel)*2);
            LDSM_X4T(ah1[0],ah1[1],ah1[2],ah1[3], sb + KW_KH + offA);
            LDSM_X4T(al1[0],al1[1],al1[2],al1[3], sb + KW_KL + offA);
            uint32_t bh4[4][4], bh2[2];
            #pragma unroll
            for (int g = 0; g < 4; ++g) {
                uint32_t off = (uint32_t)(((ks*16 + arow)*72 + g*16 + acolsel)*2);
                LDSM_X4T(bh4[g][0],bh4[g][1],bh4[g][2],bh4[g][3], sb + KW_VH + off);
            }
            uint32_t off2 = (uint32_t)(((ks*16 + (lane & 15))*72 + 64)*2);
            LDSM_X2T(bh2[0], bh2[1], sb + KW_VH + off2);
            #pragma unroll
            for (int nt = 0; nt < 9; ++nt) {
                uint32_t p0 = (nt < 8) ? bh4[nt>>1][(nt&1)*2]   : bh2[0];
                uint32_t p1 = (nt < 8) ? bh4[nt>>1][(nt&1)*2+1] : bh2[1];
                MMA_F16(acc[nt], ah1, p0, p1);
                MMA_F16(acc[nt], al1, p0, p1);
            }
        }
    }
    if (w < 17) {
        float* base = g_kvpart + (size_t)(split*BH + bh)*KVROW*KVCOL;
        int r0 = w*16 + (lane >> 2);
        #pragma unroll
        for (int nt = 0; nt < 9; ++nt) {
            int c0 = nt*8 + (lane & 3)*2;
            *(float2*)(base + (size_t)r0*KVCOL + c0)     = make_float2(acc[nt][0], acc[nt][1]);
            *(float2*)(base + (size_t)(r0+8)*KVCOL + c0) = make_float2(acc[nt][2], acc[nt][3]);
        }
    }
}

__global__ void kv_reduce() {
    int idx = blockIdx.x * 256 + threadIdx.x;
    if (idx < KVSZ2) {
        float s = 0.f;
        #pragma unroll
        for (int p = 0; p < SPLIT; ++p) s += g_kvpart[(size_t)p*KVSZ2 + idx];
        g_kv[idx] = s;
    }
}

// ====== fused out kernel: fp16 2-pass, 512 thr / 16 warps / 256 rows ======
#define OUNT 512
#define OW_KVH 0
#define OW_XH  41472
#define OW_XL  78336
#define OW_QH  115200
#define OW_QL  135680
#define OW_WFH 156160
#define OW_SMEM 160768

__global__ __launch_bounds__(OUNT, 1) void out_mma(const float* __restrict__ Wf) {
    extern __shared__ char sm[];
    const uint32_t sb = smem_u32(sm);
    const int tid = threadIdx.x, lane = tid & 31, w = tid >> 5;
    const int h = blockIdx.y, b = blockIdx.z, bh = b*H_ + h;
    const int l0 = blockIdx.x * 256;
    const int arow = lane & 15, acolsel = (lane >> 4) << 3;
    const int brow = (lane & 7) + ((lane >> 4) << 3), bcolsel = ((lane >> 3) & 1) << 3;

    // zero kv buffer (rows >= 272 and any pad)
    for (int i = tid; i < 41472/4; i += OUNT) ((uint32_t*)sm)[i] = 0;
    __syncthreads();
    for (int i = tid; i < KVROW*18; i += OUNT) {
        int r = i / 18, u = i % 18;
        float4 v = *(const float4*)(g_kv + ((size_t)bh*KVROW + r)*KVCOL + u*4);
        *(uint2*)(sm + OW_KVH + (r*72 + u*4)*2) = cvt4H(v);
    }
    for (int i = tid; i < 256*16; i += OUNT) {
        int r = i >> 4, u = i & 15;
        float4 v = *(const float4*)(g_Qp + (size_t)(b*L_+l0+r)*D_ + h*64 + u*4);
        v.x*=SCALE; v.y*=SCALE; v.z*=SCALE; v.w*=SCALE;
        uint32_t h01,h23,l01,l23; cvt_splitH(v,h01,h23,l01,l23);
        *(uint2*)(sm + OW_XH + (r*72 + u*4)*2) = make_uint2(h01,h23);
        *(uint2*)(sm + OW_XL + (r*72 + u*4)*2) = make_uint2(l01,l23);
    }

    float acc[9][4];
    #pragma unroll
    for (int n = 0; n < 9; ++n)
        #pragma unroll
        for (int k = 0; k < 4; ++k) acc[n][k] = 0.f;

    const int r0 = lane >> 2, cb2 = (lane & 3)*2;

    for (int mc = 0; mc < 9; ++mc) {
        __syncthreads();
        for (int i = tid; i < 32*18; i += OUNT) {
            int r = i / 18, u = i % 18;
            int gr = mc*32 + r;
            float4 v = make_float4(0.f,0.f,0.f,0.f);
            if (gr < 266 && u < 16) v = *(const float4*)(Wf + gr*64 + u*4);
            *(uint2*)(sm + OW_WFH + (r*72 + u*4)*2) = cvt4H(v);
        }
        __syncthreads();
        float pa[4][4];
        #pragma unroll
        for (int n = 0; n < 4; ++n)
            #pragma unroll
            for (int k = 0; k < 4; ++k) pa[n][k] = 0.f;
        #pragma unroll
        for (int ks = 0; ks < 4; ++ks) {
            uint32_t ah[4], al[4];
            uint32_t aoff = (uint32_t)(((w*16 + arow)*72 + ks*16 + acolsel)*2);
            LDSM_X4(ah[0],ah[1],ah[2],ah[3], sb + OW_XH + aoff);
            LDSM_X4(al[0],al[1],al[2],al[3], sb + OW_XL + aoff);
            #pragma unroll
            for (int g = 0; g < 2; ++g) {
                uint32_t boff = (uint32_t)(((g*16 + brow)*72 + ks*16 + bcolsel)*2);
                uint32_t bh_[4];
                LDSM_X4(bh_[0],bh_[1],bh_[2],bh_[3], sb + OW_WFH + boff);
                #pragma unroll
                for (int half = 0; half < 2; ++half) {
                    int nt = 2*g + half;
                    MMA_F16(pa[nt], ah, bh_[half*2], bh_[half*2+1]);
                    MMA_F16(pa[nt], al, bh_[half*2], bh_[half*2+1]);
                }
            }
        }
        {
            int ra = w*16 + r0, rb = ra + 8;
            #pragma unroll
            for (int nt = 0; nt < 4; ++nt) {
                int lc = nt*8 + cb2;
                int gc = mc*32 + lc;
                float e0=0.f,e1=0.f,e2=0.f,e3=0.f;
                if (gc < M_)   { e0 = NC*(__expf(pa[nt][0])+KEPS); e2 = NC*(__expf(pa[nt][2])+KEPS); }
                if (gc+1 < M_) { e1 = NC*(__expf(pa[nt][1])+KEPS); e3 = NC*(__expf(pa[nt][3])+KEPS); }
                uint32_t hh, ll;
                cvt_split2H(e0, e1, hh, ll);
                *(uint32_t*)(sm + OW_QH + (ra*40 + lc)*2) = hh;
                *(uint32_t*)(sm + OW_QL + (ra*40 + lc)*2) = ll;
                cvt_split2H(e2, e3, hh, ll);
                *(uint32_t*)(sm + OW_QH + (rb*40 + lc)*2) = hh;
                *(uint32_t*)(sm + OW_QL + (rb*40 + lc)*2) = ll;
            }
        }
        __syncthreads();
        #pragma unroll
        for (int ks = 0; ks < 2; ++ks) {
            int gk = mc*32 + ks*16;
            uint32_t ah[4], al[4];
            uint32_t aoff = (uint32_t)(((w*16 + arow)*40 + ks*16 + acolsel)*2);
            LDSM_X4(ah[0],ah[1],ah[2],ah[3], sb + OW_QH + aoff);
            LDSM_X4(al[0],al[1],al[2],al[3], sb + OW_QL + aoff);
            uint32_t bh4[4][4], bh2[2];
            #pragma unroll
            for (int g = 0; g < 4; ++g) {
                uint32_t off = (uint32_t)(((gk + arow)*72 + g*16 + acolsel)*2);
                LDSM_X4T(bh4[g][0],bh4[g][1],bh4[g][2],bh4[g][3], sb + OW_KVH + off);
            }
            uint32_t off2 = (uint32_t)(((gk + (lane & 15))*72 + 64)*2);
            LDSM_X2T(bh2[0], bh2[1], sb + OW_KVH + off2);
            #pragma unroll
            for (int nt = 0; nt < 9; ++nt) {
                uint32_t p0 = (nt < 8) ? bh4[nt>>1][(nt&1)*2]   : bh2[0];
                uint32_t p1 = (nt < 8) ? bh4[nt>>1][(nt&1)*2+1] : bh2[1];
                MMA_F16(acc[nt], ah, p0, p1);
                MMA_F16(acc[nt], al, p0, p1);
            }
        }
    }
    float den0 = __shfl_sync(0xffffffffu, acc[8][0], lane & ~3);
    float den1 = __shfl_sync(0xffffffffu, acc[8][2], lane & ~3);
    if (fabsf(den0) <= NSTAB) den0 += 2.f*NSTAB;
    if (fabsf(den1) <= NSTAB) den1 += 2.f*NSTAB;
    float inv0 = 1.f/den0, inv1 = 1.f/den1;
    int rr = w*16 + r0;
    size_t gl0 = (size_t)(b*L_ + l0 + rr), gl1 = gl0 + 8;
    #pragma unroll
    for (int nt = 0; nt < 8; ++nt) {
        int c0 = nt*8 + cb2;
        uint32_t hh, ll;
        cvt_split2H(acc[nt][0]*inv0, acc[nt][1]*inv0, hh, ll);
        *(uint32_t*)(g_ctxh + gl0*D_ + h*64 + c0) = hh;
        *(uint32_t*)(g_ctxl + gl0*D_ + h*64 + c0) = ll;
        cvt_split2H(acc[nt][2]*inv1, acc[nt][3]*inv1, hh, ll);
        *(uint32_t*)(g_ctxh + gl1*D_ + h*64 + c0) = hh;
        *(uint32_t*)(g_ctxl + gl1*D_ + h*64 + c0) = ll;
    }
}

// ---------------- launch (dual-stream overlap) ----------------
extern "C" void kernel_launch(void* const* d_in, const int* in_sizes, int n_in,
                              void* d_out, int out_size) {
    const float* query = (const float*)d_in[0];
    const float* key   = (const float*)d_in[1];
    const float* value = (const float*)d_in[2];
    const float* mask  = (const float*)d_in[3];
    const float* Wq = (const float*)d_in[4];
    const float* bq = (const float*)d_in[5];
    const float* Wk = (const float*)d_in[6];
    const float* bk = (const float*)d_in[7];
    const float* Wv = (const float*)d_in[8];
    const float* bv = (const float*)d_in[9];
    const float* Wo = (const float*)d_in[10];
    const float* bo = (const float*)d_in[11];
    const float* Wf = (const float*)d_in[12];

    float *Qp, *Kp, *Vp;
    __half *qah,*qal,*kah,*kal,*vah,*vaL;
    __half *wqh,*wkh,*wvh,*woh,*cth,*ctl;
    cudaGetSymbolAddress((void**)&Qp,  g_Qp);
    cudaGetSymbolAddress((void**)&Kp,  g_Kp);
    cudaGetSymbolAddress((void**)&Vp,  g_Vp);
    cudaGetSymbolAddress((void**)&qah, g_qah); cudaGetSymbolAddress((void**)&qal, g_qal);
    cudaGetSymbolAddress((void**)&kah, g_kah); cudaGetSymbolAddress((void**)&kal, g_kal);
    cudaGetSymbolAddress((void**)&vah, g_vah); cudaGetSymbolAddress((void**)&vaL, g_vaL);
    cudaGetSymbolAddress((void**)&wqh, g_wqh);
    cudaGetSymbolAddress((void**)&wkh, g_wkh);
    cudaGetSymbolAddress((void**)&wvh, g_wvh);
    cudaGetSymbolAddress((void**)&woh, g_woh);
    cudaGetSymbolAddress((void**)&cth, g_ctxh); cudaGetSymbolAddress((void**)&ctl, g_ctxl);

    cudaFuncSetAttribute(gemm_mma_h, cudaFuncAttributeMaxDynamicSharedMemorySize, GH_SMEM);
    cudaFuncSetAttribute(kv_mma,     cudaFuncAttributeMaxDynamicSharedMemorySize, KW_SMEM);
    cudaFuncSetAttribute(out_mma,    cudaFuncAttributeMaxDynamicSharedMemorySize, OW_SMEM);

    static cudaStream_t s1 = nullptr;
    static cudaEvent_t eS, eQ, eK, eV, eWo, eG2, eHK;
    if (!s1) {
        cudaStreamCreateWithFlags(&s1, cudaStreamNonBlocking);
        cudaEventCreateWithFlags(&eS,  cudaEventDisableTiming);
        cudaEventCreateWithFlags(&eQ,  cudaEventDisableTiming);
        cudaEventCreateWithFlags(&eK,  cudaEventDisableTiming);
        cudaEventCreateWithFlags(&eV,  cudaEventDisableTiming);
        cudaEventCreateWithFlags(&eWo, cudaEventDisableTiming);
        cudaEventCreateWithFlags(&eG2, cudaEventDisableTiming);
        cudaEventCreateWithFlags(&eHK, cudaEventDisableTiming);
    }

    const int nA4 = BL*D_/4, nW4 = D_*D_/4;
    dim3 gg(D_/128, BL/128);

    init_kernel<<<1, 32>>>();
    cudaEventRecord(eS, 0);
    cudaStreamWaitEvent(s1, eS, 0);

    cvtw_f16<<<nW4/256, 256, 0, s1>>>(Wq, wqh, nW4);
    split_f16<<<nA4/256, 256, 0, s1>>>(query, qah, qal, nA4);
    cudaEventRecord(eQ, s1);
    cvtw_f16<<<nW4/256, 256, 0, s1>>>(Wk, wkh, nW4);
    split_f16<<<nA4/256, 256, 0, s1>>>(key, kah, kal, nA4);
    cudaEventRecord(eK, s1);
    cvtw_f16<<<nW4/256, 256, 0, s1>>>(Wv, wvh, nW4);
    split_f16<<<nA4/256, 256, 0, s1>>>(value, vah, vaL, nA4);
    cudaEventRecord(eV, s1);
    cvtw_f16<<<nW4/256, 256, 0, s1>>>(Wo, woh, nW4);
    cudaEventRecord(eWo, s1);

    cudaStreamWaitEvent(0, eQ, 0);
    gemm_mma_h<<<gg, 256, GH_SMEM>>>(qah, qal, wqh, bq, Qp);
    cudaStreamWaitEvent(0, eK, 0);
    gemm_mma_h<<<gg, 256, GH_SMEM>>>(kah, kal, wkh, bk, Kp);
    cudaEventRecord(eG2, 0);
    cudaStreamWaitEvent(0, eV, 0);
    gemm_mma_h<<<gg, 256, GH_SMEM>>>(vah, vaL, wvh, bv, Vp);

    cudaStreamWaitEvent(s1, eG2, 0);
    hk_kernel<<<(BH*L_)/256, 256, 0, s1>>>();
    cudaEventRecord(eHK, s1);

    cudaStreamWaitEvent(0, eHK, 0);
    kv_mma<<<dim3(SPLIT, BH), KVNT, KW_SMEM>>>(Wf, mask);
    kv_reduce<<<(KVSZ2 + 255)/256, 256>>>();
    out_mma<<<dim3(L_/256, H_, B_), OUNT, OW_SMEM>>>(Wf);
    cudaStreamWaitEvent(0, eWo, 0);
    gemm_mma_h<<<gg, 256, GH_SMEM>>>(cth, ctl, woh, bo, (float*)d_out);
}